// round 2
// baseline (speedup 1.0000x reference)
#include <cuda_runtime.h>
#include <cstdint>

#define BB 4
#define TT 2048
#define CC 256
#define HH 8
#define DH 32
#define QR 32
#define KVR 64
#define NTOK (BB*TT)          // 8192
#define TOKTILE 16
#define NBLK (NTOK/TOKTILE)   // 512
#define BM 128
#define BN 128

// ---------------- scratch (device globals; no allocation allowed) ----------------
__device__ float g_lat[(size_t)NTOK*96];                 // [tok][96]: 0..31 q_lat, 32..95 kv_lat
__device__ float g_q[(size_t)BB*HH*TT*DH];               // [B,H,T,Dh]
__device__ float g_k[(size_t)BB*HH*TT*DH];
__device__ float g_v[(size_t)BB*HH*TT*DH];
__device__ float g_y[(size_t)NTOK*CC];                   // [B,T,C]

typedef unsigned long long u64;

// ---------------- packed f32x2 helpers (FFMA2: 2x fp32 throughput) ----------------
__device__ __forceinline__ u64 pack2(float lo, float hi) {
    u64 r; asm("mov.b64 %0, {%1, %2};" : "=l"(r) : "f"(lo), "f"(hi)); return r;
}
__device__ __forceinline__ float2 unpack2(u64 v) {
    float2 r; asm("mov.b64 {%0, %1}, %2;" : "=f"(r.x), "=f"(r.y) : "l"(v)); return r;
}
__device__ __forceinline__ u64 fma2(u64 a, u64 b, u64 c) {
    u64 d; asm("fma.rn.f32x2 %0, %1, %2, %3;" : "=l"(d) : "l"(a), "l"(b), "l"(c)); return d;
}
__device__ __forceinline__ u64 mul2(u64 a, u64 b) {
    u64 d; asm("mul.rn.f32x2 %0, %1, %2;" : "=l"(d) : "l"(a), "l"(b)); return d;
}
__device__ __forceinline__ u64 add2(u64 a, u64 b) {
    u64 d; asm("add.rn.f32x2 %0, %1, %2;" : "=l"(d) : "l"(a), "l"(b)); return d;
}

// ============================================================================
// k1: LayerNorm + low-rank down projections (q_lat[32], kv_lat[64]) per token.
// 16 tokens per block, 256 threads.
// ============================================================================
__global__ void __launch_bounds__(256) k1_ln_down(
    const float* __restrict__ x, const float* __restrict__ norm_w,
    const float* __restrict__ q_a_w, const float* __restrict__ q_bias,
    const float* __restrict__ kv_a_w, const float* __restrict__ kv_bias)
{
    __shared__ __align__(16) float xs[TOKTILE][CC];
    const int tok0 = blockIdx.x * TOKTILE;
    const int tid = threadIdx.x;

    // coalesced tile load: 16*256 floats = 1024 float4
    const float4* xsrc = (const float4*)(x + (size_t)tok0 * CC);
    float4* xd = (float4*)xs;
#pragma unroll
    for (int i = 0; i < 4; i++) xd[tid + i*256] = xsrc[tid + i*256];
    __syncthreads();

    // LN: warp per token (8 warps, 2 tokens each)
    const int w = tid >> 5, l = tid & 31;
    for (int t = w; t < TOKTILE; t += 8) {
        float s = 0.f, sq = 0.f;
#pragma unroll
        for (int i = 0; i < 8; i++) { float v = xs[t][l + 32*i]; s += v; sq += v*v; }
#pragma unroll
        for (int o = 16; o; o >>= 1) {
            s  += __shfl_xor_sync(0xffffffffu, s,  o);
            sq += __shfl_xor_sync(0xffffffffu, sq, o);
        }
        float mean = s * (1.f/CC);
        float var  = sq * (1.f/CC) - mean*mean;
        float rstd = 1.f / sqrtf(var + 1e-5f);
#pragma unroll
        for (int i = 0; i < 8; i++) {
            int c = l + 32*i;
            xs[t][c] = (xs[t][c] - mean) * rstd * norm_w[c];
        }
    }
    __syncthreads();

    // down projections: 16 tok x 96 outputs = 1536 dots of length 256; 6 per thread
    for (int o = tid; o < TOKTILE*96; o += 256) {
        const int t = o / 96, r = o % 96;
        const float4* wr;
        float bias;
        if (r < QR) { wr = (const float4*)(q_a_w + (size_t)r*CC); bias = q_bias[r]; }
        else        { wr = (const float4*)(kv_a_w + (size_t)(r-QR)*CC); bias = kv_bias[r-QR]; }
        const float4* xv = (const float4*)xs[t];
        float a0=0.f, a1=0.f, a2=0.f, a3=0.f;
#pragma unroll 8
        for (int i = 0; i < 64; i++) {
            float4 wv = wr[i]; float4 vv = xv[i];
            a0 += wv.x*vv.x; a1 += wv.y*vv.y; a2 += wv.z*vv.z; a3 += wv.w*vv.w;
        }
        g_lat[(size_t)(tok0 + t)*96 + r] = (a0+a1) + (a2+a3) + bias;
    }
}

__device__ __forceinline__ void load16(const float* p, float* la) {
    const float4* lp = (const float4*)p;
    float4 a = lp[0], b = lp[1], c = lp[2], d = lp[3];
    la[0]=a.x; la[1]=a.y; la[2]=a.z; la[3]=a.w;
    la[4]=b.x; la[5]=b.y; la[6]=b.z; la[7]=b.w;
    la[8]=c.x; la[9]=c.y; la[10]=c.z; la[11]=c.w;
    la[12]=d.x; la[13]=d.y; la[14]=d.z; la[15]=d.w;
}

// ============================================================================
// k2: up projections q = lat_q @ Wqb^T, k/v = lat_kv @ Wk^T/Wv^T.
// 16 tokens per block, 256 threads; thread = output channel c.
// Writes q/k/v in [B,H,T,Dh].
// ============================================================================
__global__ void __launch_bounds__(256) k2_up(
    const float* __restrict__ q_b_w, const float* __restrict__ k_w,
    const float* __restrict__ v_w)
{
    __shared__ __align__(16) float ls[96][TOKTILE];  // transposed: [r][t]
    const int tok0 = blockIdx.x * TOKTILE;
    const int tid = threadIdx.x;

    for (int i = tid; i < TOKTILE*96; i += 256) {
        int t = i / 96, r = i % 96;
        ls[r][t] = g_lat[(size_t)(tok0 + t)*96 + r];
    }
    __syncthreads();

    const int c = tid, h = c >> 5, d = c & 31;
    float aq[16], ak[16], av[16];
#pragma unroll
    for (int t = 0; t < 16; t++) { aq[t]=0.f; ak[t]=0.f; av[t]=0.f; }

    const float* wq = q_b_w + (size_t)c * QR;
#pragma unroll 4
    for (int r = 0; r < QR; r++) {
        float wv = wq[r];
        float la[16]; load16(ls[r], la);
#pragma unroll
        for (int t = 0; t < 16; t++) aq[t] += la[t] * wv;
    }
    const float* wk = k_w + (size_t)c * KVR;
    const float* wvv = v_w + (size_t)c * KVR;
#pragma unroll 4
    for (int r = 0; r < KVR; r++) {
        float wk_ = wk[r], wv_ = wvv[r];
        float la[16]; load16(ls[QR + r], la);
#pragma unroll
        for (int t = 0; t < 16; t++) { ak[t] += la[t]*wk_; av[t] += la[t]*wv_; }
    }

    const int b = tok0 / TT, t0 = tok0 % TT;
    const size_t base = ((size_t)(b*HH + h)*TT + t0)*DH + d;
#pragma unroll
    for (int t = 0; t < 16; t++) {
        g_q[base + (size_t)t*DH] = aq[t];
        g_k[base + (size_t)t*DH] = ak[t];
        g_v[base + (size_t)t*DH] = av[t];
    }
}

// ============================================================================
// k3: flash attention, fp32 with packed f32x2 math.
// grid (T/BM, B*H); 128 threads, one query row per thread; KV tiles of 128 in smem.
// ============================================================================
__global__ void __launch_bounds__(128) k3_attn()
{
    __shared__ __align__(16) float Ks[BN*DH];
    __shared__ __align__(16) float Vs[BN*DH];

    const int bh = blockIdx.y;
    const int row = blockIdx.x * BM + threadIdx.x;
    const float SCALE = 0.17677669529663687f;  // 1/sqrt(32)

    const float4* qp = (const float4*)(g_q + ((size_t)bh*TT + row)*DH);
    u64 q2[16];
#pragma unroll
    for (int i = 0; i < 8; i++) {
        float4 v = qp[i];
        q2[2*i]   = pack2(v.x*SCALE, v.y*SCALE);
        q2[2*i+1] = pack2(v.z*SCALE, v.w*SCALE);
    }

    u64 acc[16];
#pragma unroll
    for (int i = 0; i < 16; i++) acc[i] = 0ull;
    float m = __int_as_float(0xff800000);  // -inf
    float lsum = 0.f;

    const float4* kbase = (const float4*)(g_k + (size_t)bh*TT*DH);
    const float4* vbase = (const float4*)(g_v + (size_t)bh*TT*DH);
    float4* kd = (float4*)Ks;
    float4* vd = (float4*)Vs;

    for (int kt = 0; kt < TT; kt += BN) {
        __syncthreads();
        const float4* ks4 = kbase + (size_t)kt*DH/4;
        const float4* vs4 = vbase + (size_t)kt*DH/4;
#pragma unroll
        for (int i = 0; i < BN*DH/4/128; i++) {
            int idx = threadIdx.x + i*128;
            kd[idx] = ks4[idx];
            vd[idx] = vs4[idx];
        }
        __syncthreads();

        for (int j = 0; j < BN; j++) {
            const ulonglong2* kr = (const ulonglong2*)(Ks + j*DH);
            ulonglong2 k0 = kr[0], k1 = kr[1], k2_ = kr[2], k3 = kr[3];
            u64 s0 = mul2(q2[0], k0.x), s1 = mul2(q2[1], k0.y);
            u64 s2 = mul2(q2[2], k1.x), s3 = mul2(q2[3], k1.y);
            s0 = fma2(q2[4], k2_.x, s0); s1 = fma2(q2[5], k2_.y, s1);
            s2 = fma2(q2[6], k3.x, s2);  s3 = fma2(q2[7], k3.y, s3);
            ulonglong2 k4 = kr[4], k5 = kr[5], k6 = kr[6], k7 = kr[7];
            s0 = fma2(q2[8],  k4.x, s0); s1 = fma2(q2[9],  k4.y, s1);
            s2 = fma2(q2[10], k5.x, s2); s3 = fma2(q2[11], k5.y, s3);
            s0 = fma2(q2[12], k6.x, s0); s1 = fma2(q2[13], k6.y, s1);
            s2 = fma2(q2[14], k7.x, s2); s3 = fma2(q2[15], k7.y, s3);
            s0 = add2(s0, s1); s2 = add2(s2, s3); s0 = add2(s0, s2);
            float2 sp = unpack2(s0);
            float s = sp.x + sp.y;

            if (s > m) {
                float corr = __expf(m - s);
                m = s;
                lsum *= corr;
                u64 c2 = pack2(corr, corr);
#pragma unroll
                for (int i = 0; i < 16; i++) acc[i] = mul2(acc[i], c2);
            }
            float p = __expf(s - m);
            lsum += p;
            u64 p2 = pack2(p, p);
            const ulonglong2* vr = (const ulonglong2*)(Vs + j*DH);
#pragma unroll
            for (int i = 0; i < 8; i++) {
                ulonglong2 vv = vr[i];
                acc[2*i]   = fma2(p2, vv.x, acc[2*i]);
                acc[2*i+1] = fma2(p2, vv.y, acc[2*i+1]);
            }
        }
    }

    const float inv = 1.0f / lsum;
    const int b = bh >> 3, h = bh & 7;
    float4* yo = (float4*)(g_y + (size_t)(b*TT + row)*CC + h*DH);
#pragma unroll
    for (int i = 0; i < 8; i++) {
        float2 a = unpack2(acc[2*i]);
        float2 b2 = unpack2(acc[2*i+1]);
        float4 o; o.x = a.x*inv; o.y = a.y*inv; o.z = b2.x*inv; o.w = b2.y*inv;
        yo[i] = o;
    }
}

// ============================================================================
// k4: output projection + gamma + residual.
// 16 tokens per block, 256 threads; thread = output channel d.
// ============================================================================
__global__ void __launch_bounds__(256) k4_oproj(
    const float* __restrict__ x, const float* __restrict__ o_w,
    const float* __restrict__ gamma, float* __restrict__ out)
{
    __shared__ __align__(16) float ys[TOKTILE][CC];
    __shared__ float ws[16][257];  // padded: conflict-free store & load
    const int tok0 = blockIdx.x * TOKTILE;
    const int tid = threadIdx.x;

    const float4* ysrc = (const float4*)(g_y + (size_t)tok0 * CC);
    float4* yd = (float4*)ys;
#pragma unroll
    for (int i = 0; i < 4; i++) yd[tid + i*256] = ysrc[tid + i*256];

    u64 acc[16];
#pragma unroll
    for (int t = 0; t < 16; t++) acc[t] = 0ull;

    for (int c0 = 0; c0 < CC; c0 += 16) {
        __syncthreads();
#pragma unroll
        for (int i = 0; i < 16; i++) {
            int idx = tid + i*256;
            int dd = idx >> 4, cc = idx & 15;
            ws[cc][dd] = o_w[(size_t)dd*CC + c0 + cc];
        }
        __syncthreads();
        u64 w2[8];
#pragma unroll
        for (int i = 0; i < 8; i++) w2[i] = pack2(ws[2*i][tid], ws[2*i+1][tid]);
#pragma unroll
        for (int t = 0; t < 16; t++) {
            const ulonglong2* yp = (const ulonglong2*)&ys[t][c0];
#pragma unroll
            for (int pq = 0; pq < 4; pq++) {
                ulonglong2 yv = yp[pq];
                acc[t] = fma2(yv.x, w2[2*pq],   acc[t]);
                acc[t] = fma2(yv.y, w2[2*pq+1], acc[t]);
            }
        }
    }

    const float g = gamma[tid];
#pragma unroll
    for (int t = 0; t < 16; t++) {
        float2 a = unpack2(acc[t]);
        size_t o = (size_t)(tok0 + t)*CC + tid;
        out[o] = x[o] + g * (a.x + a.y);
    }
}

// ============================================================================
extern "C" void kernel_launch(void* const* d_in, const int* in_sizes, int n_in,
                              void* d_out, int out_size)
{
    const float* x       = (const float*)d_in[0];
    const float* q_a_w   = (const float*)d_in[1];
    const float* q_bias  = (const float*)d_in[2];
    const float* q_b_w   = (const float*)d_in[3];
    const float* kv_a_w  = (const float*)d_in[4];
    const float* kv_bias = (const float*)d_in[5];
    const float* k_w     = (const float*)d_in[6];
    const float* v_w     = (const float*)d_in[7];
    const float* o_w     = (const float*)d_in[8];
    const float* norm_w  = (const float*)d_in[9];
    const float* gamma   = (const float*)d_in[10];
    float* out = (float*)d_out;

    k1_ln_down<<<NBLK, 256>>>(x, norm_w, q_a_w, q_bias, kv_a_w, kv_bias);
    k2_up<<<NBLK, 256>>>(q_b_w, k_w, v_w);
    dim3 g3(TT/BM, BB*HH);
    k3_attn<<<g3, BM>>>();
    k4_oproj<<<NBLK, 256>>>(x, o_w, gamma, out);
}

// round 3
// speedup vs baseline: 1.0923x; 1.0923x over previous
#include <cuda_runtime.h>
#include <cstdint>

#define BB 4
#define TT 2048
#define CC 256
#define HH 8
#define DH 32
#define QR 32
#define KVR 64
#define NTOK (BB*TT)          // 8192
#define TOKTILE 16
#define NBLK (NTOK/TOKTILE)   // 512
#define BM 128
#define BN 128
#define KCH 8

// ---------------- scratch (device globals; no allocation allowed) ----------------
__device__ float g_lat[(size_t)NTOK*96];                 // [tok][96]: 0..31 q_lat, 32..95 kv_lat
__device__ float g_q[(size_t)BB*HH*TT*DH];               // [B,H,T,Dh]
__device__ float g_k[(size_t)BB*HH*TT*DH];
__device__ float g_v[(size_t)BB*HH*TT*DH];
__device__ float g_y[(size_t)NTOK*CC];                   // [B,T,C]

typedef unsigned long long u64;

// ---------------- packed f32x2 helpers (FFMA2: 2x fp32 throughput) ----------------
__device__ __forceinline__ u64 pack2(float lo, float hi) {
    u64 r; asm("mov.b64 %0, {%1, %2};" : "=l"(r) : "f"(lo), "f"(hi)); return r;
}
__device__ __forceinline__ float2 unpack2(u64 v) {
    float2 r; asm("mov.b64 {%0, %1}, %2;" : "=f"(r.x), "=f"(r.y) : "l"(v)); return r;
}
__device__ __forceinline__ u64 fma2(u64 a, u64 b, u64 c) {
    u64 d; asm("fma.rn.f32x2 %0, %1, %2, %3;" : "=l"(d) : "l"(a), "l"(b), "l"(c)); return d;
}
__device__ __forceinline__ u64 mul2(u64 a, u64 b) {
    u64 d; asm("mul.rn.f32x2 %0, %1, %2;" : "=l"(d) : "l"(a), "l"(b)); return d;
}
__device__ __forceinline__ u64 add2(u64 a, u64 b) {
    u64 d; asm("add.rn.f32x2 %0, %1, %2;" : "=l"(d) : "l"(a), "l"(b)); return d;
}

// ============================================================================
// k1: LayerNorm + low-rank down projections (q_lat[32], kv_lat[64]) per token.
// ============================================================================
__global__ void __launch_bounds__(256) k1_ln_down(
    const float* __restrict__ x, const float* __restrict__ norm_w,
    const float* __restrict__ q_a_w, const float* __restrict__ q_bias,
    const float* __restrict__ kv_a_w, const float* __restrict__ kv_bias)
{
    __shared__ __align__(16) float xs[TOKTILE][CC];
    const int tok0 = blockIdx.x * TOKTILE;
    const int tid = threadIdx.x;

    const float4* xsrc = (const float4*)(x + (size_t)tok0 * CC);
    float4* xd = (float4*)xs;
#pragma unroll
    for (int i = 0; i < 4; i++) xd[tid + i*256] = xsrc[tid + i*256];
    __syncthreads();

    const int w = tid >> 5, l = tid & 31;
    for (int t = w; t < TOKTILE; t += 8) {
        float s = 0.f, sq = 0.f;
#pragma unroll
        for (int i = 0; i < 8; i++) { float v = xs[t][l + 32*i]; s += v; sq += v*v; }
#pragma unroll
        for (int o = 16; o; o >>= 1) {
            s  += __shfl_xor_sync(0xffffffffu, s,  o);
            sq += __shfl_xor_sync(0xffffffffu, sq, o);
        }
        float mean = s * (1.f/CC);
        float var  = sq * (1.f/CC) - mean*mean;
        float rstd = 1.f / sqrtf(var + 1e-5f);
#pragma unroll
        for (int i = 0; i < 8; i++) {
            int c = l + 32*i;
            xs[t][c] = (xs[t][c] - mean) * rstd * norm_w[c];
        }
    }
    __syncthreads();

    for (int o = tid; o < TOKTILE*96; o += 256) {
        const int t = o / 96, r = o % 96;
        const float4* wr;
        float bias;
        if (r < QR) { wr = (const float4*)(q_a_w + (size_t)r*CC); bias = q_bias[r]; }
        else        { wr = (const float4*)(kv_a_w + (size_t)(r-QR)*CC); bias = kv_bias[r-QR]; }
        const float4* xv = (const float4*)xs[t];
        float a0=0.f, a1=0.f, a2=0.f, a3=0.f;
#pragma unroll 8
        for (int i = 0; i < 64; i++) {
            float4 wv = wr[i]; float4 vv = xv[i];
            a0 += wv.x*vv.x; a1 += wv.y*vv.y; a2 += wv.z*vv.z; a3 += wv.w*vv.w;
        }
        g_lat[(size_t)(tok0 + t)*96 + r] = (a0+a1) + (a2+a3) + bias;
    }
}

__device__ __forceinline__ void load16(const float* p, float* la) {
    const float4* lp = (const float4*)p;
    float4 a = lp[0], b = lp[1], c = lp[2], d = lp[3];
    la[0]=a.x; la[1]=a.y; la[2]=a.z; la[3]=a.w;
    la[4]=b.x; la[5]=b.y; la[6]=b.z; la[7]=b.w;
    la[8]=c.x; la[9]=c.y; la[10]=c.z; la[11]=c.w;
    la[12]=d.x; la[13]=d.y; la[14]=d.z; la[15]=d.w;
}

// ============================================================================
// k2: up projections q/k/v; writes [B,H,T,Dh].
// ============================================================================
__global__ void __launch_bounds__(256) k2_up(
    const float* __restrict__ q_b_w, const float* __restrict__ k_w,
    const float* __restrict__ v_w)
{
    __shared__ __align__(16) float ls[96][TOKTILE];
    const int tok0 = blockIdx.x * TOKTILE;
    const int tid = threadIdx.x;

    for (int i = tid; i < TOKTILE*96; i += 256) {
        int t = i / 96, r = i % 96;
        ls[r][t] = g_lat[(size_t)(tok0 + t)*96 + r];
    }
    __syncthreads();

    const int c = tid, h = c >> 5, d = c & 31;
    float aq[16], ak[16], av[16];
#pragma unroll
    for (int t = 0; t < 16; t++) { aq[t]=0.f; ak[t]=0.f; av[t]=0.f; }

    const float* wq = q_b_w + (size_t)c * QR;
#pragma unroll 4
    for (int r = 0; r < QR; r++) {
        float wv = wq[r];
        float la[16]; load16(ls[r], la);
#pragma unroll
        for (int t = 0; t < 16; t++) aq[t] += la[t] * wv;
    }
    const float* wk = k_w + (size_t)c * KVR;
    const float* wvv = v_w + (size_t)c * KVR;
#pragma unroll 4
    for (int r = 0; r < KVR; r++) {
        float wk_ = wk[r], wv_ = wvv[r];
        float la[16]; load16(ls[QR + r], la);
#pragma unroll
        for (int t = 0; t < 16; t++) { ak[t] += la[t]*wk_; av[t] += la[t]*wv_; }
    }

    const int b = tok0 / TT, t0 = tok0 % TT;
    const size_t base = ((size_t)(b*HH + h)*TT + t0)*DH + d;
#pragma unroll
    for (int t = 0; t < 16; t++) {
        g_q[base + (size_t)t*DH] = aq[t];
        g_k[base + (size_t)t*DH] = ak[t];
        g_v[base + (size_t)t*DH] = av[t];
    }
}

// ============================================================================
// k3: flash attention, fp32 packed f32x2, 8 keys per iter, BRANCHLESS softmax.
// q prescaled by (1/sqrt(Dh))*log2(e); probabilities via exp2f (raw MUFU.EX2).
// grid (T/BM, B*H); 128 threads, one query row per thread.
// ============================================================================
__global__ void __launch_bounds__(128) k3_attn()
{
    __shared__ __align__(16) float Ks[BN*DH];
    __shared__ __align__(16) float Vs[BN*DH];

    const int bh = blockIdx.y;
    const int row = blockIdx.x * BM + threadIdx.x;
    const float SC = 0.17677669529663687f * 1.4426950408889634f; // 1/sqrt(32) * log2(e)

    const float4* qp = (const float4*)(g_q + ((size_t)bh*TT + row)*DH);
    u64 q2[16];
#pragma unroll
    for (int i = 0; i < 8; i++) {
        float4 v = qp[i];
        q2[2*i]   = pack2(v.x*SC, v.y*SC);
        q2[2*i+1] = pack2(v.z*SC, v.w*SC);
    }

    u64 acc[16];
#pragma unroll
    for (int i = 0; i < 16; i++) acc[i] = 0ull;
    float m = -3.0e38f;
    float lsum = 0.f;

    const float4* kbase = (const float4*)(g_k + (size_t)bh*TT*DH);
    const float4* vbase = (const float4*)(g_v + (size_t)bh*TT*DH);
    float4* kd = (float4*)Ks;
    float4* vd = (float4*)Vs;

    for (int kt = 0; kt < TT; kt += BN) {
        __syncthreads();
        const float4* ks4 = kbase + (size_t)kt*DH/4;
        const float4* vs4 = vbase + (size_t)kt*DH/4;
#pragma unroll
        for (int i = 0; i < BN*DH/4/128; i++) {
            int idx = threadIdx.x + i*128;
            kd[idx] = ks4[idx];
            vd[idx] = vs4[idx];
        }
        __syncthreads();

        for (int j = 0; j < BN; j += KCH) {
            float s[KCH];
#pragma unroll
            for (int jj = 0; jj < KCH; jj++) {
                const ulonglong2* kr = (const ulonglong2*)(Ks + (j+jj)*DH);
                ulonglong2 k0 = kr[0], k1 = kr[1], k2_ = kr[2], k3 = kr[3];
                u64 s0 = mul2(q2[0], k0.x), s1 = mul2(q2[1], k0.y);
                u64 s2 = mul2(q2[2], k1.x), s3 = mul2(q2[3], k1.y);
                s0 = fma2(q2[4], k2_.x, s0); s1 = fma2(q2[5], k2_.y, s1);
                s2 = fma2(q2[6], k3.x, s2);  s3 = fma2(q2[7], k3.y, s3);
                ulonglong2 k4 = kr[4], k5 = kr[5], k6 = kr[6], k7 = kr[7];
                s0 = fma2(q2[8],  k4.x, s0); s1 = fma2(q2[9],  k4.y, s1);
                s2 = fma2(q2[10], k5.x, s2); s3 = fma2(q2[11], k5.y, s3);
                s0 = fma2(q2[12], k6.x, s0); s1 = fma2(q2[13], k6.y, s1);
                s2 = fma2(q2[14], k7.x, s2); s3 = fma2(q2[15], k7.y, s3);
                s0 = add2(s0, s1); s2 = add2(s2, s3); s0 = add2(s0, s2);
                float2 sp = unpack2(s0);
                s[jj] = sp.x + sp.y;
            }

            // branchless online-softmax update (per 8 keys)
            float mx = fmaxf(fmaxf(fmaxf(s[0], s[1]), fmaxf(s[2], s[3])),
                             fmaxf(fmaxf(s[4], s[5]), fmaxf(s[6], s[7])));
            float mnew = fmaxf(m, mx);
            float corr = exp2f(m - mnew);   // == 1.0f when m unchanged
            m = mnew;
            lsum *= corr;
            u64 c2 = pack2(corr, corr);
#pragma unroll
            for (int i = 0; i < 16; i++) acc[i] = mul2(acc[i], c2);

            float p[KCH];
#pragma unroll
            for (int jj = 0; jj < KCH; jj++) {
                p[jj] = exp2f(s[jj] - m);
                lsum += p[jj];
            }

#pragma unroll
            for (int jj = 0; jj < KCH; jj++) {
                u64 p2 = pack2(p[jj], p[jj]);
                const ulonglong2* vr = (const ulonglong2*)(Vs + (j+jj)*DH);
#pragma unroll
                for (int i = 0; i < 8; i++) {
                    ulonglong2 vv = vr[i];
                    acc[2*i]   = fma2(p2, vv.x, acc[2*i]);
                    acc[2*i+1] = fma2(p2, vv.y, acc[2*i+1]);
                }
            }
        }
    }

    const float inv = 1.0f / lsum;
    const int b = bh >> 3, h = bh & 7;
    float4* yo = (float4*)(g_y + (size_t)(b*TT + row)*CC + h*DH);
#pragma unroll
    for (int i = 0; i < 8; i++) {
        float2 a = unpack2(acc[2*i]);
        float2 b2 = unpack2(acc[2*i+1]);
        float4 o; o.x = a.x*inv; o.y = a.y*inv; o.z = b2.x*inv; o.w = b2.y*inv;
        yo[i] = o;
    }
}

// ============================================================================
// k4: output projection + gamma + residual.
// ============================================================================
__global__ void __launch_bounds__(256) k4_oproj(
    const float* __restrict__ x, const float* __restrict__ o_w,
    const float* __restrict__ gamma, float* __restrict__ out)
{
    __shared__ __align__(16) float ys[TOKTILE][CC];
    __shared__ float ws[16][257];
    const int tok0 = blockIdx.x * TOKTILE;
    const int tid = threadIdx.x;

    const float4* ysrc = (const float4*)(g_y + (size_t)tok0 * CC);
    float4* yd = (float4*)ys;
#pragma unroll
    for (int i = 0; i < 4; i++) yd[tid + i*256] = ysrc[tid + i*256];

    u64 acc[16];
#pragma unroll
    for (int t = 0; t < 16; t++) acc[t] = 0ull;

    for (int c0 = 0; c0 < CC; c0 += 16) {
        __syncthreads();
#pragma unroll
        for (int i = 0; i < 16; i++) {
            int idx = tid + i*256;
            int dd = idx >> 4, cc = idx & 15;
            ws[cc][dd] = o_w[(size_t)dd*CC + c0 + cc];
        }
        __syncthreads();
        u64 w2[8];
#pragma unroll
        for (int i = 0; i < 8; i++) w2[i] = pack2(ws[2*i][tid], ws[2*i+1][tid]);
#pragma unroll
        for (int t = 0; t < 16; t++) {
            const ulonglong2* yp = (const ulonglong2*)&ys[t][c0];
#pragma unroll
            for (int pq = 0; pq < 4; pq++) {
                ulonglong2 yv = yp[pq];
                acc[t] = fma2(yv.x, w2[2*pq],   acc[t]);
                acc[t] = fma2(yv.y, w2[2*pq+1], acc[t]);
            }
        }
    }

    const float g = gamma[tid];
#pragma unroll
    for (int t = 0; t < 16; t++) {
        float2 a = unpack2(acc[t]);
        size_t o = (size_t)(tok0 + t)*CC + tid;
        out[o] = x[o] + g * (a.x + a.y);
    }
}

// ============================================================================
extern "C" void kernel_launch(void* const* d_in, const int* in_sizes, int n_in,
                              void* d_out, int out_size)
{
    const float* x       = (const float*)d_in[0];
    const float* q_a_w   = (const float*)d_in[1];
    const float* q_bias  = (const float*)d_in[2];
    const float* q_b_w   = (const float*)d_in[3];
    const float* kv_a_w  = (const float*)d_in[4];
    const float* kv_bias = (const float*)d_in[5];
    const float* k_w     = (const float*)d_in[6];
    const float* v_w     = (const float*)d_in[7];
    const float* o_w     = (const float*)d_in[8];
    const float* norm_w  = (const float*)d_in[9];
    const float* gamma   = (const float*)d_in[10];
    float* out = (float*)d_out;

    k1_ln_down<<<NBLK, 256>>>(x, norm_w, q_a_w, q_bias, kv_a_w, kv_bias);
    k2_up<<<NBLK, 256>>>(q_b_w, k_w, v_w);
    dim3 g3(TT/BM, BB*HH);
    k3_attn<<<g3, BM>>>();
    k4_oproj<<<NBLK, 256>>>(x, o_w, gamma, out);
}

// round 4
// speedup vs baseline: 1.7654x; 1.6161x over previous
#include <cuda_runtime.h>
#include <cstdint>

#define BB 4
#define TT 2048
#define CC 256
#define HH 8
#define DH 32
#define QR 32
#define KVR 64
#define NTOK (BB*TT)          // 8192
#define TOKTILE 16
#define NBLK (NTOK/TOKTILE)   // 512

// ---------------- scratch (device globals; no allocation allowed) ----------------
__device__ float g_lat[(size_t)NTOK*96];                 // [tok][96]: 0..31 q_lat, 32..95 kv_lat
__device__ float g_q[(size_t)BB*HH*TT*DH];               // [B,H,T,Dh]
__device__ float g_k[(size_t)BB*HH*TT*DH];
__device__ float g_v[(size_t)BB*HH*TT*DH];
__device__ float g_y[(size_t)NTOK*CC];                   // [B,T,C]

typedef unsigned long long u64;

// ---------------- packed f32x2 helpers ----------------
__device__ __forceinline__ u64 pack2(float lo, float hi) {
    u64 r; asm("mov.b64 %0, {%1, %2};" : "=l"(r) : "f"(lo), "f"(hi)); return r;
}
__device__ __forceinline__ float2 unpack2(u64 v) {
    float2 r; asm("mov.b64 {%0, %1}, %2;" : "=f"(r.x), "=f"(r.y) : "l"(v)); return r;
}
__device__ __forceinline__ u64 fma2(u64 a, u64 b, u64 c) {
    u64 d; asm("fma.rn.f32x2 %0, %1, %2, %3;" : "=l"(d) : "l"(a), "l"(b), "l"(c)); return d;
}
__device__ __forceinline__ u64 mul2(u64 a, u64 b) {
    u64 d; asm("mul.rn.f32x2 %0, %1, %2;" : "=l"(d) : "l"(a), "l"(b)); return d;
}

// ---------------- tf32 mma helpers ----------------
__device__ __forceinline__ unsigned cvt_tf32(float f) {
    unsigned r; asm("cvt.rna.tf32.f32 %0, %1;" : "=r"(r) : "f"(f)); return r;
}
__device__ __forceinline__ void mma_tf32(float& d0, float& d1, float& d2, float& d3,
    unsigned a0, unsigned a1, unsigned a2, unsigned a3, unsigned b0, unsigned b1) {
    asm volatile("mma.sync.aligned.m16n8k8.row.col.f32.tf32.tf32.f32 "
        "{%0,%1,%2,%3}, {%4,%5,%6,%7}, {%8,%9}, {%0,%1,%2,%3};"
        : "+f"(d0), "+f"(d1), "+f"(d2), "+f"(d3)
        : "r"(a0), "r"(a1), "r"(a2), "r"(a3), "r"(b0), "r"(b1));
}

// ============================================================================
// k1: LayerNorm + low-rank down projections
// ============================================================================
__global__ void __launch_bounds__(256) k1_ln_down(
    const float* __restrict__ x, const float* __restrict__ norm_w,
    const float* __restrict__ q_a_w, const float* __restrict__ q_bias,
    const float* __restrict__ kv_a_w, const float* __restrict__ kv_bias)
{
    __shared__ __align__(16) float xs[TOKTILE][CC];
    const int tok0 = blockIdx.x * TOKTILE;
    const int tid = threadIdx.x;

    const float4* xsrc = (const float4*)(x + (size_t)tok0 * CC);
    float4* xd = (float4*)xs;
#pragma unroll
    for (int i = 0; i < 4; i++) xd[tid + i*256] = xsrc[tid + i*256];
    __syncthreads();

    const int w = tid >> 5, l = tid & 31;
    for (int t = w; t < TOKTILE; t += 8) {
        float s = 0.f, sq = 0.f;
#pragma unroll
        for (int i = 0; i < 8; i++) { float v = xs[t][l + 32*i]; s += v; sq += v*v; }
#pragma unroll
        for (int o = 16; o; o >>= 1) {
            s  += __shfl_xor_sync(0xffffffffu, s,  o);
            sq += __shfl_xor_sync(0xffffffffu, sq, o);
        }
        float mean = s * (1.f/CC);
        float var  = sq * (1.f/CC) - mean*mean;
        float rstd = 1.f / sqrtf(var + 1e-5f);
#pragma unroll
        for (int i = 0; i < 8; i++) {
            int c = l + 32*i;
            xs[t][c] = (xs[t][c] - mean) * rstd * norm_w[c];
        }
    }
    __syncthreads();

    for (int o = tid; o < TOKTILE*96; o += 256) {
        const int t = o / 96, r = o % 96;
        const float4* wr;
        float bias;
        if (r < QR) { wr = (const float4*)(q_a_w + (size_t)r*CC); bias = q_bias[r]; }
        else        { wr = (const float4*)(kv_a_w + (size_t)(r-QR)*CC); bias = kv_bias[r-QR]; }
        const float4* xv = (const float4*)xs[t];
        float a0=0.f, a1=0.f, a2=0.f, a3=0.f;
#pragma unroll 8
        for (int i = 0; i < 64; i++) {
            float4 wv = wr[i]; float4 vv = xv[i];
            a0 += wv.x*vv.x; a1 += wv.y*vv.y; a2 += wv.z*vv.z; a3 += wv.w*vv.w;
        }
        g_lat[(size_t)(tok0 + t)*96 + r] = (a0+a1) + (a2+a3) + bias;
    }
}

__device__ __forceinline__ void load16(const float* p, float* la) {
    const float4* lp = (const float4*)p;
    float4 a = lp[0], b = lp[1], c = lp[2], d = lp[3];
    la[0]=a.x; la[1]=a.y; la[2]=a.z; la[3]=a.w;
    la[4]=b.x; la[5]=b.y; la[6]=b.z; la[7]=b.w;
    la[8]=c.x; la[9]=c.y; la[10]=c.z; la[11]=c.w;
    la[12]=d.x; la[13]=d.y; la[14]=d.z; la[15]=d.w;
}

// ============================================================================
// k2: up projections q/k/v; writes [B,H,T,Dh].
// ============================================================================
__global__ void __launch_bounds__(256) k2_up(
    const float* __restrict__ q_b_w, const float* __restrict__ k_w,
    const float* __restrict__ v_w)
{
    __shared__ __align__(16) float ls[96][TOKTILE];
    const int tok0 = blockIdx.x * TOKTILE;
    const int tid = threadIdx.x;

    for (int i = tid; i < TOKTILE*96; i += 256) {
        int t = i / 96, r = i % 96;
        ls[r][t] = g_lat[(size_t)(tok0 + t)*96 + r];
    }
    __syncthreads();

    const int c = tid, h = c >> 5, d = c & 31;
    float aq[16], ak[16], av[16];
#pragma unroll
    for (int t = 0; t < 16; t++) { aq[t]=0.f; ak[t]=0.f; av[t]=0.f; }

    const float* wq = q_b_w + (size_t)c * QR;
#pragma unroll 4
    for (int r = 0; r < QR; r++) {
        float wv = wq[r];
        float la[16]; load16(ls[r], la);
#pragma unroll
        for (int t = 0; t < 16; t++) aq[t] += la[t] * wv;
    }
    const float* wk = k_w + (size_t)c * KVR;
    const float* wvv = v_w + (size_t)c * KVR;
#pragma unroll 4
    for (int r = 0; r < KVR; r++) {
        float wk_ = wk[r], wv_ = wvv[r];
        float la[16]; load16(ls[QR + r], la);
#pragma unroll
        for (int t = 0; t < 16; t++) { ak[t] += la[t]*wk_; av[t] += la[t]*wv_; }
    }

    const int b = tok0 / TT, t0 = tok0 % TT;
    const size_t base = ((size_t)(b*HH + h)*TT + t0)*DH + d;
#pragma unroll
    for (int t = 0; t < 16; t++) {
        g_q[base + (size_t)t*DH] = aq[t];
        g_k[base + (size_t)t*DH] = ak[t];
        g_v[base + (size_t)t*DH] = av[t];
    }
}

// ============================================================================
// k3: flash attention on TENSOR CORES (mma.sync m16n8k8 tf32).
// grid (T/64, B*H); 128 threads = 4 warps; warp owns 16 query rows.
// K/V tiles of 64 keys in smem (stride 36 floats: conflict-free frag loads).
// P re-layout D-frag -> A-frag via per-warp smem (stride 72).
// ============================================================================
#define KSTR 36
#define PSTR 72
__global__ void __launch_bounds__(128) k3_attn_mma()
{
    __shared__ __align__(16) float Ks[64*KSTR];
    __shared__ __align__(16) float Vs[64*KSTR];
    __shared__ __align__(16) unsigned Ps[4*16*PSTR];

    const int tid = threadIdx.x;
    const int w = tid >> 5, lane = tid & 31;
    const int gid = lane >> 2, tig = lane & 3;
    const int bh = blockIdx.y;
    const int qbase = blockIdx.x * 64 + w * 16;
    const int r0 = qbase + gid, r1 = r0 + 8;
    const float SC = 0.17677669529663687f * 1.4426950408889634f; // 1/sqrt(32)*log2(e)

    // Q fragments (A-layout), scaled + tf32, loaded once
    const float* qptr = g_q + (size_t)bh*TT*DH;
    unsigned qA[4][4];
#pragma unroll
    for (int kc = 0; kc < 4; kc++) {
        qA[kc][0] = cvt_tf32(qptr[(size_t)r0*DH + 8*kc + tig]     * SC);
        qA[kc][1] = cvt_tf32(qptr[(size_t)r1*DH + 8*kc + tig]     * SC);
        qA[kc][2] = cvt_tf32(qptr[(size_t)r0*DH + 8*kc + tig + 4] * SC);
        qA[kc][3] = cvt_tf32(qptr[(size_t)r1*DH + 8*kc + tig + 4] * SC);
    }

    float y[4][4];
#pragma unroll
    for (int i = 0; i < 4; i++)
#pragma unroll
        for (int j = 0; j < 4; j++) y[i][j] = 0.f;
    float m0 = -3.0e38f, m1 = -3.0e38f, l0 = 0.f, l1 = 0.f;

    const float4* kg = (const float4*)(g_k + (size_t)bh*TT*DH);
    const float4* vg = (const float4*)(g_v + (size_t)bh*TT*DH);
    unsigned* myPs = Ps + w*16*PSTR;

    for (int kt = 0; kt < TT; kt += 64) {
        __syncthreads();
        // cooperative K/V tile load: 64 rows x 8 float4
#pragma unroll
        for (int i = 0; i < 4; i++) {
            int idx = tid + 128*i;
            int row = idx >> 3, c4 = idx & 7;
            ((float4*)(Ks + row*KSTR))[c4] = kg[((size_t)(kt + row))*8 + c4];
            ((float4*)(Vs + row*KSTR))[c4] = vg[((size_t)(kt + row))*8 + c4];
        }
        __syncthreads();

        // S = Q K^T : 8 n-chunks x 4 k-chunks
        float s[8][4];
#pragma unroll
        for (int nc = 0; nc < 8; nc++) {
            s[nc][0] = s[nc][1] = s[nc][2] = s[nc][3] = 0.f;
#pragma unroll
            for (int kc = 0; kc < 4; kc++) {
                const float* kb = Ks + (8*nc + gid)*KSTR + 8*kc + tig;
                unsigned b0 = cvt_tf32(kb[0]);
                unsigned b1 = cvt_tf32(kb[4]);
                mma_tf32(s[nc][0], s[nc][1], s[nc][2], s[nc][3],
                         qA[kc][0], qA[kc][1], qA[kc][2], qA[kc][3], b0, b1);
            }
        }

        // online softmax (rows r0, r1)
        float mx0 = s[0][0], mx1 = s[0][2];
#pragma unroll
        for (int nc = 0; nc < 8; nc++) {
            mx0 = fmaxf(mx0, fmaxf(s[nc][0], s[nc][1]));
            mx1 = fmaxf(mx1, fmaxf(s[nc][2], s[nc][3]));
        }
        mx0 = fmaxf(mx0, __shfl_xor_sync(0xffffffffu, mx0, 1));
        mx0 = fmaxf(mx0, __shfl_xor_sync(0xffffffffu, mx0, 2));
        mx1 = fmaxf(mx1, __shfl_xor_sync(0xffffffffu, mx1, 1));
        mx1 = fmaxf(mx1, __shfl_xor_sync(0xffffffffu, mx1, 2));
        float mn0 = fmaxf(m0, mx0), mn1 = fmaxf(m1, mx1);
        float c0 = exp2f(m0 - mn0), c1 = exp2f(m1 - mn1);
        m0 = mn0; m1 = mn1;
        l0 *= c0; l1 *= c1;
#pragma unroll
        for (int nc2 = 0; nc2 < 4; nc2++) {
            y[nc2][0] *= c0; y[nc2][1] *= c0;
            y[nc2][2] *= c1; y[nc2][3] *= c1;
        }
        float ps0 = 0.f, ps1 = 0.f;
#pragma unroll
        for (int nc = 0; nc < 8; nc++) {
            s[nc][0] = exp2f(s[nc][0] - m0);
            s[nc][1] = exp2f(s[nc][1] - m0);
            s[nc][2] = exp2f(s[nc][2] - m1);
            s[nc][3] = exp2f(s[nc][3] - m1);
            ps0 += s[nc][0] + s[nc][1];
            ps1 += s[nc][2] + s[nc][3];
        }
        ps0 += __shfl_xor_sync(0xffffffffu, ps0, 1);
        ps0 += __shfl_xor_sync(0xffffffffu, ps0, 2);
        ps1 += __shfl_xor_sync(0xffffffffu, ps1, 1);
        ps1 += __shfl_xor_sync(0xffffffffu, ps1, 2);
        l0 += ps0; l1 += ps1;

        // store P (tf32) to per-warp smem in row-major [16][64]
#pragma unroll
        for (int nc = 0; nc < 8; nc++) {
            uint2 v0; v0.x = cvt_tf32(s[nc][0]); v0.y = cvt_tf32(s[nc][1]);
            uint2 v1; v1.x = cvt_tf32(s[nc][2]); v1.y = cvt_tf32(s[nc][3]);
            *(uint2*)&myPs[gid*PSTR + 8*nc + 2*tig]     = v0;
            *(uint2*)&myPs[(gid+8)*PSTR + 8*nc + 2*tig] = v1;
        }
        __syncwarp();

        // Y += P V : 8 k-chunks x 4 n-chunks
#pragma unroll
        for (int kc = 0; kc < 8; kc++) {
            unsigned a0 = myPs[gid*PSTR     + 8*kc + tig];
            unsigned a1 = myPs[(gid+8)*PSTR + 8*kc + tig];
            unsigned a2 = myPs[gid*PSTR     + 8*kc + tig + 4];
            unsigned a3 = myPs[(gid+8)*PSTR + 8*kc + tig + 4];
#pragma unroll
            for (int nc2 = 0; nc2 < 4; nc2++) {
                unsigned b0 = cvt_tf32(Vs[(8*kc + tig)*KSTR     + 8*nc2 + gid]);
                unsigned b1 = cvt_tf32(Vs[(8*kc + tig + 4)*KSTR + 8*nc2 + gid]);
                mma_tf32(y[nc2][0], y[nc2][1], y[nc2][2], y[nc2][3],
                         a0, a1, a2, a3, b0, b1);
            }
        }
        __syncwarp();
    }

    // normalize + write to g_y[B,T,C]
    const float inv0 = 1.0f / l0, inv1 = 1.0f / l1;
    const int b = bh >> 3, h = bh & 7;
#pragma unroll
    for (int nc2 = 0; nc2 < 4; nc2++) {
        int col = h*DH + nc2*8 + 2*tig;
        float2 o0; o0.x = y[nc2][0]*inv0; o0.y = y[nc2][1]*inv0;
        float2 o1; o1.x = y[nc2][2]*inv1; o1.y = y[nc2][3]*inv1;
        *(float2*)&g_y[(size_t)(b*TT + r0)*CC + col] = o0;
        *(float2*)&g_y[(size_t)(b*TT + r1)*CC + col] = o1;
    }
}

// ============================================================================
// k4: output projection + gamma + residual.
// ============================================================================
__global__ void __launch_bounds__(256) k4_oproj(
    const float* __restrict__ x, const float* __restrict__ o_w,
    const float* __restrict__ gamma, float* __restrict__ out)
{
    __shared__ __align__(16) float ys[TOKTILE][CC];
    __shared__ float ws[16][257];
    const int tok0 = blockIdx.x * TOKTILE;
    const int tid = threadIdx.x;

    const float4* ysrc = (const float4*)(g_y + (size_t)tok0 * CC);
    float4* yd = (float4*)ys;
#pragma unroll
    for (int i = 0; i < 4; i++) yd[tid + i*256] = ysrc[tid + i*256];

    u64 acc[16];
#pragma unroll
    for (int t = 0; t < 16; t++) acc[t] = 0ull;

    for (int c0 = 0; c0 < CC; c0 += 16) {
        __syncthreads();
#pragma unroll
        for (int i = 0; i < 16; i++) {
            int idx = tid + i*256;
            int dd = idx >> 4, cc = idx & 15;
            ws[cc][dd] = o_w[(size_t)dd*CC + c0 + cc];
        }
        __syncthreads();
        u64 w2[8];
#pragma unroll
        for (int i = 0; i < 8; i++) w2[i] = pack2(ws[2*i][tid], ws[2*i+1][tid]);
#pragma unroll
        for (int t = 0; t < 16; t++) {
            const ulonglong2* yp = (const ulonglong2*)&ys[t][c0];
#pragma unroll
            for (int pq = 0; pq < 4; pq++) {
                ulonglong2 yv = yp[pq];
                acc[t] = fma2(yv.x, w2[2*pq],   acc[t]);
                acc[t] = fma2(yv.y, w2[2*pq+1], acc[t]);
            }
        }
    }

    const float g = gamma[tid];
#pragma unroll
    for (int t = 0; t < 16; t++) {
        float2 a = unpack2(acc[t]);
        size_t o = (size_t)(tok0 + t)*CC + tid;
        out[o] = x[o] + g * (a.x + a.y);
    }
}

// ============================================================================
extern "C" void kernel_launch(void* const* d_in, const int* in_sizes, int n_in,
                              void* d_out, int out_size)
{
    const float* x       = (const float*)d_in[0];
    const float* q_a_w   = (const float*)d_in[1];
    const float* q_bias  = (const float*)d_in[2];
    const float* q_b_w   = (const float*)d_in[3];
    const float* kv_a_w  = (const float*)d_in[4];
    const float* kv_bias = (const float*)d_in[5];
    const float* k_w     = (const float*)d_in[6];
    const float* v_w     = (const float*)d_in[7];
    const float* o_w     = (const float*)d_in[8];
    const float* norm_w  = (const float*)d_in[9];
    const float* gamma   = (const float*)d_in[10];
    float* out = (float*)d_out;

    k1_ln_down<<<NBLK, 256>>>(x, norm_w, q_a_w, q_bias, kv_a_w, kv_bias);
    k2_up<<<NBLK, 256>>>(q_b_w, k_w, v_w);
    dim3 g3(TT/64, BB*HH);
    k3_attn_mma<<<g3, 128>>>();
    k4_oproj<<<NBLK, 256>>>(x, o_w, gamma, out);
}

// round 5
// speedup vs baseline: 1.7719x; 1.0037x over previous
#include <cuda_runtime.h>
#include <cstdint>

#define BB 4
#define TT 2048
#define CC 256
#define HH 8
#define DH 32
#define QR 32
#define KVR 64
#define NTOK (BB*TT)          // 8192
#define TOKTILE 16
#define NBLK (NTOK/TOKTILE)   // 512

// ---------------- scratch (device globals; no allocation allowed) ----------------
__device__ float g_lat[(size_t)NTOK*96];                 // [tok][96]
__device__ float g_q[(size_t)BB*HH*TT*DH];               // [B,H,T,Dh]  (tf32 bits, pre-scaled)
__device__ float g_k[(size_t)BB*HH*TT*DH];               // tf32 bits
__device__ float g_v[(size_t)BB*HH*TT*DH];               // tf32 bits
__device__ float g_y[(size_t)NTOK*CC];                   // [B,T,C]
__device__ unsigned long long g_owT2[(size_t)128*256];   // packed o_w^T pairs [c2][d]

typedef unsigned long long u64;

// ---------------- packed f32x2 helpers ----------------
__device__ __forceinline__ u64 pack2(float lo, float hi) {
    u64 r; asm("mov.b64 %0, {%1, %2};" : "=l"(r) : "f"(lo), "f"(hi)); return r;
}
__device__ __forceinline__ float2 unpack2(u64 v) {
    float2 r; asm("mov.b64 {%0, %1}, %2;" : "=f"(r.x), "=f"(r.y) : "l"(v)); return r;
}
__device__ __forceinline__ u64 fma2(u64 a, u64 b, u64 c) {
    u64 d; asm("fma.rn.f32x2 %0, %1, %2, %3;" : "=l"(d) : "l"(a), "l"(b), "l"(c)); return d;
}

// ---------------- tf32 helpers ----------------
__device__ __forceinline__ float cvt_tf32f(float f) {
    unsigned r; asm("cvt.rna.tf32.f32 %0, %1;" : "=r"(r) : "f"(f));
    return __uint_as_float(r);
}
__device__ __forceinline__ void mma_tf32(float& d0, float& d1, float& d2, float& d3,
    unsigned a0, unsigned a1, unsigned a2, unsigned a3, unsigned b0, unsigned b1) {
    asm volatile("mma.sync.aligned.m16n8k8.row.col.f32.tf32.tf32.f32 "
        "{%0,%1,%2,%3}, {%4,%5,%6,%7}, {%8,%9}, {%0,%1,%2,%3};"
        : "+f"(d0), "+f"(d1), "+f"(d2), "+f"(d3)
        : "r"(a0), "r"(a1), "r"(a2), "r"(a3), "r"(b0), "r"(b1));
}

// ============================================================================
// k0: pack o_w^T into u64 pairs: g_owT2[c2*256 + d] = (o_w[d][2c2], o_w[d][2c2+1])
// ============================================================================
__global__ void __launch_bounds__(256) k0_twt(const float* __restrict__ o_w) {
    int i = blockIdx.x * 256 + threadIdx.x;   // 0..32767
    int d = i >> 7, c2 = i & 127;             // read-coalesced over c2
    g_owT2[(size_t)c2*256 + d] = pack2(o_w[(size_t)d*256 + 2*c2],
                                       o_w[(size_t)d*256 + 2*c2 + 1]);
}

// ============================================================================
// k1: LayerNorm + low-rank down projections
// ============================================================================
__global__ void __launch_bounds__(256) k1_ln_down(
    const float* __restrict__ x, const float* __restrict__ norm_w,
    const float* __restrict__ q_a_w, const float* __restrict__ q_bias,
    const float* __restrict__ kv_a_w, const float* __restrict__ kv_bias)
{
    __shared__ __align__(16) float xs[TOKTILE][CC];
    const int tok0 = blockIdx.x * TOKTILE;
    const int tid = threadIdx.x;

    const float4* xsrc = (const float4*)(x + (size_t)tok0 * CC);
    float4* xd = (float4*)xs;
#pragma unroll
    for (int i = 0; i < 4; i++) xd[tid + i*256] = xsrc[tid + i*256];
    __syncthreads();

    const int w = tid >> 5, l = tid & 31;
    for (int t = w; t < TOKTILE; t += 8) {
        float s = 0.f, sq = 0.f;
#pragma unroll
        for (int i = 0; i < 8; i++) { float v = xs[t][l + 32*i]; s += v; sq += v*v; }
#pragma unroll
        for (int o = 16; o; o >>= 1) {
            s  += __shfl_xor_sync(0xffffffffu, s,  o);
            sq += __shfl_xor_sync(0xffffffffu, sq, o);
        }
        float mean = s * (1.f/CC);
        float var  = sq * (1.f/CC) - mean*mean;
        float rstd = 1.f / sqrtf(var + 1e-5f);
#pragma unroll
        for (int i = 0; i < 8; i++) {
            int c = l + 32*i;
            xs[t][c] = (xs[t][c] - mean) * rstd * norm_w[c];
        }
    }
    __syncthreads();

    for (int o = tid; o < TOKTILE*96; o += 256) {
        const int t = o / 96, r = o % 96;
        const float4* wr;
        float bias;
        if (r < QR) { wr = (const float4*)(q_a_w + (size_t)r*CC); bias = q_bias[r]; }
        else        { wr = (const float4*)(kv_a_w + (size_t)(r-QR)*CC); bias = kv_bias[r-QR]; }
        const float4* xv = (const float4*)xs[t];
        float a0=0.f, a1=0.f, a2=0.f, a3=0.f;
#pragma unroll 8
        for (int i = 0; i < 64; i++) {
            float4 wv = wr[i]; float4 vv = xv[i];
            a0 += wv.x*vv.x; a1 += wv.y*vv.y; a2 += wv.z*vv.z; a3 += wv.w*vv.w;
        }
        g_lat[(size_t)(tok0 + t)*96 + r] = (a0+a1) + (a2+a3) + bias;
    }
}

__device__ __forceinline__ void load16(const float* p, float* la) {
    const float4* lp = (const float4*)p;
    float4 a = lp[0], b = lp[1], c = lp[2], d = lp[3];
    la[0]=a.x; la[1]=a.y; la[2]=a.z; la[3]=a.w;
    la[4]=b.x; la[5]=b.y; la[6]=b.z; la[7]=b.w;
    la[8]=c.x; la[9]=c.y; la[10]=c.z; la[11]=c.w;
    la[12]=d.x; la[13]=d.y; la[14]=d.z; la[15]=d.w;
}

// ============================================================================
// k2: up projections; writes q (scaled, tf32-rounded), k/v (tf32-rounded), [B,H,T,Dh].
// ============================================================================
__global__ void __launch_bounds__(256) k2_up(
    const float* __restrict__ q_b_w, const float* __restrict__ k_w,
    const float* __restrict__ v_w)
{
    __shared__ __align__(16) float ls[96][TOKTILE];
    const int tok0 = blockIdx.x * TOKTILE;
    const int tid = threadIdx.x;
    const float SC = 0.17677669529663687f * 1.4426950408889634f; // 1/sqrt(32)*log2(e)

    for (int i = tid; i < TOKTILE*96; i += 256) {
        int t = i / 96, r = i % 96;
        ls[r][t] = g_lat[(size_t)(tok0 + t)*96 + r];
    }
    __syncthreads();

    const int c = tid, h = c >> 5, d = c & 31;
    float aq[16], ak[16], av[16];
#pragma unroll
    for (int t = 0; t < 16; t++) { aq[t]=0.f; ak[t]=0.f; av[t]=0.f; }

    const float* wq = q_b_w + (size_t)c * QR;
#pragma unroll 4
    for (int r = 0; r < QR; r++) {
        float wv = wq[r];
        float la[16]; load16(ls[r], la);
#pragma unroll
        for (int t = 0; t < 16; t++) aq[t] += la[t] * wv;
    }
    const float* wk = k_w + (size_t)c * KVR;
    const float* wvv = v_w + (size_t)c * KVR;
#pragma unroll 4
    for (int r = 0; r < KVR; r++) {
        float wk_ = wk[r], wv_ = wvv[r];
        float la[16]; load16(ls[QR + r], la);
#pragma unroll
        for (int t = 0; t < 16; t++) { ak[t] += la[t]*wk_; av[t] += la[t]*wv_; }
    }

    const int b = tok0 / TT, t0 = tok0 % TT;
    const size_t base = ((size_t)(b*HH + h)*TT + t0)*DH + d;
#pragma unroll
    for (int t = 0; t < 16; t++) {
        g_q[base + (size_t)t*DH] = cvt_tf32f(aq[t] * SC);
        g_k[base + (size_t)t*DH] = cvt_tf32f(ak[t]);
        g_v[base + (size_t)t*DH] = cvt_tf32f(av[t]);
    }
}

// ============================================================================
// k3: flash attention on tensor cores (mma m16n8k8 tf32), ZERO cvt in hot loop.
// grid (T/64, B*H); 4 warps; warp owns 16 query rows; 64-key K/V smem tiles.
// ============================================================================
#define KSTR 36
#define PSTR 68
__global__ void __launch_bounds__(128) k3_attn_mma()
{
    __shared__ __align__(16) float Ks[64*KSTR];
    __shared__ __align__(16) float Vs[64*KSTR];
    __shared__ __align__(16) unsigned Ps[4*16*PSTR];

    const int tid = threadIdx.x;
    const int w = tid >> 5, lane = tid & 31;
    const int gid = lane >> 2, tig = lane & 3;
    const int bh = blockIdx.y;
    const int qbase = blockIdx.x * 64 + w * 16;
    const int r0 = qbase + gid, r1 = r0 + 8;

    // Q fragments (already scaled + tf32-rounded in k2): raw bits
    const float* qptr = g_q + (size_t)bh*TT*DH;
    unsigned qA[4][4];
#pragma unroll
    for (int kc = 0; kc < 4; kc++) {
        qA[kc][0] = __float_as_uint(qptr[(size_t)r0*DH + 8*kc + tig]);
        qA[kc][1] = __float_as_uint(qptr[(size_t)r1*DH + 8*kc + tig]);
        qA[kc][2] = __float_as_uint(qptr[(size_t)r0*DH + 8*kc + tig + 4]);
        qA[kc][3] = __float_as_uint(qptr[(size_t)r1*DH + 8*kc + tig + 4]);
    }

    float y[4][4];
#pragma unroll
    for (int i = 0; i < 4; i++)
#pragma unroll
        for (int j = 0; j < 4; j++) y[i][j] = 0.f;
    float m0 = -3.0e38f, m1 = -3.0e38f, l0 = 0.f, l1 = 0.f;

    const float4* kg = (const float4*)(g_k + (size_t)bh*TT*DH);
    const float4* vg = (const float4*)(g_v + (size_t)bh*TT*DH);
    unsigned* myPs = Ps + w*16*PSTR;

    for (int kt = 0; kt < TT; kt += 64) {
        __syncthreads();
#pragma unroll
        for (int i = 0; i < 4; i++) {
            int idx = tid + 128*i;
            int row = idx >> 3, c4 = idx & 7;
            ((float4*)(Ks + row*KSTR))[c4] = kg[((size_t)(kt + row))*8 + c4];
            ((float4*)(Vs + row*KSTR))[c4] = vg[((size_t)(kt + row))*8 + c4];
        }
        __syncthreads();

        // S = Q K^T
        float s[8][4];
#pragma unroll
        for (int nc = 0; nc < 8; nc++) {
            s[nc][0] = s[nc][1] = s[nc][2] = s[nc][3] = 0.f;
#pragma unroll
            for (int kc = 0; kc < 4; kc++) {
                const float* kb = Ks + (8*nc + gid)*KSTR + 8*kc + tig;
                unsigned b0 = __float_as_uint(kb[0]);
                unsigned b1 = __float_as_uint(kb[4]);
                mma_tf32(s[nc][0], s[nc][1], s[nc][2], s[nc][3],
                         qA[kc][0], qA[kc][1], qA[kc][2], qA[kc][3], b0, b1);
            }
        }

        // online softmax (rows r0, r1), log2 domain
        float mx0 = s[0][0], mx1 = s[0][2];
#pragma unroll
        for (int nc = 0; nc < 8; nc++) {
            mx0 = fmaxf(mx0, fmaxf(s[nc][0], s[nc][1]));
            mx1 = fmaxf(mx1, fmaxf(s[nc][2], s[nc][3]));
        }
        mx0 = fmaxf(mx0, __shfl_xor_sync(0xffffffffu, mx0, 1));
        mx0 = fmaxf(mx0, __shfl_xor_sync(0xffffffffu, mx0, 2));
        mx1 = fmaxf(mx1, __shfl_xor_sync(0xffffffffu, mx1, 1));
        mx1 = fmaxf(mx1, __shfl_xor_sync(0xffffffffu, mx1, 2));
        float mn0 = fmaxf(m0, mx0), mn1 = fmaxf(m1, mx1);
        float c0 = exp2f(m0 - mn0), c1 = exp2f(m1 - mn1);
        m0 = mn0; m1 = mn1;
        l0 *= c0; l1 *= c1;
#pragma unroll
        for (int nc2 = 0; nc2 < 4; nc2++) {
            y[nc2][0] *= c0; y[nc2][1] *= c0;
            y[nc2][2] *= c1; y[nc2][3] *= c1;
        }
        float ps0 = 0.f, ps1 = 0.f;
#pragma unroll
        for (int nc = 0; nc < 8; nc++) {
            s[nc][0] = exp2f(s[nc][0] - m0);
            s[nc][1] = exp2f(s[nc][1] - m0);
            s[nc][2] = exp2f(s[nc][2] - m1);
            s[nc][3] = exp2f(s[nc][3] - m1);
            ps0 += s[nc][0] + s[nc][1];
            ps1 += s[nc][2] + s[nc][3];
        }
        ps0 += __shfl_xor_sync(0xffffffffu, ps0, 1);
        ps0 += __shfl_xor_sync(0xffffffffu, ps0, 2);
        ps1 += __shfl_xor_sync(0xffffffffu, ps1, 1);
        ps1 += __shfl_xor_sync(0xffffffffu, ps1, 2);
        l0 += ps0; l1 += ps1;

        // store P (raw fp32 bits; truncation bias cancels in normalization)
#pragma unroll
        for (int nc = 0; nc < 8; nc++) {
            uint2 v0; v0.x = __float_as_uint(s[nc][0]); v0.y = __float_as_uint(s[nc][1]);
            uint2 v1; v1.x = __float_as_uint(s[nc][2]); v1.y = __float_as_uint(s[nc][3]);
            *(uint2*)&myPs[gid*PSTR + 8*nc + 2*tig]     = v0;
            *(uint2*)&myPs[(gid+8)*PSTR + 8*nc + 2*tig] = v1;
        }
        __syncwarp();

        // Y += P V
#pragma unroll
        for (int kc = 0; kc < 8; kc++) {
            unsigned a0 = myPs[gid*PSTR     + 8*kc + tig];
            unsigned a1 = myPs[(gid+8)*PSTR + 8*kc + tig];
            unsigned a2 = myPs[gid*PSTR     + 8*kc + tig + 4];
            unsigned a3 = myPs[(gid+8)*PSTR + 8*kc + tig + 4];
#pragma unroll
            for (int nc2 = 0; nc2 < 4; nc2++) {
                unsigned b0 = __float_as_uint(Vs[(8*kc + tig)*KSTR     + 8*nc2 + gid]);
                unsigned b1 = __float_as_uint(Vs[(8*kc + tig + 4)*KSTR + 8*nc2 + gid]);
                mma_tf32(y[nc2][0], y[nc2][1], y[nc2][2], y[nc2][3],
                         a0, a1, a2, a3, b0, b1);
            }
        }
        __syncwarp();
    }

    const float inv0 = 1.0f / l0, inv1 = 1.0f / l1;
    const int b = bh >> 3, h = bh & 7;
#pragma unroll
    for (int nc2 = 0; nc2 < 4; nc2++) {
        int col = h*DH + nc2*8 + 2*tig;
        float2 o0; o0.x = y[nc2][0]*inv0; o0.y = y[nc2][1]*inv0;
        float2 o1; o1.x = y[nc2][2]*inv1; o1.y = y[nc2][3]*inv1;
        *(float2*)&g_y[(size_t)(b*TT + r0)*CC + col] = o0;
        *(float2*)&g_y[(size_t)(b*TT + r1)*CC + col] = o1;
    }
}

// ============================================================================
// k4: output projection + gamma + residual. Barrier-free main loop:
// weights from L2 (g_owT2 packed pairs), y broadcast from smem.
// ============================================================================
__global__ void __launch_bounds__(256) k4_oproj(
    const float* __restrict__ x, const float* __restrict__ gamma,
    float* __restrict__ out)
{
    __shared__ __align__(16) float ys[TOKTILE][CC];
    const int tok0 = blockIdx.x * TOKTILE;
    const int tid = threadIdx.x;

    const float4* ysrc = (const float4*)(g_y + (size_t)tok0 * CC);
    float4* yd = (float4*)ys;
#pragma unroll
    for (int i = 0; i < 4; i++) yd[tid + i*256] = ysrc[tid + i*256];
    __syncthreads();

    u64 acc[16];
#pragma unroll
    for (int t = 0; t < 16; t++) acc[t] = 0ull;

    const u64* wT = g_owT2;
#pragma unroll 4
    for (int c2 = 0; c2 < 128; c2++) {
        u64 w2 = wT[(size_t)c2*256 + tid];          // coalesced, L2-resident
        const float* yb = &ys[0][2*c2];
#pragma unroll
        for (int t = 0; t < 16; t++) {
            u64 yv = *(const u64*)(yb + t*CC);      // broadcast LDS.64
            acc[t] = fma2(yv, w2, acc[t]);
        }
    }

    const float g = gamma[tid];
#pragma unroll
    for (int t = 0; t < 16; t++) {
        float2 a = unpack2(acc[t]);
        size_t o = (size_t)(tok0 + t)*CC + tid;
        out[o] = x[o] + g * (a.x + a.y);
    }
}

// ============================================================================
extern "C" void kernel_launch(void* const* d_in, const int* in_sizes, int n_in,
                              void* d_out, int out_size)
{
    const float* x       = (const float*)d_in[0];
    const float* q_a_w   = (const float*)d_in[1];
    const float* q_bias  = (const float*)d_in[2];
    const float* q_b_w   = (const float*)d_in[3];
    const float* kv_a_w  = (const float*)d_in[4];
    const float* kv_bias = (const float*)d_in[5];
    const float* k_w     = (const float*)d_in[6];
    const float* v_w     = (const float*)d_in[7];
    const float* o_w     = (const float*)d_in[8];
    const float* norm_w  = (const float*)d_in[9];
    const float* gamma   = (const float*)d_in[10];
    float* out = (float*)d_out;

    k0_twt<<<128, 256>>>(o_w);
    k1_ln_down<<<NBLK, 256>>>(x, norm_w, q_a_w, q_bias, kv_a_w, kv_bias);
    k2_up<<<NBLK, 256>>>(q_b_w, k_w, v_w);
    dim3 g3(TT/64, BB*HH);
    k3_attn_mma<<<g3, 128>>>();
    k4_oproj<<<NBLK, 256>>>(x, gamma, out);
}

// round 6
// speedup vs baseline: 3.5098x; 1.9809x over previous
#include <cuda_runtime.h>
#include <cstdint>

#define BB 4
#define TT 2048
#define CC 256
#define HH 8
#define DH 32
#define QR 32
#define KVR 64
#define NTOK (BB*TT)          // 8192
#define TOKTILE 16
#define NBLK (NTOK/TOKTILE)   // 512

// ---------------- scratch (device globals; no allocation allowed) ----------------
__device__ float g_lat[(size_t)NTOK*96];                 // [tok][96]
__device__ float g_q[(size_t)BB*HH*TT*DH];               // [B,H,T,Dh]  (tf32 bits, pre-scaled)
__device__ float g_k[(size_t)BB*HH*TT*DH];               // tf32 bits
__device__ float g_v[(size_t)BB*HH*TT*DH];               // tf32 bits
__device__ float g_y[(size_t)NTOK*CC];                   // [B,T,C]
__device__ unsigned long long g_owT2[(size_t)128*256];   // packed o_w^T pairs [c2][d]
__device__ ulonglong2 g_wAT4[(size_t)64*96];             // down-proj W^T packed [c4][r]
__device__ float g_wqT[(size_t)QR*256];                  // q_b_w^T [r][c]
__device__ float g_wkT[(size_t)KVR*256];                 // k_w^T  [r][c]
__device__ float g_wvT[(size_t)KVR*256];                 // v_w^T  [r][c]

typedef unsigned long long u64;

// ---------------- packed f32x2 helpers ----------------
__device__ __forceinline__ u64 pack2(float lo, float hi) {
    u64 r; asm("mov.b64 %0, {%1, %2};" : "=l"(r) : "f"(lo), "f"(hi)); return r;
}
__device__ __forceinline__ float2 unpack2(u64 v) {
    float2 r; asm("mov.b64 {%0, %1}, %2;" : "=f"(r.x), "=f"(r.y) : "l"(v)); return r;
}
__device__ __forceinline__ u64 fma2(u64 a, u64 b, u64 c) {
    u64 d; asm("fma.rn.f32x2 %0, %1, %2, %3;" : "=l"(d) : "l"(a), "l"(b), "l"(c)); return d;
}

// ---------------- tf32 helpers ----------------
__device__ __forceinline__ float cvt_tf32f(float f) {
    unsigned r; asm("cvt.rna.tf32.f32 %0, %1;" : "=r"(r) : "f"(f));
    return __uint_as_float(r);
}
__device__ __forceinline__ void mma_tf32(float& d0, float& d1, float& d2, float& d3,
    unsigned a0, unsigned a1, unsigned a2, unsigned a3, unsigned b0, unsigned b1) {
    asm volatile("mma.sync.aligned.m16n8k8.row.col.f32.tf32.tf32.f32 "
        "{%0,%1,%2,%3}, {%4,%5,%6,%7}, {%8,%9}, {%0,%1,%2,%3};"
        : "+f"(d0), "+f"(d1), "+f"(d2), "+f"(d3)
        : "r"(a0), "r"(a1), "r"(a2), "r"(a3), "r"(b0), "r"(b1));
}

// ============================================================================
// k0: one-time weight repack/transpose (reads coalesced where it matters;
// scattered writes are a tiny one-time cost, arrays stay L2-resident).
// ranges: [0,32768) owT2 | [32768,38912) wAT4 | [38912,47104) wqT
//         [47104,63488) wkT | [63488,79872) wvT
// ============================================================================
__global__ void __launch_bounds__(256) k0_prep(
    const float* __restrict__ o_w,
    const float* __restrict__ q_a_w, const float* __restrict__ kv_a_w,
    const float* __restrict__ q_b_w, const float* __restrict__ k_w,
    const float* __restrict__ v_w)
{
    int i = blockIdx.x * 256 + threadIdx.x;
    if (i < 32768) {
        int d = i >> 7, c2 = i & 127;
        g_owT2[(size_t)c2*256 + d] = pack2(o_w[(size_t)d*256 + 2*c2],
                                           o_w[(size_t)d*256 + 2*c2 + 1]);
    } else if (i < 38912) {
        int j = i - 32768;
        int c4 = j / 96, r = j % 96;
        const float* src = (r < QR) ? (q_a_w + (size_t)r*CC)
                                    : (kv_a_w + (size_t)(r-QR)*CC);
        ulonglong2 v;
        v.x = pack2(src[4*c4],     src[4*c4 + 1]);
        v.y = pack2(src[4*c4 + 2], src[4*c4 + 3]);
        g_wAT4[(size_t)c4*96 + r] = v;
    } else if (i < 47104) {
        int j = i - 38912;               // j = r*256 + c
        int r = j >> 8, c = j & 255;
        g_wqT[j] = q_b_w[(size_t)c*QR + r];
    } else if (i < 63488) {
        int j = i - 47104;
        int r = j >> 8, c = j & 255;
        g_wkT[j] = k_w[(size_t)c*KVR + r];
    } else if (i < 79872) {
        int j = i - 63488;
        int r = j >> 8, c = j & 255;
        g_wvT[j] = v_w[(size_t)c*KVR + r];
    }
}

// ============================================================================
// k1: LayerNorm + low-rank down projections. GEMM phase uses transposed
// packed weights (coalesced LDG.128) + broadcast LDS.128 + f32x2 FMA.
// ============================================================================
__global__ void __launch_bounds__(256) k1_ln_down(
    const float* __restrict__ x, const float* __restrict__ norm_w,
    const float* __restrict__ q_bias, const float* __restrict__ kv_bias)
{
    __shared__ __align__(16) float xs[TOKTILE][CC];
    const int tok0 = blockIdx.x * TOKTILE;
    const int tid = threadIdx.x;

    const float4* xsrc = (const float4*)(x + (size_t)tok0 * CC);
    float4* xd = (float4*)xs;
#pragma unroll
    for (int i = 0; i < 4; i++) xd[tid + i*256] = xsrc[tid + i*256];
    __syncthreads();

    const int w = tid >> 5, l = tid & 31;
    for (int t = w; t < TOKTILE; t += 8) {
        float s = 0.f, sq = 0.f;
#pragma unroll
        for (int i = 0; i < 8; i++) { float v = xs[t][l + 32*i]; s += v; sq += v*v; }
#pragma unroll
        for (int o = 16; o; o >>= 1) {
            s  += __shfl_xor_sync(0xffffffffu, s,  o);
            sq += __shfl_xor_sync(0xffffffffu, sq, o);
        }
        float mean = s * (1.f/CC);
        float var  = sq * (1.f/CC) - mean*mean;
        float rstd = 1.f / sqrtf(var + 1e-5f);
#pragma unroll
        for (int i = 0; i < 8; i++) {
            int c = l + 32*i;
            xs[t][c] = (xs[t][c] - mean) * rstd * norm_w[c];
        }
    }
    __syncthreads();

    // GEMM: 192 active threads; thread = (r, token-half). Warp lanes span
    // consecutive r -> weight LDG fully coalesced.
    if (tid < 192) {
        const int r = tid % 96, th = tid / 96;
        const int t0 = th * 8;
        u64 acc[8];
#pragma unroll
        for (int tt = 0; tt < 8; tt++) acc[tt] = 0ull;

#pragma unroll 8
        for (int c4 = 0; c4 < 64; c4++) {
            ulonglong2 w4 = g_wAT4[(size_t)c4*96 + r];   // coalesced LDG.128
#pragma unroll
            for (int tt = 0; tt < 8; tt++) {
                ulonglong2 xv = *(const ulonglong2*)&xs[t0 + tt][4*c4];  // broadcast
                acc[tt] = fma2(xv.x, w4.x, acc[tt]);
                acc[tt] = fma2(xv.y, w4.y, acc[tt]);
            }
        }
        const float bias = (r < QR) ? q_bias[r] : kv_bias[r - QR];
#pragma unroll
        for (int tt = 0; tt < 8; tt++) {
            float2 a = unpack2(acc[tt]);
            g_lat[(size_t)(tok0 + t0 + tt)*96 + r] = a.x + a.y + bias;   // coalesced
        }
    }
}

// ============================================================================
// k2: up projections with transposed weights (coalesced LDG) + token-pair
// f32x2 accumulators. Writes q (scaled, tf32-rounded), k/v (tf32-rounded).
// ============================================================================
__global__ void __launch_bounds__(256) k2_up()
{
    __shared__ __align__(16) float ls[96][TOKTILE];   // [r][t]
    const int tok0 = blockIdx.x * TOKTILE;
    const int tid = threadIdx.x;
    const float SC = 0.17677669529663687f * 1.4426950408889634f; // 1/sqrt(32)*log2(e)

    for (int i = tid; i < TOKTILE*96; i += 256) {
        int t = i / 96, r = i % 96;
        ls[r][t] = g_lat[(size_t)(tok0 + t)*96 + r];
    }
    __syncthreads();

    const int c = tid, h = c >> 5, d = c & 31;
    u64 aq[8], ak[8], av[8];
#pragma unroll
    for (int p = 0; p < 8; p++) { aq[p] = 0ull; ak[p] = 0ull; av[p] = 0ull; }

#pragma unroll 4
    for (int r = 0; r < QR; r++) {
        float wv = g_wqT[(size_t)r*256 + c];          // coalesced LDG.32
        u64 w2 = pack2(wv, wv);
        const ulonglong2* lp = (const ulonglong2*)ls[r];
#pragma unroll
        for (int p = 0; p < 4; p++) {
            ulonglong2 lv = lp[p];                     // broadcast LDS.128
            aq[2*p]   = fma2(lv.x, w2, aq[2*p]);
            aq[2*p+1] = fma2(lv.y, w2, aq[2*p+1]);
        }
    }
#pragma unroll 4
    for (int r = 0; r < KVR; r++) {
        float wk_ = g_wkT[(size_t)r*256 + c];
        float wv_ = g_wvT[(size_t)r*256 + c];
        u64 wk2 = pack2(wk_, wk_), wv2 = pack2(wv_, wv_);
        const ulonglong2* lp = (const ulonglong2*)ls[QR + r];
#pragma unroll
        for (int p = 0; p < 4; p++) {
            ulonglong2 lv = lp[p];
            ak[2*p]   = fma2(lv.x, wk2, ak[2*p]);
            ak[2*p+1] = fma2(lv.y, wk2, ak[2*p+1]);
            av[2*p]   = fma2(lv.x, wv2, av[2*p]);
            av[2*p+1] = fma2(lv.y, wv2, av[2*p+1]);
        }
    }

    const int b = tok0 / TT, t0 = tok0 % TT;
    const size_t base = ((size_t)(b*HH + h)*TT + t0)*DH + d;
#pragma unroll
    for (int p = 0; p < 8; p++) {
        float2 q2v = unpack2(aq[p]);
        float2 k2v = unpack2(ak[p]);
        float2 v2v = unpack2(av[p]);
        g_q[base + (size_t)(2*p)*DH]   = cvt_tf32f(q2v.x * SC);
        g_q[base + (size_t)(2*p+1)*DH] = cvt_tf32f(q2v.y * SC);
        g_k[base + (size_t)(2*p)*DH]   = cvt_tf32f(k2v.x);
        g_k[base + (size_t)(2*p+1)*DH] = cvt_tf32f(k2v.y);
        g_v[base + (size_t)(2*p)*DH]   = cvt_tf32f(v2v.x);
        g_v[base + (size_t)(2*p+1)*DH] = cvt_tf32f(v2v.y);
    }
}

// ============================================================================
// k3: flash attention on tensor cores (mma m16n8k8 tf32), zero cvt in hot loop.
// grid (T/64, B*H); 4 warps; warp owns 16 query rows; 64-key K/V smem tiles.
// ============================================================================
#define KSTR 36
#define PSTR 68
__global__ void __launch_bounds__(128) k3_attn_mma()
{
    __shared__ __align__(16) float Ks[64*KSTR];
    __shared__ __align__(16) float Vs[64*KSTR];
    __shared__ __align__(16) unsigned Ps[4*16*PSTR];

    const int tid = threadIdx.x;
    const int w = tid >> 5, lane = tid & 31;
    const int gid = lane >> 2, tig = lane & 3;
    const int bh = blockIdx.y;
    const int qbase = blockIdx.x * 64 + w * 16;
    const int r0 = qbase + gid, r1 = r0 + 8;

    const float* qptr = g_q + (size_t)bh*TT*DH;
    unsigned qA[4][4];
#pragma unroll
    for (int kc = 0; kc < 4; kc++) {
        qA[kc][0] = __float_as_uint(qptr[(size_t)r0*DH + 8*kc + tig]);
        qA[kc][1] = __float_as_uint(qptr[(size_t)r1*DH + 8*kc + tig]);
        qA[kc][2] = __float_as_uint(qptr[(size_t)r0*DH + 8*kc + tig + 4]);
        qA[kc][3] = __float_as_uint(qptr[(size_t)r1*DH + 8*kc + tig + 4]);
    }

    float y[4][4];
#pragma unroll
    for (int i = 0; i < 4; i++)
#pragma unroll
        for (int j = 0; j < 4; j++) y[i][j] = 0.f;
    float m0 = -3.0e38f, m1 = -3.0e38f, l0 = 0.f, l1 = 0.f;

    const float4* kg = (const float4*)(g_k + (size_t)bh*TT*DH);
    const float4* vg = (const float4*)(g_v + (size_t)bh*TT*DH);
    unsigned* myPs = Ps + w*16*PSTR;

    for (int kt = 0; kt < TT; kt += 64) {
        __syncthreads();
#pragma unroll
        for (int i = 0; i < 4; i++) {
            int idx = tid + 128*i;
            int row = idx >> 3, c4 = idx & 7;
            ((float4*)(Ks + row*KSTR))[c4] = kg[((size_t)(kt + row))*8 + c4];
            ((float4*)(Vs + row*KSTR))[c4] = vg[((size_t)(kt + row))*8 + c4];
        }
        __syncthreads();

        float s[8][4];
#pragma unroll
        for (int nc = 0; nc < 8; nc++) {
            s[nc][0] = s[nc][1] = s[nc][2] = s[nc][3] = 0.f;
#pragma unroll
            for (int kc = 0; kc < 4; kc++) {
                const float* kb = Ks + (8*nc + gid)*KSTR + 8*kc + tig;
                unsigned b0 = __float_as_uint(kb[0]);
                unsigned b1 = __float_as_uint(kb[4]);
                mma_tf32(s[nc][0], s[nc][1], s[nc][2], s[nc][3],
                         qA[kc][0], qA[kc][1], qA[kc][2], qA[kc][3], b0, b1);
            }
        }

        float mx0 = s[0][0], mx1 = s[0][2];
#pragma unroll
        for (int nc = 0; nc < 8; nc++) {
            mx0 = fmaxf(mx0, fmaxf(s[nc][0], s[nc][1]));
            mx1 = fmaxf(mx1, fmaxf(s[nc][2], s[nc][3]));
        }
        mx0 = fmaxf(mx0, __shfl_xor_sync(0xffffffffu, mx0, 1));
        mx0 = fmaxf(mx0, __shfl_xor_sync(0xffffffffu, mx0, 2));
        mx1 = fmaxf(mx1, __shfl_xor_sync(0xffffffffu, mx1, 1));
        mx1 = fmaxf(mx1, __shfl_xor_sync(0xffffffffu, mx1, 2));
        float mn0 = fmaxf(m0, mx0), mn1 = fmaxf(m1, mx1);
        float c0 = exp2f(m0 - mn0), c1 = exp2f(m1 - mn1);
        m0 = mn0; m1 = mn1;
        l0 *= c0; l1 *= c1;
#pragma unroll
        for (int nc2 = 0; nc2 < 4; nc2++) {
            y[nc2][0] *= c0; y[nc2][1] *= c0;
            y[nc2][2] *= c1; y[nc2][3] *= c1;
        }
        float ps0 = 0.f, ps1 = 0.f;
#pragma unroll
        for (int nc = 0; nc < 8; nc++) {
            s[nc][0] = exp2f(s[nc][0] - m0);
            s[nc][1] = exp2f(s[nc][1] - m0);
            s[nc][2] = exp2f(s[nc][2] - m1);
            s[nc][3] = exp2f(s[nc][3] - m1);
            ps0 += s[nc][0] + s[nc][1];
            ps1 += s[nc][2] + s[nc][3];
        }
        ps0 += __shfl_xor_sync(0xffffffffu, ps0, 1);
        ps0 += __shfl_xor_sync(0xffffffffu, ps0, 2);
        ps1 += __shfl_xor_sync(0xffffffffu, ps1, 1);
        ps1 += __shfl_xor_sync(0xffffffffu, ps1, 2);
        l0 += ps0; l1 += ps1;

#pragma unroll
        for (int nc = 0; nc < 8; nc++) {
            uint2 v0; v0.x = __float_as_uint(s[nc][0]); v0.y = __float_as_uint(s[nc][1]);
            uint2 v1; v1.x = __float_as_uint(s[nc][2]); v1.y = __float_as_uint(s[nc][3]);
            *(uint2*)&myPs[gid*PSTR + 8*nc + 2*tig]     = v0;
            *(uint2*)&myPs[(gid+8)*PSTR + 8*nc + 2*tig] = v1;
        }
        __syncwarp();

#pragma unroll
        for (int kc = 0; kc < 8; kc++) {
            unsigned a0 = myPs[gid*PSTR     + 8*kc + tig];
            unsigned a1 = myPs[(gid+8)*PSTR + 8*kc + tig];
            unsigned a2 = myPs[gid*PSTR     + 8*kc + tig + 4];
            unsigned a3 = myPs[(gid+8)*PSTR + 8*kc + tig + 4];
#pragma unroll
            for (int nc2 = 0; nc2 < 4; nc2++) {
                unsigned b0 = __float_as_uint(Vs[(8*kc + tig)*KSTR     + 8*nc2 + gid]);
                unsigned b1 = __float_as_uint(Vs[(8*kc + tig + 4)*KSTR + 8*nc2 + gid]);
                mma_tf32(y[nc2][0], y[nc2][1], y[nc2][2], y[nc2][3],
                         a0, a1, a2, a3, b0, b1);
            }
        }
        __syncwarp();
    }

    const float inv0 = 1.0f / l0, inv1 = 1.0f / l1;
    const int b = bh >> 3, h = bh & 7;
#pragma unroll
    for (int nc2 = 0; nc2 < 4; nc2++) {
        int col = h*DH + nc2*8 + 2*tig;
        float2 o0; o0.x = y[nc2][0]*inv0; o0.y = y[nc2][1]*inv0;
        float2 o1; o1.x = y[nc2][2]*inv1; o1.y = y[nc2][3]*inv1;
        *(float2*)&g_y[(size_t)(b*TT + r0)*CC + col] = o0;
        *(float2*)&g_y[(size_t)(b*TT + r1)*CC + col] = o1;
    }
}

// ============================================================================
// k4: output projection + gamma + residual. Barrier-free main loop.
// ============================================================================
__global__ void __launch_bounds__(256) k4_oproj(
    const float* __restrict__ x, const float* __restrict__ gamma,
    float* __restrict__ out)
{
    __shared__ __align__(16) float ys[TOKTILE][CC];
    const int tok0 = blockIdx.x * TOKTILE;
    const int tid = threadIdx.x;

    const float4* ysrc = (const float4*)(g_y + (size_t)tok0 * CC);
    float4* yd = (float4*)ys;
#pragma unroll
    for (int i = 0; i < 4; i++) yd[tid + i*256] = ysrc[tid + i*256];
    __syncthreads();

    u64 acc[16];
#pragma unroll
    for (int t = 0; t < 16; t++) acc[t] = 0ull;

    const u64* wT = g_owT2;
#pragma unroll 4
    for (int c2 = 0; c2 < 128; c2++) {
        u64 w2 = wT[(size_t)c2*256 + tid];
        const float* yb = &ys[0][2*c2];
#pragma unroll
        for (int t = 0; t < 16; t++) {
            u64 yv = *(const u64*)(yb + t*CC);
            acc[t] = fma2(yv, w2, acc[t]);
        }
    }

    const float g = gamma[tid];
#pragma unroll
    for (int t = 0; t < 16; t++) {
        float2 a = unpack2(acc[t]);
        size_t o = (size_t)(tok0 + t)*CC + tid;
        out[o] = x[o] + g * (a.x + a.y);
    }
}

// ============================================================================
extern "C" void kernel_launch(void* const* d_in, const int* in_sizes, int n_in,
                              void* d_out, int out_size)
{
    const float* x       = (const float*)d_in[0];
    const float* q_a_w   = (const float*)d_in[1];
    const float* q_bias  = (const float*)d_in[2];
    const float* q_b_w   = (const float*)d_in[3];
    const float* kv_a_w  = (const float*)d_in[4];
    const float* kv_bias = (const float*)d_in[5];
    const float* k_w     = (const float*)d_in[6];
    const float* v_w     = (const float*)d_in[7];
    const float* o_w     = (const float*)d_in[8];
    const float* norm_w  = (const float*)d_in[9];
    const float* gamma   = (const float*)d_in[10];
    float* out = (float*)d_out;

    k0_prep<<<312, 256>>>(o_w, q_a_w, kv_a_w, q_b_w, k_w, v_w);
    k1_ln_down<<<NBLK, 256>>>(x, norm_w, q_bias, kv_bias);
    k2_up<<<NBLK, 256>>>();
    dim3 g3(TT/64, BB*HH);
    k3_attn_mma<<<g3, 128>>>();
    k4_oproj<<<NBLK, 256>>>(x, gamma, out);
}

// round 7
// speedup vs baseline: 3.8569x; 1.0989x over previous
#include <cuda_runtime.h>
#include <cstdint>

#define BB 4
#define TT 2048
#define CC 256
#define HH 8
#define DH 32
#define QR 32
#define KVR 64
#define NTOK (BB*TT)          // 8192
#define TOKTILE 16
#define NBLK (NTOK/TOKTILE)   // 512

// ---------------- scratch (device globals; no allocation allowed) ----------------
__device__ float g_lat[(size_t)NTOK*96];                 // [tok][96]
__device__ float g_q[(size_t)BB*HH*TT*DH];               // [B,H,T,Dh]  (tf32 bits, pre-scaled)
__device__ float g_k[(size_t)BB*HH*TT*DH];               // tf32 bits
__device__ float g_v[(size_t)BB*HH*TT*DH];               // tf32 bits
__device__ float g_y[(size_t)NTOK*CC];                   // [B,T,C]
__device__ unsigned long long g_owT2[(size_t)128*256];   // packed o_w^T pairs [c2][d]
__device__ ulonglong2 g_wAT4[(size_t)64*96];             // down-proj W^T packed [c4][r]
__device__ float g_wqT[(size_t)QR*256];                  // q_b_w^T [r][c]
__device__ float g_wkT[(size_t)KVR*256];                 // k_w^T  [r][c]
__device__ float g_wvT[(size_t)KVR*256];                 // v_w^T  [r][c]

typedef unsigned long long u64;

// ---------------- packed f32x2 helpers ----------------
__device__ __forceinline__ u64 pack2(float lo, float hi) {
    u64 r; asm("mov.b64 %0, {%1, %2};" : "=l"(r) : "f"(lo), "f"(hi)); return r;
}
__device__ __forceinline__ float2 unpack2(u64 v) {
    float2 r; asm("mov.b64 {%0, %1}, %2;" : "=f"(r.x), "=f"(r.y) : "l"(v)); return r;
}
__device__ __forceinline__ u64 fma2(u64 a, u64 b, u64 c) {
    u64 d; asm("fma.rn.f32x2 %0, %1, %2, %3;" : "=l"(d) : "l"(a), "l"(b), "l"(c)); return d;
}

// ---------------- tf32 helpers ----------------
__device__ __forceinline__ float cvt_tf32f(float f) {
    unsigned r; asm("cvt.rna.tf32.f32 %0, %1;" : "=r"(r) : "f"(f));
    return __uint_as_float(r);
}
__device__ __forceinline__ void mma_tf32(float& d0, float& d1, float& d2, float& d3,
    unsigned a0, unsigned a1, unsigned a2, unsigned a3, unsigned b0, unsigned b1) {
    asm volatile("mma.sync.aligned.m16n8k8.row.col.f32.tf32.tf32.f32 "
        "{%0,%1,%2,%3}, {%4,%5,%6,%7}, {%8,%9}, {%0,%1,%2,%3};"
        : "+f"(d0), "+f"(d1), "+f"(d2), "+f"(d3)
        : "r"(a0), "r"(a1), "r"(a2), "r"(a3), "r"(b0), "r"(b1));
}

// ============================================================================
// k0: one-time weight repack/transpose.
// ============================================================================
__global__ void __launch_bounds__(256) k0_prep(
    const float* __restrict__ o_w,
    const float* __restrict__ q_a_w, const float* __restrict__ kv_a_w,
    const float* __restrict__ q_b_w, const float* __restrict__ k_w,
    const float* __restrict__ v_w)
{
    int i = blockIdx.x * 256 + threadIdx.x;
    if (i < 32768) {
        int d = i >> 7, c2 = i & 127;
        g_owT2[(size_t)c2*256 + d] = pack2(o_w[(size_t)d*256 + 2*c2],
                                           o_w[(size_t)d*256 + 2*c2 + 1]);
    } else if (i < 38912) {
        int j = i - 32768;
        int c4 = j / 96, r = j % 96;
        const float* src = (r < QR) ? (q_a_w + (size_t)r*CC)
                                    : (kv_a_w + (size_t)(r-QR)*CC);
        ulonglong2 v;
        v.x = pack2(src[4*c4],     src[4*c4 + 1]);
        v.y = pack2(src[4*c4 + 2], src[4*c4 + 3]);
        g_wAT4[(size_t)c4*96 + r] = v;
    } else if (i < 47104) {
        int j = i - 38912;
        int r = j >> 8, c = j & 255;
        g_wqT[j] = q_b_w[(size_t)c*QR + r];
    } else if (i < 63488) {
        int j = i - 47104;
        int r = j >> 8, c = j & 255;
        g_wkT[j] = k_w[(size_t)c*KVR + r];
    } else if (i < 79872) {
        int j = i - 63488;
        int r = j >> 8, c = j & 255;
        g_wvT[j] = v_w[(size_t)c*KVR + r];
    }
}

// ============================================================================
// k1: LayerNorm + low-rank down projections (coalesced transposed weights).
// ============================================================================
__global__ void __launch_bounds__(256) k1_ln_down(
    const float* __restrict__ x, const float* __restrict__ norm_w,
    const float* __restrict__ q_bias, const float* __restrict__ kv_bias)
{
    __shared__ __align__(16) float xs[TOKTILE][CC];
    const int tok0 = blockIdx.x * TOKTILE;
    const int tid = threadIdx.x;

    const float4* xsrc = (const float4*)(x + (size_t)tok0 * CC);
    float4* xd = (float4*)xs;
#pragma unroll
    for (int i = 0; i < 4; i++) xd[tid + i*256] = xsrc[tid + i*256];
    __syncthreads();

    const int w = tid >> 5, l = tid & 31;
    for (int t = w; t < TOKTILE; t += 8) {
        float s = 0.f, sq = 0.f;
#pragma unroll
        for (int i = 0; i < 8; i++) { float v = xs[t][l + 32*i]; s += v; sq += v*v; }
#pragma unroll
        for (int o = 16; o; o >>= 1) {
            s  += __shfl_xor_sync(0xffffffffu, s,  o);
            sq += __shfl_xor_sync(0xffffffffu, sq, o);
        }
        float mean = s * (1.f/CC);
        float var  = sq * (1.f/CC) - mean*mean;
        float rstd = 1.f / sqrtf(var + 1e-5f);
#pragma unroll
        for (int i = 0; i < 8; i++) {
            int c = l + 32*i;
            xs[t][c] = (xs[t][c] - mean) * rstd * norm_w[c];
        }
    }
    __syncthreads();

    if (tid < 192) {
        const int r = tid % 96, th = tid / 96;
        const int t0 = th * 8;
        u64 acc[8];
#pragma unroll
        for (int tt = 0; tt < 8; tt++) acc[tt] = 0ull;

#pragma unroll 8
        for (int c4 = 0; c4 < 64; c4++) {
            ulonglong2 w4 = g_wAT4[(size_t)c4*96 + r];
#pragma unroll
            for (int tt = 0; tt < 8; tt++) {
                ulonglong2 xv = *(const ulonglong2*)&xs[t0 + tt][4*c4];
                acc[tt] = fma2(xv.x, w4.x, acc[tt]);
                acc[tt] = fma2(xv.y, w4.y, acc[tt]);
            }
        }
        const float bias = (r < QR) ? q_bias[r] : kv_bias[r - QR];
#pragma unroll
        for (int tt = 0; tt < 8; tt++) {
            float2 a = unpack2(acc[tt]);
            g_lat[(size_t)(tok0 + t0 + tt)*96 + r] = a.x + a.y + bias;
        }
    }
}

// ============================================================================
// k2: up projections (coalesced transposed weights, f32x2 accumulators).
// ============================================================================
__global__ void __launch_bounds__(256) k2_up()
{
    __shared__ __align__(16) float ls[96][TOKTILE];
    const int tok0 = blockIdx.x * TOKTILE;
    const int tid = threadIdx.x;
    const float SC = 0.17677669529663687f * 1.4426950408889634f;

    for (int i = tid; i < TOKTILE*96; i += 256) {
        int t = i / 96, r = i % 96;
        ls[r][t] = g_lat[(size_t)(tok0 + t)*96 + r];
    }
    __syncthreads();

    const int c = tid, h = c >> 5, d = c & 31;
    u64 aq[8], ak[8], av[8];
#pragma unroll
    for (int p = 0; p < 8; p++) { aq[p] = 0ull; ak[p] = 0ull; av[p] = 0ull; }

#pragma unroll 4
    for (int r = 0; r < QR; r++) {
        float wv = g_wqT[(size_t)r*256 + c];
        u64 w2 = pack2(wv, wv);
        const ulonglong2* lp = (const ulonglong2*)ls[r];
#pragma unroll
        for (int p = 0; p < 4; p++) {
            ulonglong2 lv = lp[p];
            aq[2*p]   = fma2(lv.x, w2, aq[2*p]);
            aq[2*p+1] = fma2(lv.y, w2, aq[2*p+1]);
        }
    }
#pragma unroll 4
    for (int r = 0; r < KVR; r++) {
        float wk_ = g_wkT[(size_t)r*256 + c];
        float wv_ = g_wvT[(size_t)r*256 + c];
        u64 wk2 = pack2(wk_, wk_), wv2 = pack2(wv_, wv_);
        const ulonglong2* lp = (const ulonglong2*)ls[QR + r];
#pragma unroll
        for (int p = 0; p < 4; p++) {
            ulonglong2 lv = lp[p];
            ak[2*p]   = fma2(lv.x, wk2, ak[2*p]);
            ak[2*p+1] = fma2(lv.y, wk2, ak[2*p+1]);
            av[2*p]   = fma2(lv.x, wv2, av[2*p]);
            av[2*p+1] = fma2(lv.y, wv2, av[2*p+1]);
        }
    }

    const int b = tok0 / TT, t0 = tok0 % TT;
    const size_t base = ((size_t)(b*HH + h)*TT + t0)*DH + d;
#pragma unroll
    for (int p = 0; p < 8; p++) {
        float2 q2v = unpack2(aq[p]);
        float2 k2v = unpack2(ak[p]);
        float2 v2v = unpack2(av[p]);
        g_q[base + (size_t)(2*p)*DH]   = cvt_tf32f(q2v.x * SC);
        g_q[base + (size_t)(2*p+1)*DH] = cvt_tf32f(q2v.y * SC);
        g_k[base + (size_t)(2*p)*DH]   = cvt_tf32f(k2v.x);
        g_k[base + (size_t)(2*p+1)*DH] = cvt_tf32f(k2v.y);
        g_v[base + (size_t)(2*p)*DH]   = cvt_tf32f(v2v.x);
        g_v[base + (size_t)(2*p+1)*DH] = cvt_tf32f(v2v.y);
    }
}

// ============================================================================
// k3: flash attention, tensor cores, 32 q-rows per warp (two m16 halves
// sharing every B-fragment). 128 q-rows per CTA; 64-key tiles.
// Ks stride 36 (K-frag conflict-free), Vs stride 40 (V-frag conflict-free).
// Dynamic smem: 64*36 + 64*40 + 4*32*68 floats = 54272 B.
// ============================================================================
#define KS_STR 36
#define VS_STR 40
#define PSTR 68
#define K3_SMEM ((64*KS_STR + 64*VS_STR + 4*32*PSTR) * 4)

__global__ void __launch_bounds__(128) k3_attn_mma()
{
    extern __shared__ __align__(16) float smem_dyn[];
    float* Ks = smem_dyn;                        // 64*36
    float* Vs = Ks + 64*KS_STR;                  // 64*40
    unsigned* Ps = (unsigned*)(Vs + 64*VS_STR);  // 4 warps * 32 rows * 68

    const int tid = threadIdx.x;
    const int w = tid >> 5, lane = tid & 31;
    const int gid = lane >> 2, tig = lane & 3;
    const int bh = blockIdx.y;
    const int qbase = blockIdx.x * 128 + w * 32;

    // Q fragments for both halves (rows qbase+16*mh + {gid, gid+8})
    const float* qptr = g_q + (size_t)bh*TT*DH;
    unsigned qA[2][4][4];
#pragma unroll
    for (int mh = 0; mh < 2; mh++) {
        const int rA = qbase + 16*mh + gid, rB = rA + 8;
#pragma unroll
        for (int kc = 0; kc < 4; kc++) {
            qA[mh][kc][0] = __float_as_uint(qptr[(size_t)rA*DH + 8*kc + tig]);
            qA[mh][kc][1] = __float_as_uint(qptr[(size_t)rB*DH + 8*kc + tig]);
            qA[mh][kc][2] = __float_as_uint(qptr[(size_t)rA*DH + 8*kc + tig + 4]);
            qA[mh][kc][3] = __float_as_uint(qptr[(size_t)rB*DH + 8*kc + tig + 4]);
        }
    }

    float y[2][4][4];
#pragma unroll
    for (int mh = 0; mh < 2; mh++)
#pragma unroll
        for (int i = 0; i < 4; i++)
#pragma unroll
            for (int j = 0; j < 4; j++) y[mh][i][j] = 0.f;
    float mA[2] = {-3.0e38f, -3.0e38f}, mB[2] = {-3.0e38f, -3.0e38f};
    float lA[2] = {0.f, 0.f},           lB[2] = {0.f, 0.f};

    const float4* kg = (const float4*)(g_k + (size_t)bh*TT*DH);
    const float4* vg = (const float4*)(g_v + (size_t)bh*TT*DH);
    unsigned* myPs = Ps + w*32*PSTR;

    for (int kt = 0; kt < TT; kt += 64) {
        __syncthreads();
#pragma unroll
        for (int i = 0; i < 4; i++) {
            int idx = tid + 128*i;
            int row = idx >> 3, c4 = idx & 7;
            ((float4*)(Ks + row*KS_STR))[c4] = kg[((size_t)(kt + row))*8 + c4];
            ((float4*)(Vs + row*VS_STR))[c4] = vg[((size_t)(kt + row))*8 + c4];
        }
        __syncthreads();

        // S = Q K^T for both halves, sharing each K B-fragment
        float s[2][8][4];
#pragma unroll
        for (int nc = 0; nc < 8; nc++) {
            s[0][nc][0] = s[0][nc][1] = s[0][nc][2] = s[0][nc][3] = 0.f;
            s[1][nc][0] = s[1][nc][1] = s[1][nc][2] = s[1][nc][3] = 0.f;
#pragma unroll
            for (int kc = 0; kc < 4; kc++) {
                const float* kb = Ks + (8*nc + gid)*KS_STR + 8*kc + tig;
                unsigned b0 = __float_as_uint(kb[0]);
                unsigned b1 = __float_as_uint(kb[4]);
                mma_tf32(s[0][nc][0], s[0][nc][1], s[0][nc][2], s[0][nc][3],
                         qA[0][kc][0], qA[0][kc][1], qA[0][kc][2], qA[0][kc][3], b0, b1);
                mma_tf32(s[1][nc][0], s[1][nc][1], s[1][nc][2], s[1][nc][3],
                         qA[1][kc][0], qA[1][kc][1], qA[1][kc][2], qA[1][kc][3], b0, b1);
            }
        }

        // online softmax + P store, per half
#pragma unroll
        for (int mh = 0; mh < 2; mh++) {
            float mx0 = s[mh][0][0], mx1 = s[mh][0][2];
#pragma unroll
            for (int nc = 0; nc < 8; nc++) {
                mx0 = fmaxf(mx0, fmaxf(s[mh][nc][0], s[mh][nc][1]));
                mx1 = fmaxf(mx1, fmaxf(s[mh][nc][2], s[mh][nc][3]));
            }
            mx0 = fmaxf(mx0, __shfl_xor_sync(0xffffffffu, mx0, 1));
            mx0 = fmaxf(mx0, __shfl_xor_sync(0xffffffffu, mx0, 2));
            mx1 = fmaxf(mx1, __shfl_xor_sync(0xffffffffu, mx1, 1));
            mx1 = fmaxf(mx1, __shfl_xor_sync(0xffffffffu, mx1, 2));
            float mn0 = fmaxf(mA[mh], mx0), mn1 = fmaxf(mB[mh], mx1);
            float c0 = exp2f(mA[mh] - mn0), c1 = exp2f(mB[mh] - mn1);
            mA[mh] = mn0; mB[mh] = mn1;
            lA[mh] *= c0; lB[mh] *= c1;
#pragma unroll
            for (int nc2 = 0; nc2 < 4; nc2++) {
                y[mh][nc2][0] *= c0; y[mh][nc2][1] *= c0;
                y[mh][nc2][2] *= c1; y[mh][nc2][3] *= c1;
            }
            float ps0 = 0.f, ps1 = 0.f;
#pragma unroll
            for (int nc = 0; nc < 8; nc++) {
                s[mh][nc][0] = exp2f(s[mh][nc][0] - mn0);
                s[mh][nc][1] = exp2f(s[mh][nc][1] - mn0);
                s[mh][nc][2] = exp2f(s[mh][nc][2] - mn1);
                s[mh][nc][3] = exp2f(s[mh][nc][3] - mn1);
                ps0 += s[mh][nc][0] + s[mh][nc][1];
                ps1 += s[mh][nc][2] + s[mh][nc][3];
            }
            ps0 += __shfl_xor_sync(0xffffffffu, ps0, 1);
            ps0 += __shfl_xor_sync(0xffffffffu, ps0, 2);
            ps1 += __shfl_xor_sync(0xffffffffu, ps1, 1);
            ps1 += __shfl_xor_sync(0xffffffffu, ps1, 2);
            lA[mh] += ps0; lB[mh] += ps1;

#pragma unroll
            for (int nc = 0; nc < 8; nc++) {
                uint2 v0; v0.x = __float_as_uint(s[mh][nc][0]); v0.y = __float_as_uint(s[mh][nc][1]);
                uint2 v1; v1.x = __float_as_uint(s[mh][nc][2]); v1.y = __float_as_uint(s[mh][nc][3]);
                *(uint2*)&myPs[(gid + 16*mh)*PSTR     + 8*nc + 2*tig] = v0;
                *(uint2*)&myPs[(gid + 8 + 16*mh)*PSTR + 8*nc + 2*tig] = v1;
            }
        }
        __syncwarp();

        // Y += P V, sharing each V B-fragment across halves
#pragma unroll
        for (int kc = 0; kc < 8; kc++) {
            unsigned a[2][4];
#pragma unroll
            for (int mh = 0; mh < 2; mh++) {
                a[mh][0] = myPs[(gid + 16*mh)*PSTR     + 8*kc + tig];
                a[mh][1] = myPs[(gid + 8 + 16*mh)*PSTR + 8*kc + tig];
                a[mh][2] = myPs[(gid + 16*mh)*PSTR     + 8*kc + tig + 4];
                a[mh][3] = myPs[(gid + 8 + 16*mh)*PSTR + 8*kc + tig + 4];
            }
#pragma unroll
            for (int nc2 = 0; nc2 < 4; nc2++) {
                unsigned b0 = __float_as_uint(Vs[(8*kc + tig)*VS_STR     + 8*nc2 + gid]);
                unsigned b1 = __float_as_uint(Vs[(8*kc + tig + 4)*VS_STR + 8*nc2 + gid]);
                mma_tf32(y[0][nc2][0], y[0][nc2][1], y[0][nc2][2], y[0][nc2][3],
                         a[0][0], a[0][1], a[0][2], a[0][3], b0, b1);
                mma_tf32(y[1][nc2][0], y[1][nc2][1], y[1][nc2][2], y[1][nc2][3],
                         a[1][0], a[1][1], a[1][2], a[1][3], b0, b1);
            }
        }
        __syncwarp();
    }

    const int b = bh >> 3, h = bh & 7;
#pragma unroll
    for (int mh = 0; mh < 2; mh++) {
        const int rA = qbase + 16*mh + gid, rB = rA + 8;
        const float inv0 = 1.0f / lA[mh], inv1 = 1.0f / lB[mh];
#pragma unroll
        for (int nc2 = 0; nc2 < 4; nc2++) {
            int col = h*DH + nc2*8 + 2*tig;
            float2 o0; o0.x = y[mh][nc2][0]*inv0; o0.y = y[mh][nc2][1]*inv0;
            float2 o1; o1.x = y[mh][nc2][2]*inv1; o1.y = y[mh][nc2][3]*inv1;
            *(float2*)&g_y[(size_t)(b*TT + rA)*CC + col] = o0;
            *(float2*)&g_y[(size_t)(b*TT + rB)*CC + col] = o1;
        }
    }
}

// ============================================================================
// k4: output projection + gamma + residual. Barrier-free main loop.
// ============================================================================
__global__ void __launch_bounds__(256) k4_oproj(
    const float* __restrict__ x, const float* __restrict__ gamma,
    float* __restrict__ out)
{
    __shared__ __align__(16) float ys[TOKTILE][CC];
    const int tok0 = blockIdx.x * TOKTILE;
    const int tid = threadIdx.x;

    const float4* ysrc = (const float4*)(g_y + (size_t)tok0 * CC);
    float4* yd = (float4*)ys;
#pragma unroll
    for (int i = 0; i < 4; i++) yd[tid + i*256] = ysrc[tid + i*256];
    __syncthreads();

    u64 acc[16];
#pragma unroll
    for (int t = 0; t < 16; t++) acc[t] = 0ull;

    const u64* wT = g_owT2;
#pragma unroll 4
    for (int c2 = 0; c2 < 128; c2++) {
        u64 w2 = wT[(size_t)c2*256 + tid];
        const float* yb = &ys[0][2*c2];
#pragma unroll
        for (int t = 0; t < 16; t++) {
            u64 yv = *(const u64*)(yb + t*CC);
            acc[t] = fma2(yv, w2, acc[t]);
        }
    }

    const float g = gamma[tid];
#pragma unroll
    for (int t = 0; t < 16; t++) {
        float2 a = unpack2(acc[t]);
        size_t o = (size_t)(tok0 + t)*CC + tid;
        out[o] = x[o] + g * (a.x + a.y);
    }
}

// ============================================================================
extern "C" void kernel_launch(void* const* d_in, const int* in_sizes, int n_in,
                              void* d_out, int out_size)
{
    const float* x       = (const float*)d_in[0];
    const float* q_a_w   = (const float*)d_in[1];
    const float* q_bias  = (const float*)d_in[2];
    const float* q_b_w   = (const float*)d_in[3];
    const float* kv_a_w  = (const float*)d_in[4];
    const float* kv_bias = (const float*)d_in[5];
    const float* k_w     = (const float*)d_in[6];
    const float* v_w     = (const float*)d_in[7];
    const float* o_w     = (const float*)d_in[8];
    const float* norm_w  = (const float*)d_in[9];
    const float* gamma   = (const float*)d_in[10];
    float* out = (float*)d_out;

    cudaFuncSetAttribute(k3_attn_mma,
                         cudaFuncAttributeMaxDynamicSharedMemorySize, K3_SMEM);

    k0_prep<<<312, 256>>>(o_w, q_a_w, kv_a_w, q_b_w, k_w, v_w);
    k1_ln_down<<<NBLK, 256>>>(x, norm_w, q_bias, kv_bias);
    k2_up<<<NBLK, 256>>>();
    dim3 g3(TT/128, BB*HH);
    k3_attn_mma<<<g3, 128, K3_SMEM>>>();
    k4_oproj<<<NBLK, 256>>>(x, gamma, out);
}

// round 8
// speedup vs baseline: 3.8931x; 1.0094x over previous
#include <cuda_runtime.h>
#include <cstdint>

#define BB 4
#define TT 2048
#define CC 256
#define HH 8
#define DH 32
#define QR 32
#define KVR 64
#define NTOK (BB*TT)          // 8192
#define TOKTILE 16
#define NBLK (NTOK/TOKTILE)   // 512

// ---------------- scratch (device globals; no allocation allowed) ----------------
__device__ float g_lat[(size_t)NTOK*96];                 // [tok][96]
__device__ float g_q[(size_t)BB*HH*TT*DH];               // [B,H,T,Dh]  (tf32 bits, pre-scaled)
__device__ float g_k[(size_t)BB*HH*TT*DH];               // tf32 bits, dim-columns pair-permuted
__device__ float g_v[(size_t)BB*HH*TT*DH];               // tf32 bits
__device__ float g_y[(size_t)NTOK*CC];                   // [B,T,C]
__device__ unsigned long long g_owT2[(size_t)128*256];   // packed o_w^T pairs [c2][d]
__device__ ulonglong2 g_wAT4[(size_t)64*96];             // down-proj W^T packed [c4][r]
__device__ float g_wqT[(size_t)QR*256];                  // q_b_w^T [r][c]
__device__ float g_wkT[(size_t)KVR*256];                 // k_w^T  [r][c]
__device__ float g_wvT[(size_t)KVR*256];                 // v_w^T  [r][c]

typedef unsigned long long u64;

// ---------------- packed f32x2 helpers ----------------
__device__ __forceinline__ u64 pack2(float lo, float hi) {
    u64 r; asm("mov.b64 %0, {%1, %2};" : "=l"(r) : "f"(lo), "f"(hi)); return r;
}
__device__ __forceinline__ float2 unpack2(u64 v) {
    float2 r; asm("mov.b64 {%0, %1}, %2;" : "=f"(r.x), "=f"(r.y) : "l"(v)); return r;
}
__device__ __forceinline__ u64 fma2(u64 a, u64 b, u64 c) {
    u64 d; asm("fma.rn.f32x2 %0, %1, %2, %3;" : "=l"(d) : "l"(a), "l"(b), "l"(c)); return d;
}

// ---------------- tf32 helpers ----------------
__device__ __forceinline__ float cvt_tf32f(float f) {
    unsigned r; asm("cvt.rna.tf32.f32 %0, %1;" : "=r"(r) : "f"(f));
    return __uint_as_float(r);
}
__device__ __forceinline__ void mma_tf32(float& d0, float& d1, float& d2, float& d3,
    unsigned a0, unsigned a1, unsigned a2, unsigned a3, unsigned b0, unsigned b1) {
    asm volatile("mma.sync.aligned.m16n8k8.row.col.f32.tf32.tf32.f32 "
        "{%0,%1,%2,%3}, {%4,%5,%6,%7}, {%8,%9}, {%0,%1,%2,%3};"
        : "+f"(d0), "+f"(d1), "+f"(d2), "+f"(d3)
        : "r"(a0), "r"(a1), "r"(a2), "r"(a3), "r"(b0), "r"(b1));
}

// ============================================================================
// k0: one-time weight repack/transpose.
// ============================================================================
__global__ void __launch_bounds__(256) k0_prep(
    const float* __restrict__ o_w,
    const float* __restrict__ q_a_w, const float* __restrict__ kv_a_w,
    const float* __restrict__ q_b_w, const float* __restrict__ k_w,
    const float* __restrict__ v_w)
{
    int i = blockIdx.x * 256 + threadIdx.x;
    if (i < 32768) {
        int d = i >> 7, c2 = i & 127;
        g_owT2[(size_t)c2*256 + d] = pack2(o_w[(size_t)d*256 + 2*c2],
                                           o_w[(size_t)d*256 + 2*c2 + 1]);
    } else if (i < 38912) {
        int j = i - 32768;
        int c4 = j / 96, r = j % 96;
        const float* src = (r < QR) ? (q_a_w + (size_t)r*CC)
                                    : (kv_a_w + (size_t)(r-QR)*CC);
        ulonglong2 v;
        v.x = pack2(src[4*c4],     src[4*c4 + 1]);
        v.y = pack2(src[4*c4 + 2], src[4*c4 + 3]);
        g_wAT4[(size_t)c4*96 + r] = v;
    } else if (i < 47104) {
        int j = i - 38912;
        int r = j >> 8, c = j & 255;
        g_wqT[j] = q_b_w[(size_t)c*QR + r];
    } else if (i < 63488) {
        int j = i - 47104;
        int r = j >> 8, c = j & 255;
        g_wkT[j] = k_w[(size_t)c*KVR + r];
    } else if (i < 79872) {
        int j = i - 63488;
        int r = j >> 8, c = j & 255;
        g_wvT[j] = v_w[(size_t)c*KVR + r];
    }
}

// ============================================================================
// k1: LayerNorm + low-rank down projections (coalesced transposed weights).
// ============================================================================
__global__ void __launch_bounds__(256) k1_ln_down(
    const float* __restrict__ x, const float* __restrict__ norm_w,
    const float* __restrict__ q_bias, const float* __restrict__ kv_bias)
{
    __shared__ __align__(16) float xs[TOKTILE][CC];
    const int tok0 = blockIdx.x * TOKTILE;
    const int tid = threadIdx.x;

    const float4* xsrc = (const float4*)(x + (size_t)tok0 * CC);
    float4* xd = (float4*)xs;
#pragma unroll
    for (int i = 0; i < 4; i++) xd[tid + i*256] = xsrc[tid + i*256];
    __syncthreads();

    const int w = tid >> 5, l = tid & 31;
    for (int t = w; t < TOKTILE; t += 8) {
        float s = 0.f, sq = 0.f;
#pragma unroll
        for (int i = 0; i < 8; i++) { float v = xs[t][l + 32*i]; s += v; sq += v*v; }
#pragma unroll
        for (int o = 16; o; o >>= 1) {
            s  += __shfl_xor_sync(0xffffffffu, s,  o);
            sq += __shfl_xor_sync(0xffffffffu, sq, o);
        }
        float mean = s * (1.f/CC);
        float var  = sq * (1.f/CC) - mean*mean;
        float rstd = 1.f / sqrtf(var + 1e-5f);
#pragma unroll
        for (int i = 0; i < 8; i++) {
            int c = l + 32*i;
            xs[t][c] = (xs[t][c] - mean) * rstd * norm_w[c];
        }
    }
    __syncthreads();

    if (tid < 192) {
        const int r = tid % 96, th = tid / 96;
        const int t0 = th * 8;
        u64 acc[8];
#pragma unroll
        for (int tt = 0; tt < 8; tt++) acc[tt] = 0ull;

#pragma unroll 8
        for (int c4 = 0; c4 < 64; c4++) {
            ulonglong2 w4 = g_wAT4[(size_t)c4*96 + r];
#pragma unroll
            for (int tt = 0; tt < 8; tt++) {
                ulonglong2 xv = *(const ulonglong2*)&xs[t0 + tt][4*c4];
                acc[tt] = fma2(xv.x, w4.x, acc[tt]);
                acc[tt] = fma2(xv.y, w4.y, acc[tt]);
            }
        }
        const float bias = (r < QR) ? q_bias[r] : kv_bias[r - QR];
#pragma unroll
        for (int tt = 0; tt < 8; tt++) {
            float2 a = unpack2(acc[tt]);
            g_lat[(size_t)(tok0 + t0 + tt)*96 + r] = a.x + a.y + bias;
        }
    }
}

// ============================================================================
// k2: up projections. g_k written with dim-columns pair-permuted so that
// k3's K B-fragments (cols tig, tig+4) are smem-contiguous (LDS.64).
// ============================================================================
__global__ void __launch_bounds__(256) k2_up()
{
    __shared__ __align__(16) float ls[96][TOKTILE];
    const int tok0 = blockIdx.x * TOKTILE;
    const int tid = threadIdx.x;
    const float SC = 0.17677669529663687f * 1.4426950408889634f;

    for (int i = tid; i < TOKTILE*96; i += 256) {
        int t = i / 96, r = i % 96;
        ls[r][t] = g_lat[(size_t)(tok0 + t)*96 + r];
    }
    __syncthreads();

    const int c = tid, h = c >> 5, d = c & 31;
    const int dp = 8*(d >> 3) + 2*(d & 3) + ((d >> 2) & 1);   // permuted position
    u64 aq[8], ak[8], av[8];
#pragma unroll
    for (int p = 0; p < 8; p++) { aq[p] = 0ull; ak[p] = 0ull; av[p] = 0ull; }

#pragma unroll 4
    for (int r = 0; r < QR; r++) {
        float wv = g_wqT[(size_t)r*256 + c];
        u64 w2 = pack2(wv, wv);
        const ulonglong2* lp = (const ulonglong2*)ls[r];
#pragma unroll
        for (int p = 0; p < 4; p++) {
            ulonglong2 lv = lp[p];
            aq[2*p]   = fma2(lv.x, w2, aq[2*p]);
            aq[2*p+1] = fma2(lv.y, w2, aq[2*p+1]);
        }
    }
#pragma unroll 4
    for (int r = 0; r < KVR; r++) {
        float wk_ = g_wkT[(size_t)r*256 + c];
        float wv_ = g_wvT[(size_t)r*256 + c];
        u64 wk2 = pack2(wk_, wk_), wv2 = pack2(wv_, wv_);
        const ulonglong2* lp = (const ulonglong2*)ls[QR + r];
#pragma unroll
        for (int p = 0; p < 4; p++) {
            ulonglong2 lv = lp[p];
            ak[2*p]   = fma2(lv.x, wk2, ak[2*p]);
            ak[2*p+1] = fma2(lv.y, wk2, ak[2*p+1]);
            av[2*p]   = fma2(lv.x, wv2, av[2*p]);
            av[2*p+1] = fma2(lv.y, wv2, av[2*p+1]);
        }
    }

    const int b = tok0 / TT, t0 = tok0 % TT;
    const size_t baseq = ((size_t)(b*HH + h)*TT + t0)*DH + d;
    const size_t basek = ((size_t)(b*HH + h)*TT + t0)*DH + dp;
#pragma unroll
    for (int p = 0; p < 8; p++) {
        float2 q2v = unpack2(aq[p]);
        float2 k2v = unpack2(ak[p]);
        float2 v2v = unpack2(av[p]);
        g_q[baseq + (size_t)(2*p)*DH]   = cvt_tf32f(q2v.x * SC);
        g_q[baseq + (size_t)(2*p+1)*DH] = cvt_tf32f(q2v.y * SC);
        g_k[basek + (size_t)(2*p)*DH]   = cvt_tf32f(k2v.x);
        g_k[basek + (size_t)(2*p+1)*DH] = cvt_tf32f(k2v.y);
        g_v[baseq + (size_t)(2*p)*DH]   = cvt_tf32f(v2v.x);
        g_v[baseq + (size_t)(2*p+1)*DH] = cvt_tf32f(v2v.y);
    }
}

// ============================================================================
// k3: flash attention, tensor cores, 32 q-rows per warp, 32-key tiles.
// K-frags via LDS.64 (pair-permuted g_k, stride 40). 3 CTAs/SM target.
// ============================================================================
#define KS_STR 40
#define VS_STR 40
#define PSTR 36
__global__ void __launch_bounds__(128, 3) k3_attn_mma()
{
    __shared__ __align__(16) float Ks[32*KS_STR];
    __shared__ __align__(16) float Vs[32*VS_STR];
    __shared__ __align__(16) unsigned Ps[4*32*PSTR];

    const int tid = threadIdx.x;
    const int w = tid >> 5, lane = tid & 31;
    const int gid = lane >> 2, tig = lane & 3;
    const int bh = blockIdx.y;
    const int qbase = blockIdx.x * 128 + w * 32;

    const float* qptr = g_q + (size_t)bh*TT*DH;
    unsigned qA[2][4][4];
#pragma unroll
    for (int mh = 0; mh < 2; mh++) {
        const int rA = qbase + 16*mh + gid, rB = rA + 8;
#pragma unroll
        for (int kc = 0; kc < 4; kc++) {
            qA[mh][kc][0] = __float_as_uint(qptr[(size_t)rA*DH + 8*kc + tig]);
            qA[mh][kc][1] = __float_as_uint(qptr[(size_t)rB*DH + 8*kc + tig]);
            qA[mh][kc][2] = __float_as_uint(qptr[(size_t)rA*DH + 8*kc + tig + 4]);
            qA[mh][kc][3] = __float_as_uint(qptr[(size_t)rB*DH + 8*kc + tig + 4]);
        }
    }

    float y[2][4][4];
#pragma unroll
    for (int mh = 0; mh < 2; mh++)
#pragma unroll
        for (int i = 0; i < 4; i++)
#pragma unroll
            for (int j = 0; j < 4; j++) y[mh][i][j] = 0.f;
    float mA[2] = {-3.0e38f, -3.0e38f}, mB[2] = {-3.0e38f, -3.0e38f};
    float lA[2] = {0.f, 0.f},           lB[2] = {0.f, 0.f};

    const float4* kg = (const float4*)(g_k + (size_t)bh*TT*DH);
    const float4* vg = (const float4*)(g_v + (size_t)bh*TT*DH);
    unsigned* myPs = Ps + w*32*PSTR;

    for (int kt = 0; kt < TT; kt += 32) {
        __syncthreads();
#pragma unroll
        for (int i = 0; i < 2; i++) {
            int idx = tid + 128*i;
            int row = idx >> 3, c4 = idx & 7;
            ((float4*)(Ks + row*KS_STR))[c4] = kg[((size_t)(kt + row))*8 + c4];
            ((float4*)(Vs + row*VS_STR))[c4] = vg[((size_t)(kt + row))*8 + c4];
        }
        __syncthreads();

        // S = Q K^T for both halves, sharing each K B-fragment (LDS.64)
        float s[2][4][4];
#pragma unroll
        for (int nc = 0; nc < 4; nc++) {
            s[0][nc][0] = s[0][nc][1] = s[0][nc][2] = s[0][nc][3] = 0.f;
            s[1][nc][0] = s[1][nc][1] = s[1][nc][2] = s[1][nc][3] = 0.f;
#pragma unroll
            for (int kc = 0; kc < 4; kc++) {
                uint2 kk = *(const uint2*)(Ks + (8*nc + gid)*KS_STR + 8*kc + 2*tig);
                mma_tf32(s[0][nc][0], s[0][nc][1], s[0][nc][2], s[0][nc][3],
                         qA[0][kc][0], qA[0][kc][1], qA[0][kc][2], qA[0][kc][3], kk.x, kk.y);
                mma_tf32(s[1][nc][0], s[1][nc][1], s[1][nc][2], s[1][nc][3],
                         qA[1][kc][0], qA[1][kc][1], qA[1][kc][2], qA[1][kc][3], kk.x, kk.y);
            }
        }

        // online softmax + P store, per half
#pragma unroll
        for (int mh = 0; mh < 2; mh++) {
            float mx0 = s[mh][0][0], mx1 = s[mh][0][2];
#pragma unroll
            for (int nc = 0; nc < 4; nc++) {
                mx0 = fmaxf(mx0, fmaxf(s[mh][nc][0], s[mh][nc][1]));
                mx1 = fmaxf(mx1, fmaxf(s[mh][nc][2], s[mh][nc][3]));
            }
            mx0 = fmaxf(mx0, __shfl_xor_sync(0xffffffffu, mx0, 1));
            mx0 = fmaxf(mx0, __shfl_xor_sync(0xffffffffu, mx0, 2));
            mx1 = fmaxf(mx1, __shfl_xor_sync(0xffffffffu, mx1, 1));
            mx1 = fmaxf(mx1, __shfl_xor_sync(0xffffffffu, mx1, 2));
            float mn0 = fmaxf(mA[mh], mx0), mn1 = fmaxf(mB[mh], mx1);
            float c0 = exp2f(mA[mh] - mn0), c1 = exp2f(mB[mh] - mn1);
            mA[mh] = mn0; mB[mh] = mn1;
            lA[mh] *= c0; lB[mh] *= c1;
#pragma unroll
            for (int nc2 = 0; nc2 < 4; nc2++) {
                y[mh][nc2][0] *= c0; y[mh][nc2][1] *= c0;
                y[mh][nc2][2] *= c1; y[mh][nc2][3] *= c1;
            }
            float ps0 = 0.f, ps1 = 0.f;
#pragma unroll
            for (int nc = 0; nc < 4; nc++) {
                s[mh][nc][0] = exp2f(s[mh][nc][0] - mn0);
                s[mh][nc][1] = exp2f(s[mh][nc][1] - mn0);
                s[mh][nc][2] = exp2f(s[mh][nc][2] - mn1);
                s[mh][nc][3] = exp2f(s[mh][nc][3] - mn1);
                ps0 += s[mh][nc][0] + s[mh][nc][1];
                ps1 += s[mh][nc][2] + s[mh][nc][3];
            }
            ps0 += __shfl_xor_sync(0xffffffffu, ps0, 1);
            ps0 += __shfl_xor_sync(0xffffffffu, ps0, 2);
            ps1 += __shfl_xor_sync(0xffffffffu, ps1, 1);
            ps1 += __shfl_xor_sync(0xffffffffu, ps1, 2);
            lA[mh] += ps0; lB[mh] += ps1;

#pragma unroll
            for (int nc = 0; nc < 4; nc++) {
                uint2 v0; v0.x = __float_as_uint(s[mh][nc][0]); v0.y = __float_as_uint(s[mh][nc][1]);
                uint2 v1; v1.x = __float_as_uint(s[mh][nc][2]); v1.y = __float_as_uint(s[mh][nc][3]);
                *(uint2*)&myPs[(gid + 16*mh)*PSTR     + 8*nc + 2*tig] = v0;
                *(uint2*)&myPs[(gid + 8 + 16*mh)*PSTR + 8*nc + 2*tig] = v1;
            }
        }
        __syncwarp();

        // Y += P V, sharing each V B-fragment across halves
#pragma unroll
        for (int kc = 0; kc < 4; kc++) {
            unsigned a[2][4];
#pragma unroll
            for (int mh = 0; mh < 2; mh++) {
                a[mh][0] = myPs[(gid + 16*mh)*PSTR     + 8*kc + tig];
                a[mh][1] = myPs[(gid + 8 + 16*mh)*PSTR + 8*kc + tig];
                a[mh][2] = myPs[(gid + 16*mh)*PSTR     + 8*kc + tig + 4];
                a[mh][3] = myPs[(gid + 8 + 16*mh)*PSTR + 8*kc + tig + 4];
            }
#pragma unroll
            for (int nc2 = 0; nc2 < 4; nc2++) {
                unsigned b0 = __float_as_uint(Vs[(8*kc + tig)*VS_STR     + 8*nc2 + gid]);
                unsigned b1 = __float_as_uint(Vs[(8*kc + tig + 4)*VS_STR + 8*nc2 + gid]);
                mma_tf32(y[0][nc2][0], y[0][nc2][1], y[0][nc2][2], y[0][nc2][3],
                         a[0][0], a[0][1], a[0][2], a[0][3], b0, b1);
                mma_tf32(y[1][nc2][0], y[1][nc2][1], y[1][nc2][2], y[1][nc2][3],
                         a[1][0], a[1][1], a[1][2], a[1][3], b0, b1);
            }
        }
        __syncwarp();
    }

    const int b = bh >> 3, h = bh & 7;
#pragma unroll
    for (int mh = 0; mh < 2; mh++) {
        const int rA = qbase + 16*mh + gid, rB = rA + 8;
        const float inv0 = 1.0f / lA[mh], inv1 = 1.0f / lB[mh];
#pragma unroll
        for (int nc2 = 0; nc2 < 4; nc2++) {
            int col = h*DH + nc2*8 + 2*tig;
            float2 o0; o0.x = y[mh][nc2][0]*inv0; o0.y = y[mh][nc2][1]*inv0;
            float2 o1; o1.x = y[mh][nc2][2]*inv1; o1.y = y[mh][nc2][3]*inv1;
            *(float2*)&g_y[(size_t)(b*TT + rA)*CC + col] = o0;
            *(float2*)&g_y[(size_t)(b*TT + rB)*CC + col] = o1;
        }
    }
}

// ============================================================================
// k4: output projection + gamma + residual. Barrier-free main loop.
// ============================================================================
__global__ void __launch_bounds__(256) k4_oproj(
    const float* __restrict__ x, const float* __restrict__ gamma,
    float* __restrict__ out)
{
    __shared__ __align__(16) float ys[TOKTILE][CC];
    const int tok0 = blockIdx.x * TOKTILE;
    const int tid = threadIdx.x;

    const float4* ysrc = (const float4*)(g_y + (size_t)tok0 * CC);
    float4* yd = (float4*)ys;
#pragma unroll
    for (int i = 0; i < 4; i++) yd[tid + i*256] = ysrc[tid + i*256];
    __syncthreads();

    u64 acc[16];
#pragma unroll
    for (int t = 0; t < 16; t++) acc[t] = 0ull;

    const u64* wT = g_owT2;
#pragma unroll 4
    for (int c2 = 0; c2 < 128; c2++) {
        u64 w2 = wT[(size_t)c2*256 + tid];
        const float* yb = &ys[0][2*c2];
#pragma unroll
        for (int t = 0; t < 16; t++) {
            u64 yv = *(const u64*)(yb + t*CC);
            acc[t] = fma2(yv, w2, acc[t]);
        }
    }

    const float g = gamma[tid];
#pragma unroll
    for (int t = 0; t < 16; t++) {
        float2 a = unpack2(acc[t]);
        size_t o = (size_t)(tok0 + t)*CC + tid;
        out[o] = x[o] + g * (a.x + a.y);
    }
}

// ============================================================================
extern "C" void kernel_launch(void* const* d_in, const int* in_sizes, int n_in,
                              void* d_out, int out_size)
{
    const float* x       = (const float*)d_in[0];
    const float* q_a_w   = (const float*)d_in[1];
    const float* q_bias  = (const float*)d_in[2];
    const float* q_b_w   = (const float*)d_in[3];
    const float* kv_a_w  = (const float*)d_in[4];
    const float* kv_bias = (const float*)d_in[5];
    const float* k_w     = (const float*)d_in[6];
    const float* v_w     = (const float*)d_in[7];
    const float* o_w     = (const float*)d_in[8];
    const float* norm_w  = (const float*)d_in[9];
    const float* gamma   = (const float*)d_in[10];
    float* out = (float*)d_out;

    k0_prep<<<312, 256>>>(o_w, q_a_w, kv_a_w, q_b_w, k_w, v_w);
    k1_ln_down<<<NBLK, 256>>>(x, norm_w, q_bias, kv_bias);
    k2_up<<<NBLK, 256>>>();
    dim3 g3(TT/128, BB*HH);
    k3_attn_mma<<<g3, 128>>>();
    k4_oproj<<<NBLK, 256>>>(x, gamma, out);
}

// round 9
// speedup vs baseline: 4.0126x; 1.0307x over previous
#include <cuda_runtime.h>
#include <cstdint>

#define BB 4
#define TT 2048
#define CC 256
#define HH 8
#define DH 32
#define QR 32
#define KVR 64
#define NTOK (BB*TT)          // 8192
#define TOKTILE 16
#define NBLK (NTOK/TOKTILE)   // 512

// ---------------- scratch (device globals; no allocation allowed) ----------------
__device__ float g_lat[(size_t)NTOK*96];                 // [tok][96]
__device__ float g_q[(size_t)BB*HH*TT*DH];               // [B,H,T,Dh]  (tf32 bits, pre-scaled)
__device__ float g_k[(size_t)BB*HH*TT*DH];               // tf32 bits, dim-columns pair-permuted
__device__ float g_v[(size_t)BB*HH*TT*DH];               // tf32 bits
__device__ float g_y[(size_t)NTOK*CC];                   // [B,T,C]
__device__ unsigned long long g_owT2[(size_t)128*256];   // packed o_w^T pairs [c2][d]
__device__ ulonglong2 g_wAT4[(size_t)64*96];             // down-proj W^T packed [c4][r]
__device__ float g_wqT[(size_t)QR*256];                  // q_b_w^T [r][c]
__device__ float g_wkT[(size_t)KVR*256];                 // k_w^T  [r][c]
__device__ float g_wvT[(size_t)KVR*256];                 // v_w^T  [r][c]

typedef unsigned long long u64;

// ---------------- packed f32x2 helpers ----------------
__device__ __forceinline__ u64 pack2(float lo, float hi) {
    u64 r; asm("mov.b64 %0, {%1, %2};" : "=l"(r) : "f"(lo), "f"(hi)); return r;
}
__device__ __forceinline__ float2 unpack2(u64 v) {
    float2 r; asm("mov.b64 {%0, %1}, %2;" : "=f"(r.x), "=f"(r.y) : "l"(v)); return r;
}
__device__ __forceinline__ u64 fma2(u64 a, u64 b, u64 c) {
    u64 d; asm("fma.rn.f32x2 %0, %1, %2, %3;" : "=l"(d) : "l"(a), "l"(b), "l"(c)); return d;
}

// ---------------- tf32 helpers ----------------
__device__ __forceinline__ float cvt_tf32f(float f) {
    unsigned r; asm("cvt.rna.tf32.f32 %0, %1;" : "=r"(r) : "f"(f));
    return __uint_as_float(r);
}
__device__ __forceinline__ void mma_tf32(float& d0, float& d1, float& d2, float& d3,
    unsigned a0, unsigned a1, unsigned a2, unsigned a3, unsigned b0, unsigned b1) {
    asm volatile("mma.sync.aligned.m16n8k8.row.col.f32.tf32.tf32.f32 "
        "{%0,%1,%2,%3}, {%4,%5,%6,%7}, {%8,%9}, {%0,%1,%2,%3};"
        : "+f"(d0), "+f"(d1), "+f"(d2), "+f"(d3)
        : "r"(a0), "r"(a1), "r"(a2), "r"(a3), "r"(b0), "r"(b1));
}

// ============================================================================
// k0: one-time weight repack/transpose.
// ============================================================================
__global__ void __launch_bounds__(256) k0_prep(
    const float* __restrict__ o_w,
    const float* __restrict__ q_a_w, const float* __restrict__ kv_a_w,
    const float* __restrict__ q_b_w, const float* __restrict__ k_w,
    const float* __restrict__ v_w)
{
    int i = blockIdx.x * 256 + threadIdx.x;
    if (i < 32768) {
        int d = i >> 7, c2 = i & 127;
        g_owT2[(size_t)c2*256 + d] = pack2(o_w[(size_t)d*256 + 2*c2],
                                           o_w[(size_t)d*256 + 2*c2 + 1]);
    } else if (i < 38912) {
        int j = i - 32768;
        int c4 = j / 96, r = j % 96;
        const float* src = (r < QR) ? (q_a_w + (size_t)r*CC)
                                    : (kv_a_w + (size_t)(r-QR)*CC);
        ulonglong2 v;
        v.x = pack2(src[4*c4],     src[4*c4 + 1]);
        v.y = pack2(src[4*c4 + 2], src[4*c4 + 3]);
        g_wAT4[(size_t)c4*96 + r] = v;
    } else if (i < 47104) {
        int j = i - 38912;
        int r = j >> 8, c = j & 255;
        g_wqT[j] = q_b_w[(size_t)c*QR + r];
    } else if (i < 63488) {
        int j = i - 47104;
        int r = j >> 8, c = j & 255;
        g_wkT[j] = k_w[(size_t)c*KVR + r];
    } else if (i < 79872) {
        int j = i - 63488;
        int r = j >> 8, c = j & 255;
        g_wvT[j] = v_w[(size_t)c*KVR + r];
    }
}

// ============================================================================
// k1: LayerNorm + low-rank down projections (coalesced transposed weights).
// ============================================================================
__global__ void __launch_bounds__(256) k1_ln_down(
    const float* __restrict__ x, const float* __restrict__ norm_w,
    const float* __restrict__ q_bias, const float* __restrict__ kv_bias)
{
    __shared__ __align__(16) float xs[TOKTILE][CC];
    const int tok0 = blockIdx.x * TOKTILE;
    const int tid = threadIdx.x;

    const float4* xsrc = (const float4*)(x + (size_t)tok0 * CC);
    float4* xd = (float4*)xs;
#pragma unroll
    for (int i = 0; i < 4; i++) xd[tid + i*256] = xsrc[tid + i*256];
    __syncthreads();

    const int w = tid >> 5, l = tid & 31;
    for (int t = w; t < TOKTILE; t += 8) {
        float s = 0.f, sq = 0.f;
#pragma unroll
        for (int i = 0; i < 8; i++) { float v = xs[t][l + 32*i]; s += v; sq += v*v; }
#pragma unroll
        for (int o = 16; o; o >>= 1) {
            s  += __shfl_xor_sync(0xffffffffu, s,  o);
            sq += __shfl_xor_sync(0xffffffffu, sq, o);
        }
        float mean = s * (1.f/CC);
        float var  = sq * (1.f/CC) - mean*mean;
        float rstd = 1.f / sqrtf(var + 1e-5f);
#pragma unroll
        for (int i = 0; i < 8; i++) {
            int c = l + 32*i;
            xs[t][c] = (xs[t][c] - mean) * rstd * norm_w[c];
        }
    }
    __syncthreads();

    if (tid < 192) {
        const int r = tid % 96, th = tid / 96;
        const int t0 = th * 8;
        u64 acc[8];
#pragma unroll
        for (int tt = 0; tt < 8; tt++) acc[tt] = 0ull;

#pragma unroll 8
        for (int c4 = 0; c4 < 64; c4++) {
            ulonglong2 w4 = g_wAT4[(size_t)c4*96 + r];
#pragma unroll
            for (int tt = 0; tt < 8; tt++) {
                ulonglong2 xv = *(const ulonglong2*)&xs[t0 + tt][4*c4];
                acc[tt] = fma2(xv.x, w4.x, acc[tt]);
                acc[tt] = fma2(xv.y, w4.y, acc[tt]);
            }
        }
        const float bias = (r < QR) ? q_bias[r] : kv_bias[r - QR];
#pragma unroll
        for (int tt = 0; tt < 8; tt++) {
            float2 a = unpack2(acc[tt]);
            g_lat[(size_t)(tok0 + t0 + tt)*96 + r] = a.x + a.y + bias;
        }
    }
}

// ============================================================================
// k2: up projections. g_k written with dim-columns pair-permuted so that
// k3's K B-fragments (cols tig, tig+4) are smem-contiguous (LDS.64).
// ============================================================================
__global__ void __launch_bounds__(256) k2_up()
{
    __shared__ __align__(16) float ls[96][TOKTILE];
    const int tok0 = blockIdx.x * TOKTILE;
    const int tid = threadIdx.x;
    const float SC = 0.17677669529663687f * 1.4426950408889634f;

    for (int i = tid; i < TOKTILE*96; i += 256) {
        int t = i / 96, r = i % 96;
        ls[r][t] = g_lat[(size_t)(tok0 + t)*96 + r];
    }
    __syncthreads();

    const int c = tid, h = c >> 5, d = c & 31;
    const int dp = 8*(d >> 3) + 2*(d & 3) + ((d >> 2) & 1);   // permuted position
    u64 aq[8], ak[8], av[8];
#pragma unroll
    for (int p = 0; p < 8; p++) { aq[p] = 0ull; ak[p] = 0ull; av[p] = 0ull; }

#pragma unroll 4
    for (int r = 0; r < QR; r++) {
        float wv = g_wqT[(size_t)r*256 + c];
        u64 w2 = pack2(wv, wv);
        const ulonglong2* lp = (const ulonglong2*)ls[r];
#pragma unroll
        for (int p = 0; p < 4; p++) {
            ulonglong2 lv = lp[p];
            aq[2*p]   = fma2(lv.x, w2, aq[2*p]);
            aq[2*p+1] = fma2(lv.y, w2, aq[2*p+1]);
        }
    }
#pragma unroll 4
    for (int r = 0; r < KVR; r++) {
        float wk_ = g_wkT[(size_t)r*256 + c];
        float wv_ = g_wvT[(size_t)r*256 + c];
        u64 wk2 = pack2(wk_, wk_), wv2 = pack2(wv_, wv_);
        const ulonglong2* lp = (const ulonglong2*)ls[QR + r];
#pragma unroll
        for (int p = 0; p < 4; p++) {
            ulonglong2 lv = lp[p];
            ak[2*p]   = fma2(lv.x, wk2, ak[2*p]);
            ak[2*p+1] = fma2(lv.y, wk2, ak[2*p+1]);
            av[2*p]   = fma2(lv.x, wv2, av[2*p]);
            av[2*p+1] = fma2(lv.y, wv2, av[2*p+1]);
        }
    }

    const int b = tok0 / TT, t0 = tok0 % TT;
    const size_t baseq = ((size_t)(b*HH + h)*TT + t0)*DH + d;
    const size_t basek = ((size_t)(b*HH + h)*TT + t0)*DH + dp;
#pragma unroll
    for (int p = 0; p < 8; p++) {
        float2 q2v = unpack2(aq[p]);
        float2 k2v = unpack2(ak[p]);
        float2 v2v = unpack2(av[p]);
        g_q[baseq + (size_t)(2*p)*DH]   = cvt_tf32f(q2v.x * SC);
        g_q[baseq + (size_t)(2*p+1)*DH] = cvt_tf32f(q2v.y * SC);
        g_k[basek + (size_t)(2*p)*DH]   = cvt_tf32f(k2v.x);
        g_k[basek + (size_t)(2*p+1)*DH] = cvt_tf32f(k2v.y);
        g_v[baseq + (size_t)(2*p)*DH]   = cvt_tf32f(v2v.x);
        g_v[baseq + (size_t)(2*p+1)*DH] = cvt_tf32f(v2v.y);
    }
}

// ============================================================================
// k3: flash attention, tensor cores, FIXED-MAX softmax (scores are small and
// bounded: p = exp2(s) directly; row-sum reduced once at the end).
// 32 q-rows per warp, 64-key smem tiles processed in two 32-key sub-chunks.
// ============================================================================
#define KS_STR 40
#define VS_STR 40
#define PSTR 36
__global__ void __launch_bounds__(128, 3) k3_attn_mma()
{
    __shared__ __align__(16) float Ks[64*KS_STR];
    __shared__ __align__(16) float Vs[64*VS_STR];
    __shared__ __align__(16) unsigned Ps[4*32*PSTR];

    const int tid = threadIdx.x;
    const int w = tid >> 5, lane = tid & 31;
    const int gid = lane >> 2, tig = lane & 3;
    const int bh = blockIdx.y;
    const int qbase = blockIdx.x * 128 + w * 32;

    const float* qptr = g_q + (size_t)bh*TT*DH;
    unsigned qA[2][4][4];
#pragma unroll
    for (int mh = 0; mh < 2; mh++) {
        const int rA = qbase + 16*mh + gid, rB = rA + 8;
#pragma unroll
        for (int kc = 0; kc < 4; kc++) {
            qA[mh][kc][0] = __float_as_uint(qptr[(size_t)rA*DH + 8*kc + tig]);
            qA[mh][kc][1] = __float_as_uint(qptr[(size_t)rB*DH + 8*kc + tig]);
            qA[mh][kc][2] = __float_as_uint(qptr[(size_t)rA*DH + 8*kc + tig + 4]);
            qA[mh][kc][3] = __float_as_uint(qptr[(size_t)rB*DH + 8*kc + tig + 4]);
        }
    }

    float y[2][4][4];
#pragma unroll
    for (int mh = 0; mh < 2; mh++)
#pragma unroll
        for (int i = 0; i < 4; i++)
#pragma unroll
            for (int j = 0; j < 4; j++) y[mh][i][j] = 0.f;
    float psA[2] = {0.f, 0.f}, psB[2] = {0.f, 0.f};   // per-thread partial row sums

    const float4* kg = (const float4*)(g_k + (size_t)bh*TT*DH);
    const float4* vg = (const float4*)(g_v + (size_t)bh*TT*DH);
    unsigned* myPs = Ps + w*32*PSTR;

    for (int kt = 0; kt < TT; kt += 64) {
        __syncthreads();
#pragma unroll
        for (int i = 0; i < 4; i++) {
            int idx = tid + 128*i;
            int row = idx >> 3, c4 = idx & 7;
            ((float4*)(Ks + row*KS_STR))[c4] = kg[((size_t)(kt + row))*8 + c4];
            ((float4*)(Vs + row*VS_STR))[c4] = vg[((size_t)(kt + row))*8 + c4];
        }
        __syncthreads();

#pragma unroll
        for (int sub = 0; sub < 2; sub++) {
            const int kb0 = 32*sub;

            // S = Q K^T (both m16 halves share each K B-fragment, LDS.64)
            float s[2][4][4];
#pragma unroll
            for (int nc = 0; nc < 4; nc++) {
                s[0][nc][0] = s[0][nc][1] = s[0][nc][2] = s[0][nc][3] = 0.f;
                s[1][nc][0] = s[1][nc][1] = s[1][nc][2] = s[1][nc][3] = 0.f;
#pragma unroll
                for (int kc = 0; kc < 4; kc++) {
                    uint2 kk = *(const uint2*)(Ks + (kb0 + 8*nc + gid)*KS_STR + 8*kc + 2*tig);
                    mma_tf32(s[0][nc][0], s[0][nc][1], s[0][nc][2], s[0][nc][3],
                             qA[0][kc][0], qA[0][kc][1], qA[0][kc][2], qA[0][kc][3], kk.x, kk.y);
                    mma_tf32(s[1][nc][0], s[1][nc][1], s[1][nc][2], s[1][nc][3],
                             qA[1][kc][0], qA[1][kc][1], qA[1][kc][2], qA[1][kc][3], kk.x, kk.y);
                }
            }

            // fixed-max softmax: p = exp2(s); accumulate partial sums; store P
#pragma unroll
            for (int mh = 0; mh < 2; mh++) {
#pragma unroll
                for (int nc = 0; nc < 4; nc++) {
                    float p0 = exp2f(s[mh][nc][0]);
                    float p1 = exp2f(s[mh][nc][1]);
                    float p2 = exp2f(s[mh][nc][2]);
                    float p3 = exp2f(s[mh][nc][3]);
                    psA[mh] += p0 + p1;
                    psB[mh] += p2 + p3;
                    uint2 v0; v0.x = __float_as_uint(p0); v0.y = __float_as_uint(p1);
                    uint2 v1; v1.x = __float_as_uint(p2); v1.y = __float_as_uint(p3);
                    *(uint2*)&myPs[(gid + 16*mh)*PSTR     + 8*nc + 2*tig] = v0;
                    *(uint2*)&myPs[(gid + 8 + 16*mh)*PSTR + 8*nc + 2*tig] = v1;
                }
            }
            __syncwarp();

            // Y += P V (both halves share each V B-fragment)
#pragma unroll
            for (int kc = 0; kc < 4; kc++) {
                unsigned a[2][4];
#pragma unroll
                for (int mh = 0; mh < 2; mh++) {
                    a[mh][0] = myPs[(gid + 16*mh)*PSTR     + 8*kc + tig];
                    a[mh][1] = myPs[(gid + 8 + 16*mh)*PSTR + 8*kc + tig];
                    a[mh][2] = myPs[(gid + 16*mh)*PSTR     + 8*kc + tig + 4];
                    a[mh][3] = myPs[(gid + 8 + 16*mh)*PSTR + 8*kc + tig + 4];
                }
#pragma unroll
                for (int nc2 = 0; nc2 < 4; nc2++) {
                    unsigned b0 = __float_as_uint(Vs[(kb0 + 8*kc + tig)*VS_STR     + 8*nc2 + gid]);
                    unsigned b1 = __float_as_uint(Vs[(kb0 + 8*kc + tig + 4)*VS_STR + 8*nc2 + gid]);
                    mma_tf32(y[0][nc2][0], y[0][nc2][1], y[0][nc2][2], y[0][nc2][3],
                             a[0][0], a[0][1], a[0][2], a[0][3], b0, b1);
                    mma_tf32(y[1][nc2][0], y[1][nc2][1], y[1][nc2][2], y[1][nc2][3],
                             a[1][0], a[1][1], a[1][2], a[1][3], b0, b1);
                }
            }
            __syncwarp();
        }
    }

    // final row-sum reduction (once), then normalize + write
    const int b = bh >> 3, h = bh & 7;
#pragma unroll
    for (int mh = 0; mh < 2; mh++) {
        float sA = psA[mh], sB = psB[mh];
        sA += __shfl_xor_sync(0xffffffffu, sA, 1);
        sA += __shfl_xor_sync(0xffffffffu, sA, 2);
        sB += __shfl_xor_sync(0xffffffffu, sB, 1);
        sB += __shfl_xor_sync(0xffffffffu, sB, 2);
        const float inv0 = 1.0f / sA, inv1 = 1.0f / sB;
        const int rA = qbase + 16*mh + gid, rB = rA + 8;
#pragma unroll
        for (int nc2 = 0; nc2 < 4; nc2++) {
            int col = h*DH + nc2*8 + 2*tig;
            float2 o0; o0.x = y[mh][nc2][0]*inv0; o0.y = y[mh][nc2][1]*inv0;
            float2 o1; o1.x = y[mh][nc2][2]*inv1; o1.y = y[mh][nc2][3]*inv1;
            *(float2*)&g_y[(size_t)(b*TT + rA)*CC + col] = o0;
            *(float2*)&g_y[(size_t)(b*TT + rB)*CC + col] = o1;
        }
    }
}

// ============================================================================
// k4: output projection + gamma + residual. Barrier-free main loop.
// ============================================================================
__global__ void __launch_bounds__(256) k4_oproj(
    const float* __restrict__ x, const float* __restrict__ gamma,
    float* __restrict__ out)
{
    __shared__ __align__(16) float ys[TOKTILE][CC];
    const int tok0 = blockIdx.x * TOKTILE;
    const int tid = threadIdx.x;

    const float4* ysrc = (const float4*)(g_y + (size_t)tok0 * CC);
    float4* yd = (float4*)ys;
#pragma unroll
    for (int i = 0; i < 4; i++) yd[tid + i*256] = ysrc[tid + i*256];
    __syncthreads();

    u64 acc[16];
#pragma unroll
    for (int t = 0; t < 16; t++) acc[t] = 0ull;

    const u64* wT = g_owT2;
#pragma unroll 4
    for (int c2 = 0; c2 < 128; c2++) {
        u64 w2 = wT[(size_t)c2*256 + tid];
        const float* yb = &ys[0][2*c2];
#pragma unroll
        for (int t = 0; t < 16; t++) {
            u64 yv = *(const u64*)(yb + t*CC);
            acc[t] = fma2(yv, w2, acc[t]);
        }
    }

    const float g = gamma[tid];
#pragma unroll
    for (int t = 0; t < 16; t++) {
        float2 a = unpack2(acc[t]);
        size_t o = (size_t)(tok0 + t)*CC + tid;
        out[o] = x[o] + g * (a.x + a.y);
    }
}

// ============================================================================
extern "C" void kernel_launch(void* const* d_in, const int* in_sizes, int n_in,
                              void* d_out, int out_size)
{
    const float* x       = (const float*)d_in[0];
    const float* q_a_w   = (const float*)d_in[1];
    const float* q_bias  = (const float*)d_in[2];
    const float* q_b_w   = (const float*)d_in[3];
    const float* kv_a_w  = (const float*)d_in[4];
    const float* kv_bias = (const float*)d_in[5];
    const float* k_w     = (const float*)d_in[6];
    const float* v_w     = (const float*)d_in[7];
    const float* o_w     = (const float*)d_in[8];
    const float* norm_w  = (const float*)d_in[9];
    const float* gamma   = (const float*)d_in[10];
    float* out = (float*)d_out;

    k0_prep<<<312, 256>>>(o_w, q_a_w, kv_a_w, q_b_w, k_w, v_w);
    k1_ln_down<<<NBLK, 256>>>(x, norm_w, q_bias, kv_bias);
    k2_up<<<NBLK, 256>>>();
    dim3 g3(TT/128, BB*HH);
    k3_attn_mma<<<g3, 128>>>();
    k4_oproj<<<NBLK, 256>>>(x, gamma, out);
}

// round 10
// speedup vs baseline: 5.8647x; 1.4616x over previous
#include <cuda_runtime.h>
#include <cuda_bf16.h>
#include <cstdint>

#define BB 4
#define TT 2048
#define CC 256
#define HH 8
#define DH 32
#define QR 32
#define KVR 64
#define NTOK (BB*TT)          // 8192
#define TOKTILE 16
#define NBLK (NTOK/TOKTILE)   // 512

// ---------------- scratch (device globals; no allocation allowed) ----------------
__device__ float g_lat[(size_t)NTOK*96];                 // [tok][96]
__device__ __nv_bfloat16 g_qb[(size_t)BB*HH*TT*DH];      // [bh][t][d], pre-scaled
__device__ __nv_bfloat16 g_kb[(size_t)BB*HH*TT*DH];      // [bh][t][d]
__device__ __nv_bfloat16 g_vT[(size_t)BB*HH*DH*TT];      // [bh][d][t]  (transposed!)
__device__ float g_y[(size_t)NTOK*CC];                   // [B,T,C]
__device__ unsigned long long g_owT2[(size_t)128*256];   // packed o_w^T pairs [c2][d]
__device__ ulonglong2 g_wAT4[(size_t)64*96];             // down-proj W^T packed [c4][r]
__device__ float g_wqT[(size_t)QR*256];                  // q_b_w^T [r][c]
__device__ float g_wkT[(size_t)KVR*256];                 // k_w^T  [r][c]
__device__ float g_wvT[(size_t)KVR*256];                 // v_w^T  [r][c]

typedef unsigned long long u64;

// ---------------- packed f32x2 helpers ----------------
__device__ __forceinline__ u64 pack2(float lo, float hi) {
    u64 r; asm("mov.b64 %0, {%1, %2};" : "=l"(r) : "f"(lo), "f"(hi)); return r;
}
__device__ __forceinline__ float2 unpack2(u64 v) {
    float2 r; asm("mov.b64 {%0, %1}, %2;" : "=f"(r.x), "=f"(r.y) : "l"(v)); return r;
}
__device__ __forceinline__ u64 fma2(u64 a, u64 b, u64 c) {
    u64 d; asm("fma.rn.f32x2 %0, %1, %2, %3;" : "=l"(d) : "l"(a), "l"(b), "l"(c)); return d;
}

// ---------------- bf16 helpers ----------------
__device__ __forceinline__ unsigned bf16x2(float lo, float hi) {
    unsigned r; asm("cvt.rn.bf16x2.f32 %0, %1, %2;" : "=r"(r) : "f"(hi), "f"(lo)); return r;
}
__device__ __forceinline__ void mma_bf16(float* d,
    unsigned a0, unsigned a1, unsigned a2, unsigned a3, unsigned b0, unsigned b1) {
    asm volatile("mma.sync.aligned.m16n8k16.row.col.f32.bf16.bf16.f32 "
        "{%0,%1,%2,%3}, {%4,%5,%6,%7}, {%8,%9}, {%0,%1,%2,%3};"
        : "+f"(d[0]), "+f"(d[1]), "+f"(d[2]), "+f"(d[3])
        : "r"(a0), "r"(a1), "r"(a2), "r"(a3), "r"(b0), "r"(b1));
}

// ============================================================================
// k0: one-time weight repack/transpose.
// ============================================================================
__global__ void __launch_bounds__(256) k0_prep(
    const float* __restrict__ o_w,
    const float* __restrict__ q_a_w, const float* __restrict__ kv_a_w,
    const float* __restrict__ q_b_w, const float* __restrict__ k_w,
    const float* __restrict__ v_w)
{
    int i = blockIdx.x * 256 + threadIdx.x;
    if (i < 32768) {
        int d = i >> 7, c2 = i & 127;
        g_owT2[(size_t)c2*256 + d] = pack2(o_w[(size_t)d*256 + 2*c2],
                                           o_w[(size_t)d*256 + 2*c2 + 1]);
    } else if (i < 38912) {
        int j = i - 32768;
        int c4 = j / 96, r = j % 96;
        const float* src = (r < QR) ? (q_a_w + (size_t)r*CC)
                                    : (kv_a_w + (size_t)(r-QR)*CC);
        ulonglong2 v;
        v.x = pack2(src[4*c4],     src[4*c4 + 1]);
        v.y = pack2(src[4*c4 + 2], src[4*c4 + 3]);
        g_wAT4[(size_t)c4*96 + r] = v;
    } else if (i < 47104) {
        int j = i - 38912;
        int r = j >> 8, c = j & 255;
        g_wqT[j] = q_b_w[(size_t)c*QR + r];
    } else if (i < 63488) {
        int j = i - 47104;
        int r = j >> 8, c = j & 255;
        g_wkT[j] = k_w[(size_t)c*KVR + r];
    } else if (i < 79872) {
        int j = i - 63488;
        int r = j >> 8, c = j & 255;
        g_wvT[j] = v_w[(size_t)c*KVR + r];
    }
}

// ============================================================================
// k1: LayerNorm + low-rank down projections (coalesced transposed weights).
// ============================================================================
__global__ void __launch_bounds__(256) k1_ln_down(
    const float* __restrict__ x, const float* __restrict__ norm_w,
    const float* __restrict__ q_bias, const float* __restrict__ kv_bias)
{
    __shared__ __align__(16) float xs[TOKTILE][CC];
    const int tok0 = blockIdx.x * TOKTILE;
    const int tid = threadIdx.x;

    const float4* xsrc = (const float4*)(x + (size_t)tok0 * CC);
    float4* xd = (float4*)xs;
#pragma unroll
    for (int i = 0; i < 4; i++) xd[tid + i*256] = xsrc[tid + i*256];
    __syncthreads();

    const int w = tid >> 5, l = tid & 31;
    for (int t = w; t < TOKTILE; t += 8) {
        float s = 0.f, sq = 0.f;
#pragma unroll
        for (int i = 0; i < 8; i++) { float v = xs[t][l + 32*i]; s += v; sq += v*v; }
#pragma unroll
        for (int o = 16; o; o >>= 1) {
            s  += __shfl_xor_sync(0xffffffffu, s,  o);
            sq += __shfl_xor_sync(0xffffffffu, sq, o);
        }
        float mean = s * (1.f/CC);
        float var  = sq * (1.f/CC) - mean*mean;
        float rstd = 1.f / sqrtf(var + 1e-5f);
#pragma unroll
        for (int i = 0; i < 8; i++) {
            int c = l + 32*i;
            xs[t][c] = (xs[t][c] - mean) * rstd * norm_w[c];
        }
    }
    __syncthreads();

    if (tid < 192) {
        const int r = tid % 96, th = tid / 96;
        const int t0 = th * 8;
        u64 acc[8];
#pragma unroll
        for (int tt = 0; tt < 8; tt++) acc[tt] = 0ull;

#pragma unroll 8
        for (int c4 = 0; c4 < 64; c4++) {
            ulonglong2 w4 = g_wAT4[(size_t)c4*96 + r];
#pragma unroll
            for (int tt = 0; tt < 8; tt++) {
                ulonglong2 xv = *(const ulonglong2*)&xs[t0 + tt][4*c4];
                acc[tt] = fma2(xv.x, w4.x, acc[tt]);
                acc[tt] = fma2(xv.y, w4.y, acc[tt]);
            }
        }
        const float bias = (r < QR) ? q_bias[r] : kv_bias[r - QR];
#pragma unroll
        for (int tt = 0; tt < 8; tt++) {
            float2 a = unpack2(acc[tt]);
            g_lat[(size_t)(tok0 + t0 + tt)*96 + r] = a.x + a.y + bias;
        }
    }
}

// ============================================================================
// k2: up projections -> bf16 outputs. q pre-scaled; v written TRANSPOSED.
// ============================================================================
__global__ void __launch_bounds__(256) k2_up()
{
    __shared__ __align__(16) float ls[96][TOKTILE];
    const int tok0 = blockIdx.x * TOKTILE;
    const int tid = threadIdx.x;
    const float SC = 0.17677669529663687f * 1.4426950408889634f; // 1/sqrt(32)*log2(e)

    for (int i = tid; i < TOKTILE*96; i += 256) {
        int t = i / 96, r = i % 96;
        ls[r][t] = g_lat[(size_t)(tok0 + t)*96 + r];
    }
    __syncthreads();

    const int c = tid, h = c >> 5, d = c & 31;
    u64 aq[8], ak[8], av[8];
#pragma unroll
    for (int p = 0; p < 8; p++) { aq[p] = 0ull; ak[p] = 0ull; av[p] = 0ull; }

#pragma unroll 4
    for (int r = 0; r < QR; r++) {
        float wv = g_wqT[(size_t)r*256 + c];
        u64 w2 = pack2(wv, wv);
        const ulonglong2* lp = (const ulonglong2*)ls[r];
#pragma unroll
        for (int p = 0; p < 4; p++) {
            ulonglong2 lv = lp[p];
            aq[2*p]   = fma2(lv.x, w2, aq[2*p]);
            aq[2*p+1] = fma2(lv.y, w2, aq[2*p+1]);
        }
    }
#pragma unroll 4
    for (int r = 0; r < KVR; r++) {
        float wk_ = g_wkT[(size_t)r*256 + c];
        float wv_ = g_wvT[(size_t)r*256 + c];
        u64 wk2 = pack2(wk_, wk_), wv2 = pack2(wv_, wv_);
        const ulonglong2* lp = (const ulonglong2*)ls[QR + r];
#pragma unroll
        for (int p = 0; p < 4; p++) {
            ulonglong2 lv = lp[p];
            ak[2*p]   = fma2(lv.x, wk2, ak[2*p]);
            ak[2*p+1] = fma2(lv.y, wk2, ak[2*p+1]);
            av[2*p]   = fma2(lv.x, wv2, av[2*p]);
            av[2*p+1] = fma2(lv.y, wv2, av[2*p+1]);
        }
    }

    const int b = tok0 / TT, t0 = tok0 % TT;
    const size_t tb = (size_t)(b*HH + h)*TT + t0;
    __nv_bfloat16* qb = g_qb + tb*DH + d;
    __nv_bfloat16* kb = g_kb + tb*DH + d;
    unsigned* vt = (unsigned*)(g_vT + ((size_t)(b*HH + h)*DH + d)*TT + t0);
#pragma unroll
    for (int p = 0; p < 8; p++) {
        float2 q2v = unpack2(aq[p]);
        float2 k2v = unpack2(ak[p]);
        float2 v2v = unpack2(av[p]);
        qb[(size_t)(2*p)*DH]   = __float2bfloat16_rn(q2v.x * SC);
        qb[(size_t)(2*p+1)*DH] = __float2bfloat16_rn(q2v.y * SC);
        kb[(size_t)(2*p)*DH]   = __float2bfloat16_rn(k2v.x);
        kb[(size_t)(2*p+1)*DH] = __float2bfloat16_rn(k2v.y);
        vt[p] = bf16x2(v2v.x, v2v.y);
    }
}

// ============================================================================
// k3: flash attention, bf16 m16n8k16 tensor cores, fixed-max softmax,
// FA2 register-reuse: P stays in registers (S D-frags -> bf16 A-frags).
// 32 q-rows/warp, 64-key smem tiles, two 32-key sub-chunks.
// ============================================================================
#define KB_STR 40   // bf16 elements per K row (80B; conflict-free B-frag LDS.32)
#define VB_STR 72   // bf16 elements per V row (144B; conflict-free B-frag LDS.32)
__global__ void __launch_bounds__(128, 3) k3_attn_mma()
{
    __shared__ __align__(16) __nv_bfloat16 Kbs[64*KB_STR];   // [key][dim]
    __shared__ __align__(16) __nv_bfloat16 Vbs[32*VB_STR];   // [dim][key]

    const int tid = threadIdx.x;
    const int w = tid >> 5, lane = tid & 31;
    const int gid = lane >> 2, tig = lane & 3;
    const int bh = blockIdx.y;
    const int qbase = blockIdx.x * 128 + w * 32;

    // Q A-fragments (m16n8k16): qA[mh][kg][4], kg = 16-dim group
    const __nv_bfloat16* qptr = g_qb + (size_t)bh*TT*DH;
    unsigned qA[2][2][4];
#pragma unroll
    for (int mh = 0; mh < 2; mh++) {
        const int rA = qbase + 16*mh + gid, rB = rA + 8;
#pragma unroll
        for (int kg = 0; kg < 2; kg++) {
            qA[mh][kg][0] = *(const unsigned*)(qptr + (size_t)rA*DH + 16*kg + 2*tig);
            qA[mh][kg][1] = *(const unsigned*)(qptr + (size_t)rB*DH + 16*kg + 2*tig);
            qA[mh][kg][2] = *(const unsigned*)(qptr + (size_t)rA*DH + 16*kg + 2*tig + 8);
            qA[mh][kg][3] = *(const unsigned*)(qptr + (size_t)rB*DH + 16*kg + 2*tig + 8);
        }
    }

    float y[2][4][4];
#pragma unroll
    for (int mh = 0; mh < 2; mh++)
#pragma unroll
        for (int i = 0; i < 4; i++)
#pragma unroll
            for (int j = 0; j < 4; j++) y[mh][i][j] = 0.f;
    float psA[2] = {0.f, 0.f}, psB[2] = {0.f, 0.f};

    const uint2* kg2 = (const uint2*)(g_kb + (size_t)bh*TT*DH);   // 8 uint2 per key row
    const uint2* vg2 = (const uint2*)(g_vT + (size_t)bh*DH*TT);   // TT/4 uint2 per dim row

    for (int kt = 0; kt < TT; kt += 64) {
        __syncthreads();
        // K tile: 64 keys x 32 dims bf16 (4KB)
#pragma unroll
        for (int i = 0; i < 4; i++) {
            int idx = tid + 128*i;
            int row = idx >> 3, c = idx & 7;
            *(uint2*)(Kbs + row*KB_STR + c*4) = kg2[(size_t)(kt + row)*8 + c];
        }
        // V tile (transposed): 32 dims x 64 keys bf16 (4KB)
#pragma unroll
        for (int i = 0; i < 4; i++) {
            int idx = tid + 128*i;
            int row = idx >> 4, c = idx & 15;
            *(uint2*)(Vbs + row*VB_STR + c*4) = vg2[(size_t)row*(TT/4) + kt/4 + c];
        }
        __syncthreads();

#pragma unroll
        for (int sub = 0; sub < 2; sub++) {
            const int kb0 = 32*sub;

            // S = Q K^T : nc = 8-key group, kg = 16-dim group
            float s[2][4][4];
#pragma unroll
            for (int nc = 0; nc < 4; nc++) {
                s[0][nc][0] = s[0][nc][1] = s[0][nc][2] = s[0][nc][3] = 0.f;
                s[1][nc][0] = s[1][nc][1] = s[1][nc][2] = s[1][nc][3] = 0.f;
#pragma unroll
                for (int kg = 0; kg < 2; kg++) {
                    const __nv_bfloat16* kr = Kbs + (kb0 + 8*nc + gid)*KB_STR + 16*kg + 2*tig;
                    unsigned b0 = *(const unsigned*)(kr);
                    unsigned b1 = *(const unsigned*)(kr + 8);
                    mma_bf16(s[0][nc], qA[0][kg][0], qA[0][kg][1], qA[0][kg][2], qA[0][kg][3], b0, b1);
                    mma_bf16(s[1][nc], qA[1][kg][0], qA[1][kg][1], qA[1][kg][2], qA[1][kg][3], b0, b1);
                }
            }

            // fixed-max softmax: p = exp2(s); partial sums; pack P to bf16 A-frags
            unsigned pa[2][2][4];
#pragma unroll
            for (int mh = 0; mh < 2; mh++) {
#pragma unroll
                for (int kg = 0; kg < 2; kg++) {
                    float p00 = exp2f(s[mh][2*kg][0]);
                    float p01 = exp2f(s[mh][2*kg][1]);
                    float p02 = exp2f(s[mh][2*kg][2]);
                    float p03 = exp2f(s[mh][2*kg][3]);
                    float p10 = exp2f(s[mh][2*kg+1][0]);
                    float p11 = exp2f(s[mh][2*kg+1][1]);
                    float p12 = exp2f(s[mh][2*kg+1][2]);
                    float p13 = exp2f(s[mh][2*kg+1][3]);
                    psA[mh] += (p00 + p01) + (p10 + p11);
                    psB[mh] += (p02 + p03) + (p12 + p13);
                    pa[mh][kg][0] = bf16x2(p00, p01);   // row gid,  k 2tig..+1
                    pa[mh][kg][1] = bf16x2(p02, p03);   // row gid+8
                    pa[mh][kg][2] = bf16x2(p10, p11);   // row gid,  k 2tig+8..+9
                    pa[mh][kg][3] = bf16x2(p12, p13);   // row gid+8
                }
            }

            // Y += P V : kg = 16-key group, nc2 = 8-dim group (B shared across mh)
#pragma unroll
            for (int kg = 0; kg < 2; kg++) {
#pragma unroll
                for (int nc2 = 0; nc2 < 4; nc2++) {
                    const __nv_bfloat16* vr = Vbs + (8*nc2 + gid)*VB_STR + kb0 + 16*kg + 2*tig;
                    unsigned b0 = *(const unsigned*)(vr);
                    unsigned b1 = *(const unsigned*)(vr + 8);
                    mma_bf16(y[0][nc2], pa[0][kg][0], pa[0][kg][1], pa[0][kg][2], pa[0][kg][3], b0, b1);
                    mma_bf16(y[1][nc2], pa[1][kg][0], pa[1][kg][1], pa[1][kg][2], pa[1][kg][3], b0, b1);
                }
            }
        }
    }

    // final row-sum reduction, normalize, write
    const int b = bh >> 3, h = bh & 7;
#pragma unroll
    for (int mh = 0; mh < 2; mh++) {
        float sA = psA[mh], sB = psB[mh];
        sA += __shfl_xor_sync(0xffffffffu, sA, 1);
        sA += __shfl_xor_sync(0xffffffffu, sA, 2);
        sB += __shfl_xor_sync(0xffffffffu, sB, 1);
        sB += __shfl_xor_sync(0xffffffffu, sB, 2);
        const float inv0 = 1.0f / sA, inv1 = 1.0f / sB;
        const int rA = qbase + 16*mh + gid, rB = rA + 8;
#pragma unroll
        for (int nc2 = 0; nc2 < 4; nc2++) {
            int col = h*DH + nc2*8 + 2*tig;
            float2 o0; o0.x = y[mh][nc2][0]*inv0; o0.y = y[mh][nc2][1]*inv0;
            float2 o1; o1.x = y[mh][nc2][2]*inv1; o1.y = y[mh][nc2][3]*inv1;
            *(float2*)&g_y[(size_t)(b*TT + rA)*CC + col] = o0;
            *(float2*)&g_y[(size_t)(b*TT + rB)*CC + col] = o1;
        }
    }
}

// ============================================================================
// k4: output projection + gamma + residual. Barrier-free main loop.
// ============================================================================
__global__ void __launch_bounds__(256) k4_oproj(
    const float* __restrict__ x, const float* __restrict__ gamma,
    float* __restrict__ out)
{
    __shared__ __align__(16) float ys[TOKTILE][CC];
    const int tok0 = blockIdx.x * TOKTILE;
    const int tid = threadIdx.x;

    const float4* ysrc = (const float4*)(g_y + (size_t)tok0 * CC);
    float4* yd = (float4*)ys;
#pragma unroll
    for (int i = 0; i < 4; i++) yd[tid + i*256] = ysrc[tid + i*256];
    __syncthreads();

    u64 acc[16];
#pragma unroll
    for (int t = 0; t < 16; t++) acc[t] = 0ull;

    const u64* wT = g_owT2;
#pragma unroll 4
    for (int c2 = 0; c2 < 128; c2++) {
        u64 w2 = wT[(size_t)c2*256 + tid];
        const float* yb = &ys[0][2*c2];
#pragma unroll
        for (int t = 0; t < 16; t++) {
            u64 yv = *(const u64*)(yb + t*CC);
            acc[t] = fma2(yv, w2, acc[t]);
        }
    }

    const float g = gamma[tid];
#pragma unroll
    for (int t = 0; t < 16; t++) {
        float2 a = unpack2(acc[t]);
        size_t o = (size_t)(tok0 + t)*CC + tid;
        out[o] = x[o] + g * (a.x + a.y);
    }
}

// ============================================================================
extern "C" void kernel_launch(void* const* d_in, const int* in_sizes, int n_in,
                              void* d_out, int out_size)
{
    const float* x       = (const float*)d_in[0];
    const float* q_a_w   = (const float*)d_in[1];
    const float* q_bias  = (const float*)d_in[2];
    const float* q_b_w   = (const float*)d_in[3];
    const float* kv_a_w  = (const float*)d_in[4];
    const float* kv_bias = (const float*)d_in[5];
    const float* k_w     = (const float*)d_in[6];
    const float* v_w     = (const float*)d_in[7];
    const float* o_w     = (const float*)d_in[8];
    const float* norm_w  = (const float*)d_in[9];
    const float* gamma   = (const float*)d_in[10];
    float* out = (float*)d_out;

    k0_prep<<<312, 256>>>(o_w, q_a_w, kv_a_w, q_b_w, k_w, v_w);
    k1_ln_down<<<NBLK, 256>>>(x, norm_w, q_bias, kv_bias);
    k2_up<<<NBLK, 256>>>();
    dim3 g3(TT/128, BB*HH);
    k3_attn_mma<<<g3, 128>>>();
    k4_oproj<<<NBLK, 256>>>(x, gamma, out);
}

// round 11
// speedup vs baseline: 6.8375x; 1.1659x over previous
#include <cuda_runtime.h>
#include <cuda_bf16.h>
#include <cstdint>

#define BB 4
#define TT 2048
#define CC 256
#define HH 8
#define DH 32
#define QR 32
#define KVR 64
#define NTOK (BB*TT)          // 8192
#define TOKTILE 16
#define NBLK (NTOK/TOKTILE)   // 512

// ---------------- scratch (device globals; no allocation allowed) ----------------
__device__ __nv_bfloat16 g_qb[(size_t)BB*HH*TT*DH];      // [bh][t][d], pre-scaled
__device__ __nv_bfloat16 g_kb[(size_t)BB*HH*TT*DH];      // [bh][t][d]
__device__ __nv_bfloat16 g_vT[(size_t)BB*HH*DH*TT];      // [bh][d][t]  (transposed)
__device__ unsigned g_yb[(size_t)NTOK*CC/2];             // attention out, bf16 pairs [tok][c/2]
__device__ unsigned g_owb[(size_t)256*128];              // o_w bf16 pairs [d][c2]
__device__ ulonglong2 g_wAT4[(size_t)64*96];             // down-proj W^T packed [c4][r]
__device__ float g_wqT[(size_t)QR*256];                  // q_b_w^T [r][c]
__device__ float g_wkT[(size_t)KVR*256];                 // k_w^T  [r][c]
__device__ float g_wvT[(size_t)KVR*256];                 // v_w^T  [r][c]

typedef unsigned long long u64;

// ---------------- packed f32x2 helpers ----------------
__device__ __forceinline__ u64 pack2(float lo, float hi) {
    u64 r; asm("mov.b64 %0, {%1, %2};" : "=l"(r) : "f"(lo), "f"(hi)); return r;
}
__device__ __forceinline__ float2 unpack2(u64 v) {
    float2 r; asm("mov.b64 {%0, %1}, %2;" : "=f"(r.x), "=f"(r.y) : "l"(v)); return r;
}
__device__ __forceinline__ u64 fma2(u64 a, u64 b, u64 c) {
    u64 d; asm("fma.rn.f32x2 %0, %1, %2, %3;" : "=l"(d) : "l"(a), "l"(b), "l"(c)); return d;
}

// ---------------- bf16 helpers ----------------
__device__ __forceinline__ unsigned bf16x2(float lo, float hi) {
    unsigned r; asm("cvt.rn.bf16x2.f32 %0, %1, %2;" : "=r"(r) : "f"(hi), "f"(lo)); return r;
}
__device__ __forceinline__ void mma_bf16(float* d,
    unsigned a0, unsigned a1, unsigned a2, unsigned a3, unsigned b0, unsigned b1) {
    asm volatile("mma.sync.aligned.m16n8k16.row.col.f32.bf16.bf16.f32 "
        "{%0,%1,%2,%3}, {%4,%5,%6,%7}, {%8,%9}, {%0,%1,%2,%3};"
        : "+f"(d[0]), "+f"(d[1]), "+f"(d[2]), "+f"(d[3])
        : "r"(a0), "r"(a1), "r"(a2), "r"(a3), "r"(b0), "r"(b1));
}

// ============================================================================
// k0: one-time weight repack/transpose.
// ============================================================================
__global__ void __launch_bounds__(256) k0_prep(
    const float* __restrict__ o_w,
    const float* __restrict__ q_a_w, const float* __restrict__ kv_a_w,
    const float* __restrict__ q_b_w, const float* __restrict__ k_w,
    const float* __restrict__ v_w)
{
    int i = blockIdx.x * 256 + threadIdx.x;
    if (i < 32768) {
        int d = i >> 7, c2 = i & 127;
        g_owb[(size_t)d*128 + c2] = bf16x2(o_w[(size_t)d*256 + 2*c2],
                                           o_w[(size_t)d*256 + 2*c2 + 1]);
    } else if (i < 38912) {
        int j = i - 32768;
        int c4 = j / 96, r = j % 96;
        const float* src = (r < QR) ? (q_a_w + (size_t)r*CC)
                                    : (kv_a_w + (size_t)(r-QR)*CC);
        ulonglong2 v;
        v.x = pack2(src[4*c4],     src[4*c4 + 1]);
        v.y = pack2(src[4*c4 + 2], src[4*c4 + 3]);
        g_wAT4[(size_t)c4*96 + r] = v;
    } else if (i < 47104) {
        int j = i - 38912;
        int r = j >> 8, c = j & 255;
        g_wqT[j] = q_b_w[(size_t)c*QR + r];
    } else if (i < 63488) {
        int j = i - 47104;
        int r = j >> 8, c = j & 255;
        g_wkT[j] = k_w[(size_t)c*KVR + r];
    } else if (i < 79872) {
        int j = i - 63488;
        int r = j >> 8, c = j & 255;
        g_wvT[j] = v_w[(size_t)c*KVR + r];
    }
}

// ============================================================================
// k1: FUSED LayerNorm + down-proj + up-proj. lat stays in smem (no g_lat).
// Writes q (scaled, bf16), k (bf16), v (bf16, transposed).
// ============================================================================
#define LS_STR 20   // floats per lat row: 16B-aligned rows, <=4-way STS conflicts
__global__ void __launch_bounds__(256) k1_fused(
    const float* __restrict__ x, const float* __restrict__ norm_w,
    const float* __restrict__ q_bias, const float* __restrict__ kv_bias)
{
    __shared__ __align__(16) float xs[TOKTILE][CC];
    __shared__ __align__(16) float lsf[96][LS_STR];
    const int tok0 = blockIdx.x * TOKTILE;
    const int tid = threadIdx.x;

    const float4* xsrc = (const float4*)(x + (size_t)tok0 * CC);
    float4* xd = (float4*)xs;
#pragma unroll
    for (int i = 0; i < 4; i++) xd[tid + i*256] = xsrc[tid + i*256];
    __syncthreads();

    // LayerNorm
    const int w = tid >> 5, l = tid & 31;
    for (int t = w; t < TOKTILE; t += 8) {
        float s = 0.f, sq = 0.f;
#pragma unroll
        for (int i = 0; i < 8; i++) { float v = xs[t][l + 32*i]; s += v; sq += v*v; }
#pragma unroll
        for (int o = 16; o; o >>= 1) {
            s  += __shfl_xor_sync(0xffffffffu, s,  o);
            sq += __shfl_xor_sync(0xffffffffu, sq, o);
        }
        float mean = s * (1.f/CC);
        float var  = sq * (1.f/CC) - mean*mean;
        float rstd = 1.f / sqrtf(var + 1e-5f);
#pragma unroll
        for (int i = 0; i < 8; i++) {
            int c = l + 32*i;
            xs[t][c] = (xs[t][c] - mean) * rstd * norm_w[c];
        }
    }
    __syncthreads();

    // down-proj: 192 threads, thread = (r, token-half); writes lat to smem
    if (tid < 192) {
        const int r = tid % 96, th = tid / 96;
        const int t0 = th * 8;
        u64 acc[8];
#pragma unroll
        for (int tt = 0; tt < 8; tt++) acc[tt] = 0ull;
#pragma unroll 8
        for (int c4 = 0; c4 < 64; c4++) {
            ulonglong2 w4 = g_wAT4[(size_t)c4*96 + r];
#pragma unroll
            for (int tt = 0; tt < 8; tt++) {
                ulonglong2 xv = *(const ulonglong2*)&xs[t0 + tt][4*c4];
                acc[tt] = fma2(xv.x, w4.x, acc[tt]);
                acc[tt] = fma2(xv.y, w4.y, acc[tt]);
            }
        }
        const float bias = (r < QR) ? q_bias[r] : kv_bias[r - QR];
#pragma unroll
        for (int tt = 0; tt < 8; tt++) {
            float2 a = unpack2(acc[tt]);
            lsf[r][t0 + tt] = a.x + a.y + bias;
        }
    }
    __syncthreads();

    // up-proj: thread = output channel c; lat via broadcast LDS.128
    const float SC = 0.17677669529663687f * 1.4426950408889634f; // 1/sqrt(32)*log2(e)
    const int c = tid, h = c >> 5, d = c & 31;
    u64 aq[8], ak[8], av[8];
#pragma unroll
    for (int p = 0; p < 8; p++) { aq[p] = 0ull; ak[p] = 0ull; av[p] = 0ull; }

#pragma unroll 4
    for (int r = 0; r < QR; r++) {
        float wv = g_wqT[(size_t)r*256 + c];
        u64 w2 = pack2(wv, wv);
        const ulonglong2* lp = (const ulonglong2*)lsf[r];
#pragma unroll
        for (int p = 0; p < 4; p++) {
            ulonglong2 lv = lp[p];
            aq[2*p]   = fma2(lv.x, w2, aq[2*p]);
            aq[2*p+1] = fma2(lv.y, w2, aq[2*p+1]);
        }
    }
#pragma unroll 4
    for (int r = 0; r < KVR; r++) {
        float wk_ = g_wkT[(size_t)r*256 + c];
        float wv_ = g_wvT[(size_t)r*256 + c];
        u64 wk2 = pack2(wk_, wk_), wv2 = pack2(wv_, wv_);
        const ulonglong2* lp = (const ulonglong2*)lsf[QR + r];
#pragma unroll
        for (int p = 0; p < 4; p++) {
            ulonglong2 lv = lp[p];
            ak[2*p]   = fma2(lv.x, wk2, ak[2*p]);
            ak[2*p+1] = fma2(lv.y, wk2, ak[2*p+1]);
            av[2*p]   = fma2(lv.x, wv2, av[2*p]);
            av[2*p+1] = fma2(lv.y, wv2, av[2*p+1]);
        }
    }

    const int b = tok0 / TT, t0 = tok0 % TT;
    const size_t tb = (size_t)(b*HH + h)*TT + t0;
    __nv_bfloat16* qb = g_qb + tb*DH + d;
    __nv_bfloat16* kb = g_kb + tb*DH + d;
    unsigned* vt = (unsigned*)(g_vT + ((size_t)(b*HH + h)*DH + d)*TT + t0);
#pragma unroll
    for (int p = 0; p < 8; p++) {
        float2 q2v = unpack2(aq[p]);
        float2 k2v = unpack2(ak[p]);
        float2 v2v = unpack2(av[p]);
        qb[(size_t)(2*p)*DH]   = __float2bfloat16_rn(q2v.x * SC);
        qb[(size_t)(2*p+1)*DH] = __float2bfloat16_rn(q2v.y * SC);
        kb[(size_t)(2*p)*DH]   = __float2bfloat16_rn(k2v.x);
        kb[(size_t)(2*p+1)*DH] = __float2bfloat16_rn(k2v.y);
        vt[p] = bf16x2(v2v.x, v2v.y);
    }
}

// ============================================================================
// k3: flash attention, bf16 m16n8k16, fixed-max softmax, register-resident P.
// Writes attention output as bf16 pairs (g_yb).
// ============================================================================
#define KB_STR 40
#define VB_STR 72
__global__ void __launch_bounds__(128, 3) k3_attn_mma()
{
    __shared__ __align__(16) __nv_bfloat16 Kbs[64*KB_STR];   // [key][dim]
    __shared__ __align__(16) __nv_bfloat16 Vbs[32*VB_STR];   // [dim][key]

    const int tid = threadIdx.x;
    const int w = tid >> 5, lane = tid & 31;
    const int gid = lane >> 2, tig = lane & 3;
    const int bh = blockIdx.y;
    const int qbase = blockIdx.x * 128 + w * 32;

    const __nv_bfloat16* qptr = g_qb + (size_t)bh*TT*DH;
    unsigned qA[2][2][4];
#pragma unroll
    for (int mh = 0; mh < 2; mh++) {
        const int rA = qbase + 16*mh + gid, rB = rA + 8;
#pragma unroll
        for (int kg = 0; kg < 2; kg++) {
            qA[mh][kg][0] = *(const unsigned*)(qptr + (size_t)rA*DH + 16*kg + 2*tig);
            qA[mh][kg][1] = *(const unsigned*)(qptr + (size_t)rB*DH + 16*kg + 2*tig);
            qA[mh][kg][2] = *(const unsigned*)(qptr + (size_t)rA*DH + 16*kg + 2*tig + 8);
            qA[mh][kg][3] = *(const unsigned*)(qptr + (size_t)rB*DH + 16*kg + 2*tig + 8);
        }
    }

    float y[2][4][4];
#pragma unroll
    for (int mh = 0; mh < 2; mh++)
#pragma unroll
        for (int i = 0; i < 4; i++)
#pragma unroll
            for (int j = 0; j < 4; j++) y[mh][i][j] = 0.f;
    float psA[2] = {0.f, 0.f}, psB[2] = {0.f, 0.f};

    const uint2* kg2 = (const uint2*)(g_kb + (size_t)bh*TT*DH);
    const uint2* vg2 = (const uint2*)(g_vT + (size_t)bh*DH*TT);

    for (int kt = 0; kt < TT; kt += 64) {
        __syncthreads();
#pragma unroll
        for (int i = 0; i < 4; i++) {
            int idx = tid + 128*i;
            int row = idx >> 3, c = idx & 7;
            *(uint2*)(Kbs + row*KB_STR + c*4) = kg2[(size_t)(kt + row)*8 + c];
        }
#pragma unroll
        for (int i = 0; i < 4; i++) {
            int idx = tid + 128*i;
            int row = idx >> 4, c = idx & 15;
            *(uint2*)(Vbs + row*VB_STR + c*4) = vg2[(size_t)row*(TT/4) + kt/4 + c];
        }
        __syncthreads();

#pragma unroll
        for (int sub = 0; sub < 2; sub++) {
            const int kb0 = 32*sub;

            float s[2][4][4];
#pragma unroll
            for (int nc = 0; nc < 4; nc++) {
                s[0][nc][0] = s[0][nc][1] = s[0][nc][2] = s[0][nc][3] = 0.f;
                s[1][nc][0] = s[1][nc][1] = s[1][nc][2] = s[1][nc][3] = 0.f;
#pragma unroll
                for (int kg = 0; kg < 2; kg++) {
                    const __nv_bfloat16* kr = Kbs + (kb0 + 8*nc + gid)*KB_STR + 16*kg + 2*tig;
                    unsigned b0 = *(const unsigned*)(kr);
                    unsigned b1 = *(const unsigned*)(kr + 8);
                    mma_bf16(s[0][nc], qA[0][kg][0], qA[0][kg][1], qA[0][kg][2], qA[0][kg][3], b0, b1);
                    mma_bf16(s[1][nc], qA[1][kg][0], qA[1][kg][1], qA[1][kg][2], qA[1][kg][3], b0, b1);
                }
            }

            unsigned pa[2][2][4];
#pragma unroll
            for (int mh = 0; mh < 2; mh++) {
#pragma unroll
                for (int kg = 0; kg < 2; kg++) {
                    float p00 = exp2f(s[mh][2*kg][0]);
                    float p01 = exp2f(s[mh][2*kg][1]);
                    float p02 = exp2f(s[mh][2*kg][2]);
                    float p03 = exp2f(s[mh][2*kg][3]);
                    float p10 = exp2f(s[mh][2*kg+1][0]);
                    float p11 = exp2f(s[mh][2*kg+1][1]);
                    float p12 = exp2f(s[mh][2*kg+1][2]);
                    float p13 = exp2f(s[mh][2*kg+1][3]);
                    psA[mh] += (p00 + p01) + (p10 + p11);
                    psB[mh] += (p02 + p03) + (p12 + p13);
                    pa[mh][kg][0] = bf16x2(p00, p01);
                    pa[mh][kg][1] = bf16x2(p02, p03);
                    pa[mh][kg][2] = bf16x2(p10, p11);
                    pa[mh][kg][3] = bf16x2(p12, p13);
                }
            }

#pragma unroll
            for (int kg = 0; kg < 2; kg++) {
#pragma unroll
                for (int nc2 = 0; nc2 < 4; nc2++) {
                    const __nv_bfloat16* vr = Vbs + (8*nc2 + gid)*VB_STR + kb0 + 16*kg + 2*tig;
                    unsigned b0 = *(const unsigned*)(vr);
                    unsigned b1 = *(const unsigned*)(vr + 8);
                    mma_bf16(y[0][nc2], pa[0][kg][0], pa[0][kg][1], pa[0][kg][2], pa[0][kg][3], b0, b1);
                    mma_bf16(y[1][nc2], pa[1][kg][0], pa[1][kg][1], pa[1][kg][2], pa[1][kg][3], b0, b1);
                }
            }
        }
    }

    // final row-sum reduction, normalize, write bf16 pairs
    const int b = bh >> 3, h = bh & 7;
#pragma unroll
    for (int mh = 0; mh < 2; mh++) {
        float sA = psA[mh], sB = psB[mh];
        sA += __shfl_xor_sync(0xffffffffu, sA, 1);
        sA += __shfl_xor_sync(0xffffffffu, sA, 2);
        sB += __shfl_xor_sync(0xffffffffu, sB, 1);
        sB += __shfl_xor_sync(0xffffffffu, sB, 2);
        const float inv0 = 1.0f / sA, inv1 = 1.0f / sB;
        const int rA = qbase + 16*mh + gid, rB = rA + 8;
#pragma unroll
        for (int nc2 = 0; nc2 < 4; nc2++) {
            int col = h*DH + nc2*8 + 2*tig;
            g_yb[((size_t)(b*TT + rA)*CC + col) >> 1] = bf16x2(y[mh][nc2][0]*inv0, y[mh][nc2][1]*inv0);
            g_yb[((size_t)(b*TT + rB)*CC + col) >> 1] = bf16x2(y[mh][nc2][2]*inv1, y[mh][nc2][3]*inv1);
        }
    }
}

// ============================================================================
// k4: output projection on tensor cores (bf16 m16n8k16) + gamma + residual.
// 32 tokens per CTA, 128 threads; warp w covers output cols [64w, 64w+64).
// ============================================================================
#define YS_STR 264   // bf16 per y row in smem (528B rows: 16B-aligned, conflict-free A-frags)
__global__ void __launch_bounds__(128) k4_oproj(
    const float* __restrict__ x, const float* __restrict__ gamma,
    float* __restrict__ out)
{
    __shared__ __align__(16) __nv_bfloat16 ys[32*YS_STR];
    const int tid = threadIdx.x;
    const int w = tid >> 5, lane = tid & 31;
    const int gid = lane >> 2, tig = lane & 3;
    const int tok0 = blockIdx.x * 32;

    // load y tile: 32 rows x 256 bf16 = 1024 uint4
    const uint4* ysrc = (const uint4*)(g_yb + (size_t)tok0*CC/2);
#pragma unroll
    for (int i = 0; i < 8; i++) {
        int idx = tid + 128*i;
        int row = idx >> 5, c = idx & 31;
        *(uint4*)(ys + row*YS_STR + c*8) = ysrc[row*32 + c];
    }
    __syncthreads();

    const int n0 = w * 64;
    float acc[2][8][4];
#pragma unroll
    for (int mh = 0; mh < 2; mh++)
#pragma unroll
        for (int nc = 0; nc < 8; nc++)
#pragma unroll
            for (int j = 0; j < 4; j++) acc[mh][nc][j] = 0.f;

#pragma unroll 4
    for (int kg = 0; kg < 16; kg++) {
        unsigned a[2][4];
#pragma unroll
        for (int mh = 0; mh < 2; mh++) {
            const __nv_bfloat16* yr = ys + (16*mh + gid)*YS_STR + 16*kg + 2*tig;
            a[mh][0] = *(const unsigned*)(yr);
            a[mh][1] = *(const unsigned*)(yr + 8*YS_STR);
            a[mh][2] = *(const unsigned*)(yr + 8);
            a[mh][3] = *(const unsigned*)(yr + 8*YS_STR + 8);
        }
#pragma unroll
        for (int nc = 0; nc < 8; nc++) {
            const unsigned* wb = g_owb + (size_t)(n0 + 8*nc + gid)*128 + 8*kg + tig;
            unsigned b0 = wb[0];
            unsigned b1 = wb[4];
            mma_bf16(acc[0][nc], a[0][0], a[0][1], a[0][2], a[0][3], b0, b1);
            mma_bf16(acc[1][nc], a[1][0], a[1][1], a[1][2], a[1][3], b0, b1);
        }
    }

    // epilogue: out = x + gamma * acc
#pragma unroll
    for (int nc = 0; nc < 8; nc++) {
        int col = n0 + 8*nc + 2*tig;
        float g0 = gamma[col], g1 = gamma[col + 1];
#pragma unroll
        for (int mh = 0; mh < 2; mh++) {
            int rA = tok0 + 16*mh + gid, rB = rA + 8;
            const float2 xA = *(const float2*)&x[(size_t)rA*CC + col];
            const float2 xB = *(const float2*)&x[(size_t)rB*CC + col];
            float2 oA; oA.x = xA.x + g0*acc[mh][nc][0]; oA.y = xA.y + g1*acc[mh][nc][1];
            float2 oB; oB.x = xB.x + g0*acc[mh][nc][2]; oB.y = xB.y + g1*acc[mh][nc][3];
            *(float2*)&out[(size_t)rA*CC + col] = oA;
            *(float2*)&out[(size_t)rB*CC + col] = oB;
        }
    }
}

// ============================================================================
extern "C" void kernel_launch(void* const* d_in, const int* in_sizes, int n_in,
                              void* d_out, int out_size)
{
    const float* x       = (const float*)d_in[0];
    const float* q_a_w   = (const float*)d_in[1];
    const float* q_bias  = (const float*)d_in[2];
    const float* q_b_w   = (const float*)d_in[3];
    const float* kv_a_w  = (const float*)d_in[4];
    const float* kv_bias = (const float*)d_in[5];
    const float* k_w     = (const float*)d_in[6];
    const float* v_w     = (const float*)d_in[7];
    const float* o_w     = (const float*)d_in[8];
    const float* norm_w  = (const float*)d_in[9];
    const float* gamma   = (const float*)d_in[10];
    float* out = (float*)d_out;

    k0_prep<<<312, 256>>>(o_w, q_a_w, kv_a_w, q_b_w, k_w, v_w);
    k1_fused<<<NBLK, 256>>>(x, norm_w, q_bias, kv_bias);
    dim3 g3(TT/128, BB*HH);
    k3_attn_mma<<<g3, 128>>>();
    k4_oproj<<<NTOK/32, 128>>>(x, gamma, out);
}

// round 12
// speedup vs baseline: 7.7777x; 1.1375x over previous
#include <cuda_runtime.h>
#include <cuda_bf16.h>
#include <cstdint>

#define BB 4
#define TT 2048
#define CC 256
#define HH 8
#define DH 32
#define QR 32
#define KVR 64
#define NTOK (BB*TT)          // 8192
#define TOKTILE 16
#define NBLK (NTOK/TOKTILE)   // 512

// ---------------- scratch (device globals; no allocation allowed) ----------------
__device__ __nv_bfloat16 g_qb[(size_t)BB*HH*TT*DH];      // [bh][t][d], pre-scaled
__device__ __nv_bfloat16 g_kb[(size_t)BB*HH*TT*DH];      // [bh][t][d]
__device__ __nv_bfloat16 g_vT[(size_t)BB*HH*DH*TT];      // [bh][d][t]  (transposed)
__device__ unsigned g_yb[(size_t)NTOK*CC/2];             // attention out, bf16 pairs [tok][c/2]
__device__ unsigned g_owb[(size_t)256*128];              // o_w bf16 pairs [d][c2]
__device__ ulonglong2 g_wAT4[(size_t)64*96];             // down-proj W^T packed [c4][r]
__device__ unsigned g_wub[(size_t)768*32];               // up-proj weights bf16 pairs [n][r/2]
                                                         //   n: 0-255 q_b_w, 256-511 k_w, 512-767 v_w

typedef unsigned long long u64;

// ---------------- packed f32x2 helpers ----------------
__device__ __forceinline__ u64 pack2(float lo, float hi) {
    u64 r; asm("mov.b64 %0, {%1, %2};" : "=l"(r) : "f"(lo), "f"(hi)); return r;
}
__device__ __forceinline__ float2 unpack2(u64 v) {
    float2 r; asm("mov.b64 {%0, %1}, %2;" : "=f"(r.x), "=f"(r.y) : "l"(v)); return r;
}
__device__ __forceinline__ u64 fma2(u64 a, u64 b, u64 c) {
    u64 d; asm("fma.rn.f32x2 %0, %1, %2, %3;" : "=l"(d) : "l"(a), "l"(b), "l"(c)); return d;
}

// ---------------- bf16 helpers ----------------
__device__ __forceinline__ unsigned bf16x2(float lo, float hi) {
    unsigned r; asm("cvt.rn.bf16x2.f32 %0, %1, %2;" : "=r"(r) : "f"(hi), "f"(lo)); return r;
}
__device__ __forceinline__ void mma_bf16(float* d,
    unsigned a0, unsigned a1, unsigned a2, unsigned a3, unsigned b0, unsigned b1) {
    asm volatile("mma.sync.aligned.m16n8k16.row.col.f32.bf16.bf16.f32 "
        "{%0,%1,%2,%3}, {%4,%5,%6,%7}, {%8,%9}, {%0,%1,%2,%3};"
        : "+f"(d[0]), "+f"(d[1]), "+f"(d[2]), "+f"(d[3])
        : "r"(a0), "r"(a1), "r"(a2), "r"(a3), "r"(b0), "r"(b1));
}

// ============================================================================
// k0: one-time weight repack/transpose.
// ranges: [0,32768) owb | [32768,38912) wAT4 | [38912,63488) wub
// ============================================================================
__global__ void __launch_bounds__(256) k0_prep(
    const float* __restrict__ o_w,
    const float* __restrict__ q_a_w, const float* __restrict__ kv_a_w,
    const float* __restrict__ q_b_w, const float* __restrict__ k_w,
    const float* __restrict__ v_w)
{
    int i = blockIdx.x * 256 + threadIdx.x;
    if (i < 32768) {
        int d = i >> 7, c2 = i & 127;
        g_owb[(size_t)d*128 + c2] = bf16x2(o_w[(size_t)d*256 + 2*c2],
                                           o_w[(size_t)d*256 + 2*c2 + 1]);
    } else if (i < 38912) {
        int j = i - 32768;
        int c4 = j / 96, r = j % 96;
        const float* src = (r < QR) ? (q_a_w + (size_t)r*CC)
                                    : (kv_a_w + (size_t)(r-QR)*CC);
        ulonglong2 v;
        v.x = pack2(src[4*c4],     src[4*c4 + 1]);
        v.y = pack2(src[4*c4 + 2], src[4*c4 + 3]);
        g_wAT4[(size_t)c4*96 + r] = v;
    } else if (i < 63488) {
        int j = i - 38912;            // 0..24575
        int n = j >> 5, cx = j & 31;  // cx = rank-pair index
        float lo = 0.f, hi = 0.f;
        if (n < 256) {
            if (cx < 16) { lo = q_b_w[(size_t)n*QR + 2*cx]; hi = q_b_w[(size_t)n*QR + 2*cx + 1]; }
        } else if (n < 512) {
            lo = k_w[(size_t)(n-256)*KVR + 2*cx]; hi = k_w[(size_t)(n-256)*KVR + 2*cx + 1];
        } else {
            lo = v_w[(size_t)(n-512)*KVR + 2*cx]; hi = v_w[(size_t)(n-512)*KVR + 2*cx + 1];
        }
        g_wub[(size_t)n*32 + cx] = bf16x2(lo, hi);
    }
}

// ============================================================================
// k1: FUSED LayerNorm + down-proj (fp32 fma2) + up-proj (bf16 TENSOR MMA).
// lat kept in smem as bf16 A-fragment layout. v transposed via smem.
// ============================================================================
__global__ void __launch_bounds__(256) k1_fused(
    const float* __restrict__ x, const float* __restrict__ norm_w,
    const float* __restrict__ q_bias, const float* __restrict__ kv_bias)
{
    __shared__ __align__(16) float xs[TOKTILE][CC];
    __shared__ __align__(16) __nv_bfloat16 latb[16*104];   // [t][r], stride 104
    __shared__ __align__(16) __nv_bfloat16 vsb[16*264];    // [t][c], stride 264
    const int tok0 = blockIdx.x * TOKTILE;
    const int tid = threadIdx.x;

    const float4* xsrc = (const float4*)(x + (size_t)tok0 * CC);
    float4* xd = (float4*)xs;
#pragma unroll
    for (int i = 0; i < 4; i++) xd[tid + i*256] = xsrc[tid + i*256];
    __syncthreads();

    // LayerNorm
    const int w = tid >> 5, l = tid & 31;
    for (int t = w; t < TOKTILE; t += 8) {
        float s = 0.f, sq = 0.f;
#pragma unroll
        for (int i = 0; i < 8; i++) { float v = xs[t][l + 32*i]; s += v; sq += v*v; }
#pragma unroll
        for (int o = 16; o; o >>= 1) {
            s  += __shfl_xor_sync(0xffffffffu, s,  o);
            sq += __shfl_xor_sync(0xffffffffu, sq, o);
        }
        float mean = s * (1.f/CC);
        float var  = sq * (1.f/CC) - mean*mean;
        float rstd = 1.f / sqrtf(var + 1e-5f);
#pragma unroll
        for (int i = 0; i < 8; i++) {
            int c = l + 32*i;
            xs[t][c] = (xs[t][c] - mean) * rstd * norm_w[c];
        }
    }
    __syncthreads();

    // down-proj: 192 threads, thread = (r, token-half); write lat bf16 [t][r]
    if (tid < 192) {
        const int r = tid % 96, th = tid / 96;
        const int t0 = th * 8;
        u64 acc[8];
#pragma unroll
        for (int tt = 0; tt < 8; tt++) acc[tt] = 0ull;
#pragma unroll 8
        for (int c4 = 0; c4 < 64; c4++) {
            ulonglong2 w4 = g_wAT4[(size_t)c4*96 + r];
#pragma unroll
            for (int tt = 0; tt < 8; tt++) {
                ulonglong2 xv = *(const ulonglong2*)&xs[t0 + tt][4*c4];
                acc[tt] = fma2(xv.x, w4.x, acc[tt]);
                acc[tt] = fma2(xv.y, w4.y, acc[tt]);
            }
        }
        const float bias = (r < QR) ? q_bias[r] : kv_bias[r - QR];
#pragma unroll
        for (int tt = 0; tt < 8; tt++) {
            float2 a = unpack2(acc[tt]);
            latb[(t0 + tt)*104 + r] = __float2bfloat16_rn(a.x + a.y + bias);
        }
    }
    __syncthreads();

    // up-proj on tensor cores: A = lat[16 x 96] bf16, B = g_wub rows.
    const int lane = tid & 31, gid = lane >> 2, tig = lane & 3;
    const float SC = 0.17677669529663687f * 1.4426950408889634f; // 1/sqrt(32)*log2(e)

    unsigned aA[6][4];
    const unsigned* latu = (const unsigned*)latb;
#pragma unroll
    for (int kg = 0; kg < 6; kg++) {
        aA[kg][0] = latu[gid*52 + 8*kg + tig];
        aA[kg][1] = latu[(gid+8)*52 + 8*kg + tig];
        aA[kg][2] = latu[gid*52 + 8*kg + tig + 4];
        aA[kg][3] = latu[(gid+8)*52 + 8*kg + tig + 4];
    }

    const int b = tok0 / TT;
    const int tA = (tok0 % TT) + gid;    // token row gid within batch
    unsigned* gq_u = (unsigned*)g_qb;
    unsigned* gk_u = (unsigned*)g_kb;
    unsigned* vs_u = (unsigned*)vsb;

#pragma unroll
    for (int j = 0; j < 12; j++) {
        const int nc = w + 8*j;
        const int row = 8*nc + gid;
        float acc[4] = {0.f, 0.f, 0.f, 0.f};
        if (nc < 32) {
#pragma unroll
            for (int kk = 0; kk < 2; kk++) {
                unsigned b0 = g_wub[(size_t)row*32 + 8*kk + tig];
                unsigned b1 = g_wub[(size_t)row*32 + 8*kk + tig + 4];
                mma_bf16(acc, aA[kk][0], aA[kk][1], aA[kk][2], aA[kk][3], b0, b1);
            }
            int h = nc >> 2, d2 = 4*(nc & 3) + tig;
            size_t base = ((size_t)(b*HH + h)*TT + tA)*16 + d2;
            gq_u[base]       = bf16x2(acc[0]*SC, acc[1]*SC);
            gq_u[base + 128] = bf16x2(acc[2]*SC, acc[3]*SC);
        } else {
#pragma unroll
            for (int kk = 0; kk < 4; kk++) {
                unsigned b0 = g_wub[(size_t)row*32 + 8*kk + tig];
                unsigned b1 = g_wub[(size_t)row*32 + 8*kk + tig + 4];
                mma_bf16(acc, aA[2+kk][0], aA[2+kk][1], aA[2+kk][2], aA[2+kk][3], b0, b1);
            }
            if (nc < 64) {
                int ncl = nc - 32;
                int h = ncl >> 2, d2 = 4*(ncl & 3) + tig;
                size_t base = ((size_t)(b*HH + h)*TT + tA)*16 + d2;
                gk_u[base]       = bf16x2(acc[0], acc[1]);
                gk_u[base + 128] = bf16x2(acc[2], acc[3]);
            } else {
                int c2 = 4*(nc - 64) + tig;     // (8*(nc-64)+2*tig)/2
                vs_u[gid*132 + c2]     = bf16x2(acc[0], acc[1]);
                vs_u[(gid+8)*132 + c2] = bf16x2(acc[2], acc[3]);
            }
        }
    }
    __syncthreads();

    // v transpose store: thread = output channel c
    {
        const int c = tid, h = c >> 5, d = c & 31;
        const unsigned short* vh = (const unsigned short*)vsb;
        unsigned* vt_u = (unsigned*)g_vT + (((size_t)(b*HH + h)*DH + d)*TT + (tok0 % TT))/2;
#pragma unroll
        for (int p = 0; p < 8; p++) {
            unsigned lo = vh[(2*p)*264 + c];
            unsigned hi = vh[(2*p+1)*264 + c];
            vt_u[p] = lo | (hi << 16);
        }
    }
}

// ============================================================================
// k3: flash attention, bf16 m16n8k16, fixed-max softmax, register-resident P.
// ============================================================================
#define KB_STR 40
#define VB_STR 72
__global__ void __launch_bounds__(128, 3) k3_attn_mma()
{
    __shared__ __align__(16) __nv_bfloat16 Kbs[64*KB_STR];   // [key][dim]
    __shared__ __align__(16) __nv_bfloat16 Vbs[32*VB_STR];   // [dim][key]

    const int tid = threadIdx.x;
    const int w = tid >> 5, lane = tid & 31;
    const int gid = lane >> 2, tig = lane & 3;
    const int bh = blockIdx.y;
    const int qbase = blockIdx.x * 128 + w * 32;

    const __nv_bfloat16* qptr = g_qb + (size_t)bh*TT*DH;
    unsigned qA[2][2][4];
#pragma unroll
    for (int mh = 0; mh < 2; mh++) {
        const int rA = qbase + 16*mh + gid, rB = rA + 8;
#pragma unroll
        for (int kg = 0; kg < 2; kg++) {
            qA[mh][kg][0] = *(const unsigned*)(qptr + (size_t)rA*DH + 16*kg + 2*tig);
            qA[mh][kg][1] = *(const unsigned*)(qptr + (size_t)rB*DH + 16*kg + 2*tig);
            qA[mh][kg][2] = *(const unsigned*)(qptr + (size_t)rA*DH + 16*kg + 2*tig + 8);
            qA[mh][kg][3] = *(const unsigned*)(qptr + (size_t)rB*DH + 16*kg + 2*tig + 8);
        }
    }

    float y[2][4][4];
#pragma unroll
    for (int mh = 0; mh < 2; mh++)
#pragma unroll
        for (int i = 0; i < 4; i++)
#pragma unroll
            for (int j = 0; j < 4; j++) y[mh][i][j] = 0.f;
    float psA[2] = {0.f, 0.f}, psB[2] = {0.f, 0.f};

    const uint2* kg2 = (const uint2*)(g_kb + (size_t)bh*TT*DH);
    const uint2* vg2 = (const uint2*)(g_vT + (size_t)bh*DH*TT);

    for (int kt = 0; kt < TT; kt += 64) {
        __syncthreads();
#pragma unroll
        for (int i = 0; i < 4; i++) {
            int idx = tid + 128*i;
            int row = idx >> 3, c = idx & 7;
            *(uint2*)(Kbs + row*KB_STR + c*4) = kg2[(size_t)(kt + row)*8 + c];
        }
#pragma unroll
        for (int i = 0; i < 4; i++) {
            int idx = tid + 128*i;
            int row = idx >> 4, c = idx & 15;
            *(uint2*)(Vbs + row*VB_STR + c*4) = vg2[(size_t)row*(TT/4) + kt/4 + c];
        }
        __syncthreads();

#pragma unroll
        for (int sub = 0; sub < 2; sub++) {
            const int kb0 = 32*sub;

            float s[2][4][4];
#pragma unroll
            for (int nc = 0; nc < 4; nc++) {
                s[0][nc][0] = s[0][nc][1] = s[0][nc][2] = s[0][nc][3] = 0.f;
                s[1][nc][0] = s[1][nc][1] = s[1][nc][2] = s[1][nc][3] = 0.f;
#pragma unroll
                for (int kg = 0; kg < 2; kg++) {
                    const __nv_bfloat16* kr = Kbs + (kb0 + 8*nc + gid)*KB_STR + 16*kg + 2*tig;
                    unsigned b0 = *(const unsigned*)(kr);
                    unsigned b1 = *(const unsigned*)(kr + 8);
                    mma_bf16(s[0][nc], qA[0][kg][0], qA[0][kg][1], qA[0][kg][2], qA[0][kg][3], b0, b1);
                    mma_bf16(s[1][nc], qA[1][kg][0], qA[1][kg][1], qA[1][kg][2], qA[1][kg][3], b0, b1);
                }
            }

            unsigned pa[2][2][4];
#pragma unroll
            for (int mh = 0; mh < 2; mh++) {
#pragma unroll
                for (int kg = 0; kg < 2; kg++) {
                    float p00 = exp2f(s[mh][2*kg][0]);
                    float p01 = exp2f(s[mh][2*kg][1]);
                    float p02 = exp2f(s[mh][2*kg][2]);
                    float p03 = exp2f(s[mh][2*kg][3]);
                    float p10 = exp2f(s[mh][2*kg+1][0]);
                    float p11 = exp2f(s[mh][2*kg+1][1]);
                    float p12 = exp2f(s[mh][2*kg+1][2]);
                    float p13 = exp2f(s[mh][2*kg+1][3]);
                    psA[mh] += (p00 + p01) + (p10 + p11);
                    psB[mh] += (p02 + p03) + (p12 + p13);
                    pa[mh][kg][0] = bf16x2(p00, p01);
                    pa[mh][kg][1] = bf16x2(p02, p03);
                    pa[mh][kg][2] = bf16x2(p10, p11);
                    pa[mh][kg][3] = bf16x2(p12, p13);
                }
            }

#pragma unroll
            for (int kg = 0; kg < 2; kg++) {
#pragma unroll
                for (int nc2 = 0; nc2 < 4; nc2++) {
                    const __nv_bfloat16* vr = Vbs + (8*nc2 + gid)*VB_STR + kb0 + 16*kg + 2*tig;
                    unsigned b0 = *(const unsigned*)(vr);
                    unsigned b1 = *(const unsigned*)(vr + 8);
                    mma_bf16(y[0][nc2], pa[0][kg][0], pa[0][kg][1], pa[0][kg][2], pa[0][kg][3], b0, b1);
                    mma_bf16(y[1][nc2], pa[1][kg][0], pa[1][kg][1], pa[1][kg][2], pa[1][kg][3], b0, b1);
                }
            }
        }
    }

    const int b = bh >> 3, h = bh & 7;
#pragma unroll
    for (int mh = 0; mh < 2; mh++) {
        float sA = psA[mh], sB = psB[mh];
        sA += __shfl_xor_sync(0xffffffffu, sA, 1);
        sA += __shfl_xor_sync(0xffffffffu, sA, 2);
        sB += __shfl_xor_sync(0xffffffffu, sB, 1);
        sB += __shfl_xor_sync(0xffffffffu, sB, 2);
        const float inv0 = 1.0f / sA, inv1 = 1.0f / sB;
        const int rA = qbase + 16*mh + gid, rB = rA + 8;
#pragma unroll
        for (int nc2 = 0; nc2 < 4; nc2++) {
            int col = h*DH + nc2*8 + 2*tig;
            g_yb[((size_t)(b*TT + rA)*CC + col) >> 1] = bf16x2(y[mh][nc2][0]*inv0, y[mh][nc2][1]*inv0);
            g_yb[((size_t)(b*TT + rB)*CC + col) >> 1] = bf16x2(y[mh][nc2][2]*inv1, y[mh][nc2][3]*inv1);
        }
    }
}

// ============================================================================
// k4: output projection, bf16 MMA with SMEM-STAGED weights.
// CTA = 64 tokens x 64 out-cols; 256 threads (8 warps, warp w -> nc=w).
// ============================================================================
#define K4_SMEM (2*64*132*4)   // ws + ys, uint stride 132 per row
__global__ void __launch_bounds__(256) k4_oproj(
    const float* __restrict__ x, const float* __restrict__ gamma,
    float* __restrict__ out)
{
    extern __shared__ __align__(16) unsigned k4s[];
    unsigned* ws = k4s;              // [64][132] bf16 pairs: weight rows n_local
    unsigned* ys = k4s + 64*132;     // [64][132] bf16 pairs: y rows t_local
    const int tid = threadIdx.x;
    const int w = tid >> 5, lane = tid & 31;
    const int gid = lane >> 2, tig = lane & 3;
    const int tok0 = blockIdx.x * 64;
    const int cg = blockIdx.y;       // 0..3

    // stage weights + y (uint4, conflict-free: 132 = 33 uint4)
    {
        const uint4* wsrc = (const uint4*)(g_owb + (size_t)(cg*64)*128);
        const uint4* ysrc = (const uint4*)(g_yb + (size_t)tok0*128);
        uint4* ws4 = (uint4*)ws;
        uint4* ys4 = (uint4*)ys;
#pragma unroll
        for (int i = 0; i < 8; i++) {
            int idx = tid + 256*i;
            int r = idx >> 5, c4 = idx & 31;
            ws4[r*33 + c4] = wsrc[r*32 + c4];
            ys4[r*33 + c4] = ysrc[r*32 + c4];
        }
    }
    __syncthreads();

    const __nv_bfloat16* wsh = (const __nv_bfloat16*)ws;
    const __nv_bfloat16* ysh = (const __nv_bfloat16*)ys;

    float acc[4][4];
#pragma unroll
    for (int m = 0; m < 4; m++)
#pragma unroll
        for (int j = 0; j < 4; j++) acc[m][j] = 0.f;

#pragma unroll 4
    for (int kg = 0; kg < 16; kg++) {
        const __nv_bfloat16* wr = wsh + (8*w + gid)*264 + 16*kg + 2*tig;
        unsigned b0 = *(const unsigned*)(wr);
        unsigned b1 = *(const unsigned*)(wr + 8);
#pragma unroll
        for (int m = 0; m < 4; m++) {
            const __nv_bfloat16* yr = ysh + (16*m + gid)*264 + 16*kg + 2*tig;
            unsigned a0 = *(const unsigned*)(yr);
            unsigned a1 = *(const unsigned*)(yr + 8*264);
            unsigned a2 = *(const unsigned*)(yr + 8);
            unsigned a3 = *(const unsigned*)(yr + 8*264 + 8);
            mma_bf16(acc[m], a0, a1, a2, a3, b0, b1);
        }
    }

    // epilogue: out = x + gamma * acc
    const int n = cg*64 + 8*w + 2*tig;
    const float g0 = gamma[n], g1 = gamma[n + 1];
#pragma unroll
    for (int m = 0; m < 4; m++) {
        int rA = tok0 + 16*m + gid, rB = rA + 8;
        float2 xA = *(const float2*)&x[(size_t)rA*CC + n];
        float2 xB = *(const float2*)&x[(size_t)rB*CC + n];
        float2 oA; oA.x = xA.x + g0*acc[m][0]; oA.y = xA.y + g1*acc[m][1];
        float2 oB; oB.x = xB.x + g0*acc[m][2]; oB.y = xB.y + g1*acc[m][3];
        *(float2*)&out[(size_t)rA*CC + n] = oA;
        *(float2*)&out[(size_t)rB*CC + n] = oB;
    }
}

// ============================================================================
extern "C" void kernel_launch(void* const* d_in, const int* in_sizes, int n_in,
                              void* d_out, int out_size)
{
    const float* x       = (const float*)d_in[0];
    const float* q_a_w   = (const float*)d_in[1];
    const float* q_bias  = (const float*)d_in[2];
    const float* q_b_w   = (const float*)d_in[3];
    const float* kv_a_w  = (const float*)d_in[4];
    const float* kv_bias = (const float*)d_in[5];
    const float* k_w     = (const float*)d_in[6];
    const float* v_w     = (const float*)d_in[7];
    const float* o_w     = (const float*)d_in[8];
    const float* norm_w  = (const float*)d_in[9];
    const float* gamma   = (const float*)d_in[10];
    float* out = (float*)d_out;

    cudaFuncSetAttribute(k4_oproj,
                         cudaFuncAttributeMaxDynamicSharedMemorySize, K4_SMEM);

    k0_prep<<<248, 256>>>(o_w, q_a_w, kv_a_w, q_b_w, k_w, v_w);
    k1_fused<<<NBLK, 256>>>(x, norm_w, q_bias, kv_bias);
    dim3 g3(TT/128, BB*HH);
    k3_attn_mma<<<g3, 128>>>();
    dim3 g4(NTOK/64, 4);
    k4_oproj<<<g4, 256, K4_SMEM>>>(x, gamma, out);
}